// round 1
// baseline (speedup 1.0000x reference)
#include <cuda_runtime.h>
#include <cuda_bf16.h>

// Problem constants (static shapes from setup_inputs)
#define D_MODEL 1280
#define NUM_HEADS 20
#define HEAD_DIM 64
#define MAX_SEQLEN 1500
#define MAX_T 6000           // 4 * 1500
#define ATT_SCALE 0.125f     // 64^-0.5
#define NEG_BIG -1e30f

// ---------------- scratch (static device globals; no runtime alloc) ----------
__device__ float g_q[MAX_T * D_MODEL];
__device__ float g_k[MAX_T * D_MODEL];
__device__ float g_v[MAX_T * D_MODEL];
__device__ float g_attn[MAX_T * D_MODEL];

// ---------------- generic GEMM: C[M,N] = A[M,K] @ B[N,K]^T + bias ------------
// BM=BN=64, BK=16, 256 threads, 4x4 microtile per thread.
#define BM 64
#define BN 64
#define BK 16

__global__ __launch_bounds__(256)
void gemm_atb(const float* __restrict__ A, const float* __restrict__ B,
              const float* __restrict__ bias, float* __restrict__ C,
              int M, int N, int K) {
    __shared__ float As[BK][BM + 1];   // [kk][m], pad 65 -> conflict-free writes
    __shared__ float Bs[BK][BN + 1];   // [kk][n]

    const int tid = threadIdx.x;
    const int tx = tid & 15;
    const int ty = tid >> 4;
    const int m0 = blockIdx.y * BM;
    const int n0 = blockIdx.x * BN;

    float acc[4][4] = {};

    for (int k0 = 0; k0 < K; k0 += BK) {
        // load 64x16 tiles of A and B (1024 elems each, 4 per thread)
        #pragma unroll
        for (int it = 0; it < 4; ++it) {
            int e  = tid + it * 256;
            int i  = e >> 4;        // row within tile
            int kk = e & 15;        // k within tile
            int m = m0 + i;
            As[kk][i] = (m < M) ? A[m * K + k0 + kk] : 0.f;
            int n = n0 + i;
            Bs[kk][i] = (n < N) ? B[n * K + k0 + kk] : 0.f;
        }
        __syncthreads();

        #pragma unroll
        for (int kk = 0; kk < BK; ++kk) {
            float a[4], b[4];
            #pragma unroll
            for (int r = 0; r < 4; ++r) a[r] = As[kk][ty * 4 + r];
            #pragma unroll
            for (int c = 0; c < 4; ++c) b[c] = Bs[kk][tx * 4 + c];
            #pragma unroll
            for (int r = 0; r < 4; ++r)
                #pragma unroll
                for (int c = 0; c < 4; ++c)
                    acc[r][c] += a[r] * b[c];
        }
        __syncthreads();
    }

    #pragma unroll
    for (int r = 0; r < 4; ++r) {
        int m = m0 + ty * 4 + r;
        if (m >= M) continue;
        #pragma unroll
        for (int c = 0; c < 4; ++c) {
            int n = n0 + tx * 4 + c;
            if (n < N) {
                float bb = bias ? bias[n] : 0.f;
                C[m * N + n] = acc[r][c] + bb;
            }
        }
    }
}

// ---------------- flash attention per (batch, head, q-tile) -------------------
// BQ=64 queries, BKV=64 keys per tile, d=64. 256 threads, 4x4 microtiles.
// Dynamic smem layout (floats):
//   Qs [64][65]  (transposed: [d][q])
//   Ks [64][65]  (transposed: [d][k])
//   Vs [64][68]  ([k][d])
//   Ps [64][68]  ([q][k])
#define BQ 64
#define BKV 64
#define QS_LD 65
#define KS_LD 65
#define VS_LD 68
#define PS_LD 68
#define FLASH_SMEM_FLOATS (64*QS_LD + 64*KS_LD + 64*VS_LD + 64*PS_LD)
#define FLASH_SMEM_BYTES  (FLASH_SMEM_FLOATS * 4)

__global__ __launch_bounds__(256)
void flash_attn(const float* __restrict__ Q, const float* __restrict__ K,
                const float* __restrict__ V, const int* __restrict__ cu,
                float* __restrict__ O) {
    extern __shared__ float sm[];
    float* Qs = sm;                       // [d][q] stride QS_LD
    float* Ks = Qs + 64 * QS_LD;          // [d][k] stride KS_LD
    float* Vs = Ks + 64 * KS_LD;          // [k][d] stride VS_LD
    float* Ps = Vs + 64 * VS_LD;          // [q][k] stride PS_LD

    const int b  = blockIdx.z;
    const int h  = blockIdx.y;
    const int q0 = blockIdx.x * BQ;

    const int base = cu[b];
    const int len  = cu[b + 1] - base;
    if (q0 >= len) return;

    const int tid = threadIdx.x;
    const int tx = tid & 15;
    const int ty = tid >> 4;

    // load Q tile, transposed into [d][q]
    #pragma unroll
    for (int it = 0; it < 16; ++it) {
        int e  = tid + it * 256;
        int i  = e >> 6;    // q within tile
        int dd = e & 63;    // d
        int qi = q0 + i;
        if (qi >= len) qi = len - 1;   // clamp (rows beyond len not stored)
        Qs[dd * QS_LD + i] = Q[(base + qi) * D_MODEL + h * HEAD_DIM + dd];
    }

    float mrow[4], lrow[4], o[4][4];
    #pragma unroll
    for (int r = 0; r < 4; ++r) {
        mrow[r] = -3.0e38f;
        lrow[r] = 0.f;
        #pragma unroll
        for (int c = 0; c < 4; ++c) o[r][c] = 0.f;
    }

    const int nk = (len + BKV - 1) / BKV;
    for (int kt = 0; kt < nk; ++kt) {
        const int k0 = kt * BKV;
        __syncthreads();   // prior iteration done reading Ks/Vs/Ps

        // load K (transposed) and V (natural) tiles
        #pragma unroll
        for (int it = 0; it < 16; ++it) {
            int e  = tid + it * 256;
            int i  = e >> 6;
            int dd = e & 63;
            int ki = k0 + i;
            if (ki >= len) ki = len - 1;   // clamped; masked below
            int g = (base + ki) * D_MODEL + h * HEAD_DIM + dd;
            Ks[dd * KS_LD + i] = K[g];
            Vs[i * VS_LD + dd] = V[g];
        }
        __syncthreads();

        // S = Q @ K^T (64x64), 4x4 per thread
        float s[4][4] = {};
        #pragma unroll
        for (int dd = 0; dd < 64; ++dd) {
            float a[4], bb[4];
            #pragma unroll
            for (int r = 0; r < 4; ++r) a[r] = Qs[dd * QS_LD + ty * 4 + r];
            #pragma unroll
            for (int c = 0; c < 4; ++c) bb[c] = Ks[dd * KS_LD + tx * 4 + c];
            #pragma unroll
            for (int r = 0; r < 4; ++r)
                #pragma unroll
                for (int c = 0; c < 4; ++c)
                    s[r][c] += a[r] * bb[c];
        }

        // scale + key mask
        #pragma unroll
        for (int c = 0; c < 4; ++c) {
            int kg = k0 + tx * 4 + c;
            bool ok = (kg < len);
            #pragma unroll
            for (int r = 0; r < 4; ++r)
                s[r][c] = ok ? s[r][c] * ATT_SCALE : NEG_BIG;
        }

        // online softmax (row reduction across 16 tx lanes in half-warp)
        #pragma unroll
        for (int r = 0; r < 4; ++r) {
            float mx = fmaxf(fmaxf(s[r][0], s[r][1]), fmaxf(s[r][2], s[r][3]));
            #pragma unroll
            for (int off = 8; off > 0; off >>= 1)
                mx = fmaxf(mx, __shfl_xor_sync(0xffffffffu, mx, off));
            float nm = fmaxf(mrow[r], mx);
            float alpha = __expf(mrow[r] - nm);
            float rs = 0.f;
            #pragma unroll
            for (int c = 0; c < 4; ++c) {
                float p = __expf(s[r][c] - nm);
                Ps[(ty * 4 + r) * PS_LD + tx * 4 + c] = p;
                rs += p;
            }
            #pragma unroll
            for (int off = 8; off > 0; off >>= 1)
                rs += __shfl_xor_sync(0xffffffffu, rs, off);
            lrow[r] = lrow[r] * alpha + rs;
            mrow[r] = nm;
            #pragma unroll
            for (int c = 0; c < 4; ++c) o[r][c] *= alpha;
        }
        __syncthreads();

        // O += P @ V  (64x64 @ 64x64)
        #pragma unroll
        for (int kk = 0; kk < 64; ++kk) {
            float p[4], vv[4];
            #pragma unroll
            for (int r = 0; r < 4; ++r) p[r] = Ps[(ty * 4 + r) * PS_LD + kk];
            #pragma unroll
            for (int c = 0; c < 4; ++c) vv[c] = Vs[kk * VS_LD + tx * 4 + c];
            #pragma unroll
            for (int r = 0; r < 4; ++r)
                #pragma unroll
                for (int c = 0; c < 4; ++c)
                    o[r][c] += p[r] * vv[c];
        }
    }

    // epilogue: O /= l, store valid rows
    #pragma unroll
    for (int r = 0; r < 4; ++r) {
        int qi = q0 + ty * 4 + r;
        if (qi < len) {
            float inv = 1.0f / lrow[r];
            #pragma unroll
            for (int c = 0; c < 4; ++c)
                O[(base + qi) * D_MODEL + h * HEAD_DIM + tx * 4 + c] = o[r][c] * inv;
        }
    }
}

// ---------------- host launcher ----------------------------------------------
extern "C" void kernel_launch(void* const* d_in, const int* in_sizes, int n_in,
                              void* d_out, int out_size) {
    const float* hs = (const float*)d_in[0];
    const int*   cu = (const int*)d_in[1];
    const float* Wq = (const float*)d_in[2];
    const float* bq = (const float*)d_in[3];
    const float* Wk = (const float*)d_in[4];
    const float* Wv = (const float*)d_in[5];
    const float* bv = (const float*)d_in[6];
    const float* Wo = (const float*)d_in[7];
    const float* bo = (const float*)d_in[8];
    float* out = (float*)d_out;

    const int T    = in_sizes[0] / D_MODEL;   // 6000
    const int Bseg = in_sizes[1] - 1;         // 4

    float *pq, *pk, *pv, *pa;
    cudaGetSymbolAddress((void**)&pq, g_q);
    cudaGetSymbolAddress((void**)&pk, g_k);
    cudaGetSymbolAddress((void**)&pv, g_v);
    cudaGetSymbolAddress((void**)&pa, g_attn);

    static bool attr_set = false;
    cudaFuncSetAttribute(flash_attn, cudaFuncAttributeMaxDynamicSharedMemorySize,
                         FLASH_SMEM_BYTES);
    (void)attr_set;

    dim3 ggrid(D_MODEL / BN, (T + BM - 1) / BM);

    // projections
    gemm_atb<<<ggrid, 256>>>(hs, Wq, bq,      pq, T, D_MODEL, D_MODEL);
    gemm_atb<<<ggrid, 256>>>(hs, Wk, nullptr, pk, T, D_MODEL, D_MODEL);
    gemm_atb<<<ggrid, 256>>>(hs, Wv, bv,      pv, T, D_MODEL, D_MODEL);

    // attention
    dim3 fgrid((MAX_SEQLEN + BQ - 1) / BQ, NUM_HEADS, Bseg);
    flash_attn<<<fgrid, 256, FLASH_SMEM_BYTES>>>(pq, pk, pv, cu, pa);

    // output projection
    gemm_atb<<<ggrid, 256>>>(pa, Wo, bo, out, T, D_MODEL, D_MODEL);
}

// round 5
// speedup vs baseline: 2.2856x; 2.2856x over previous
#include <cuda_runtime.h>
#include <cuda_bf16.h>
#include <cstdint>

// Problem constants (static shapes from setup_inputs)
#define D_MODEL 1280
#define NUM_HEADS 20
#define HEAD_DIM 64
#define MAX_SEQLEN 1500
#define MAX_T 6000           // 4 * 1500
#define ATT_SCALE 0.125f     // 64^-0.5
#define NEG_BIG -1e30f

// ---------------- scratch (static device globals; no runtime alloc) ----------
__device__ float g_q[MAX_T * D_MODEL];
__device__ float g_k[MAX_T * D_MODEL];
__device__ float g_v[MAX_T * D_MODEL];
__device__ float g_attn[MAX_T * D_MODEL];
__device__ float g_hs_r[MAX_T * D_MODEL];           // tf32-rounded hidden states
__device__ float g_w_r[4][D_MODEL * D_MODEL];       // tf32-rounded Wq,Wk,Wv,Wo

// ========================= PTX helpers ======================================
__device__ __forceinline__ uint32_t smem_u32(const void* p) {
    uint32_t a;
    asm("{ .reg .u64 t; cvta.to.shared.u64 t, %1; cvt.u32.u64 %0, t; }"
        : "=r"(a) : "l"(p));
    return a;
}

__device__ __forceinline__ void cp_async16(uint32_t dst, const void* src) {
    asm volatile("cp.async.cg.shared.global [%0], [%1], 16;"
                 :: "r"(dst), "l"(src));
}
#define CP_COMMIT() asm volatile("cp.async.commit_group;" ::: "memory")
#define CP_WAIT0()  asm volatile("cp.async.wait_group 0;" ::: "memory")

__device__ __forceinline__ float round_tf32(float v) {
    uint32_t t;
    asm("cvt.rn.tf32.f32 %0, %1;" : "=r"(t) : "f"(v));
    return __uint_as_float(t);
}

// mma.sync m16n8k8 tf32: D[16,8] += A[16,8] @ B[8,8]  (A row-major, B col-major)
__device__ __forceinline__ void mma_tf32(float c[4], const uint32_t a[4],
                                         const uint32_t b[2]) {
    asm volatile(
        "mma.sync.aligned.m16n8k8.row.col.f32.tf32.tf32.f32 "
        "{%0,%1,%2,%3}, {%4,%5,%6,%7}, {%8,%9}, {%0,%1,%2,%3};"
        : "+f"(c[0]), "+f"(c[1]), "+f"(c[2]), "+f"(c[3])
        : "r"(a[0]), "r"(a[1]), "r"(a[2]), "r"(a[3]), "r"(b[0]), "r"(b[1]));
}

// ================= tf32 rounding kernel (vectorized) =========================
__global__ __launch_bounds__(256)
void round_tf32_kernel(const float4* __restrict__ in, float4* __restrict__ out, int n4) {
    int i = blockIdx.x * blockDim.x + threadIdx.x;
    if (i < n4) {
        float4 v = in[i];
        v.x = round_tf32(v.x); v.y = round_tf32(v.y);
        v.z = round_tf32(v.z); v.w = round_tf32(v.w);
        out[i] = v;
    }
}

// ============ tf32 mma.sync GEMM: C[M,1280] = A[M,1280] @ B[1280,1280]^T + bias
// CTA tile 128x128, BK=32, 8 warps, warp tile 64x32 (4x4 m16n8k8 tiles).
#define BMg 128
#define BNg 128
#define BKg 32
#define LDAg 36                                     // 32 + 4 pad (floats)
#define STAGE_FLOATS (BMg * LDAg + BNg * LDAg)      // 9216 floats = 36 KB
#define GT_SMEM_BYTES (2 * STAGE_FLOATS * 4)        // 72 KB

__device__ __forceinline__ void gt_load(const float* __restrict__ A,
                                        const float* __restrict__ B,
                                        int M, int m0, int n0, int k0,
                                        float* sA, float* sB, int tid) {
    #pragma unroll
    for (int i = 0; i < 4; ++i) {
        int e   = tid + i * 256;      // 0..1023
        int row = e >> 3;             // 0..127
        int g   = e & 7;              // float4 group within 32 k-cols
        int ar  = m0 + row; if (ar >= M) ar = M - 1;   // clamp; masked at store
        cp_async16(smem_u32(sA + row * LDAg + g * 4),
                   A + (size_t)ar * D_MODEL + k0 + g * 4);
        cp_async16(smem_u32(sB + row * LDAg + g * 4),
                   B + (size_t)(n0 + row) * D_MODEL + k0 + g * 4);
    }
}

__global__ __launch_bounds__(256)
void gemm_tf32mma(const float* __restrict__ A, const float* __restrict__ B,
                  const float* __restrict__ bias, float* __restrict__ C, int M) {
    extern __shared__ float sm[];
    float* sA[2] = { sm,                 sm + STAGE_FLOATS };
    float* sB[2] = { sm + BMg * LDAg,    sm + STAGE_FLOATS + BMg * LDAg };

    const int tid  = threadIdx.x;
    const int wid  = tid >> 5;
    const int lane = tid & 31;
    const int wm   = wid & 1;          // warp row (0..1) -> 64 rows
    const int wn   = wid >> 1;         // warp col (0..3) -> 32 cols
    const int m0   = blockIdx.y * BMg;
    const int n0   = blockIdx.x * BNg;

    const int arow = wm * 64 + (lane >> 2);
    const int brow = wn * 32 + (lane >> 2);
    const int kq   = lane & 3;

    float c[4][4][4];
    #pragma unroll
    for (int mt = 0; mt < 4; ++mt)
        #pragma unroll
        for (int nt = 0; nt < 4; ++nt)
            #pragma unroll
            for (int q = 0; q < 4; ++q) c[mt][nt][q] = 0.f;

    const int NCH = D_MODEL / BKg;     // 40
    gt_load(A, B, M, m0, n0, 0, sA[0], sB[0], tid);
    CP_COMMIT();

    for (int ch = 0; ch < NCH; ++ch) {
        CP_WAIT0();
        __syncthreads();
        if (ch + 1 < NCH) {
            gt_load(A, B, M, m0, n0, (ch + 1) * BKg,
                    sA[(ch + 1) & 1], sB[(ch + 1) & 1], tid);
            CP_COMMIT();
        }
        const float* cA = sA[ch & 1];
        const float* cB = sB[ch & 1];

        #pragma unroll
        for (int kk = 0; kk < 4; ++kk) {
            const int kb = kk * 8 + kq;
            uint32_t af[4][4];
            #pragma unroll
            for (int mt = 0; mt < 4; ++mt) {
                const float* p = cA + (arow + mt * 16) * LDAg + kb;
                af[mt][0] = __float_as_uint(p[0]);
                af[mt][1] = __float_as_uint(p[8 * LDAg]);
                af[mt][2] = __float_as_uint(p[4]);
                af[mt][3] = __float_as_uint(p[8 * LDAg + 4]);
            }
            uint32_t bf[4][2];
            #pragma unroll
            for (int nt = 0; nt < 4; ++nt) {
                const float* p = cB + (brow + nt * 8) * LDAg + kb;
                bf[nt][0] = __float_as_uint(p[0]);
                bf[nt][1] = __float_as_uint(p[4]);
            }
            #pragma unroll
            for (int mt = 0; mt < 4; ++mt)
                #pragma unroll
                for (int nt = 0; nt < 4; ++nt)
                    mma_tf32(c[mt][nt], af[mt], bf[nt]);
        }
        __syncthreads();
    }

    // epilogue: fragment -> global (float2 stores), + bias
    const int crow = m0 + wm * 64 + (lane >> 2);
    const int ccol = n0 + wn * 32 + 2 * (lane & 3);
    #pragma unroll
    for (int nt = 0; nt < 4; ++nt) {
        int col = ccol + nt * 8;
        float b0 = bias ? bias[col]     : 0.f;
        float b1 = bias ? bias[col + 1] : 0.f;
        #pragma unroll
        for (int mt = 0; mt < 4; ++mt) {
            int r0 = crow + mt * 16;
            if (r0 < M) {
                float2 v = make_float2(c[mt][nt][0] + b0, c[mt][nt][1] + b1);
                *(float2*)(C + (size_t)r0 * D_MODEL + col) = v;
            }
            int r1 = r0 + 8;
            if (r1 < M) {
                float2 v = make_float2(c[mt][nt][2] + b0, c[mt][nt][3] + b1);
                *(float2*)(C + (size_t)r1 * D_MODEL + col) = v;
            }
        }
    }
}

// ---------------- flash attention per (batch, head, q-tile) -------------------
#define BQ 64
#define BKV 64
#define QS_LD 65
#define KS_LD 65
#define VS_LD 68
#define PS_LD 68
#define FLASH_SMEM_FLOATS (64*QS_LD + 64*KS_LD + 64*VS_LD + 64*PS_LD)
#define FLASH_SMEM_BYTES  (FLASH_SMEM_FLOATS * 4)

__global__ __launch_bounds__(256)
void flash_attn(const float* __restrict__ Q, const float* __restrict__ K,
                const float* __restrict__ V, const int* __restrict__ cu,
                float* __restrict__ O) {
    extern __shared__ float sm[];
    float* Qs = sm;
    float* Ks = Qs + 64 * QS_LD;
    float* Vs = Ks + 64 * KS_LD;
    float* Ps = Vs + 64 * VS_LD;

    const int b  = blockIdx.z;
    const int h  = blockIdx.y;
    const int q0 = blockIdx.x * BQ;

    const int base = cu[b];
    const int len  = cu[b + 1] - base;
    if (q0 >= len) return;

    const int tid = threadIdx.x;
    const int tx = tid & 15;
    const int ty = tid >> 4;

    #pragma unroll
    for (int it = 0; it < 16; ++it) {
        int e  = tid + it * 256;
        int i  = e >> 6;
        int dd = e & 63;
        int qi = q0 + i;
        if (qi >= len) qi = len - 1;
        Qs[dd * QS_LD + i] = Q[(base + qi) * D_MODEL + h * HEAD_DIM + dd];
    }

    float mrow[4], lrow[4], o[4][4];
    #pragma unroll
    for (int r = 0; r < 4; ++r) {
        mrow[r] = -3.0e38f;
        lrow[r] = 0.f;
        #pragma unroll
        for (int c = 0; c < 4; ++c) o[r][c] = 0.f;
    }

    const int nk = (len + BKV - 1) / BKV;
    for (int kt = 0; kt < nk; ++kt) {
        const int k0 = kt * BKV;
        __syncthreads();

        #pragma unroll
        for (int it = 0; it < 16; ++it) {
            int e  = tid + it * 256;
            int i  = e >> 6;
            int dd = e & 63;
            int ki = k0 + i;
            if (ki >= len) ki = len - 1;
            int g = (base + ki) * D_MODEL + h * HEAD_DIM + dd;
            Ks[dd * KS_LD + i] = K[g];
            Vs[i * VS_LD + dd] = V[g];
        }
        __syncthreads();

        float s[4][4] = {};
        #pragma unroll
        for (int dd = 0; dd < 64; ++dd) {
            float a[4], bb[4];
            #pragma unroll
            for (int r = 0; r < 4; ++r) a[r] = Qs[dd * QS_LD + ty * 4 + r];
            #pragma unroll
            for (int c = 0; c < 4; ++c) bb[c] = Ks[dd * KS_LD + tx * 4 + c];
            #pragma unroll
            for (int r = 0; r < 4; ++r)
                #pragma unroll
                for (int c = 0; c < 4; ++c)
                    s[r][c] += a[r] * bb[c];
        }

        #pragma unroll
        for (int c = 0; c < 4; ++c) {
            int kg = k0 + tx * 4 + c;
            bool ok = (kg < len);
            #pragma unroll
            for (int r = 0; r < 4; ++r)
                s[r][c] = ok ? s[r][c] * ATT_SCALE : NEG_BIG;
        }

        #pragma unroll
        for (int r = 0; r < 4; ++r) {
            float mx = fmaxf(fmaxf(s[r][0], s[r][1]), fmaxf(s[r][2], s[r][3]));
            #pragma unroll
            for (int off = 8; off > 0; off >>= 1)
                mx = fmaxf(mx, __shfl_xor_sync(0xffffffffu, mx, off));
            float nm = fmaxf(mrow[r], mx);
            float alpha = __expf(mrow[r] - nm);
            float rs = 0.f;
            #pragma unroll
            for (int c = 0; c < 4; ++c) {
                float p = __expf(s[r][c] - nm);
                Ps[(ty * 4 + r) * PS_LD + tx * 4 + c] = p;
                rs += p;
            }
            #pragma unroll
            for (int off = 8; off > 0; off >>= 1)
                rs += __shfl_xor_sync(0xffffffffu, rs, off);
            lrow[r] = lrow[r] * alpha + rs;
            mrow[r] = nm;
            #pragma unroll
            for (int c = 0; c < 4; ++c) o[r][c] *= alpha;
        }
        __syncthreads();

        #pragma unroll
        for (int kk = 0; kk < 64; ++kk) {
            float p[4], vv[4];
            #pragma unroll
            for (int r = 0; r < 4; ++r) p[r] = Ps[(ty * 4 + r) * PS_LD + kk];
            #pragma unroll
            for (int c = 0; c < 4; ++c) vv[c] = Vs[kk * VS_LD + tx * 4 + c];
            #pragma unroll
            for (int r = 0; r < 4; ++r)
                #pragma unroll
                for (int c = 0; c < 4; ++c)
                    o[r][c] += p[r] * vv[c];
        }
    }

    #pragma unroll
    for (int r = 0; r < 4; ++r) {
        int qi = q0 + ty * 4 + r;
        if (qi < len) {
            float inv = 1.0f / lrow[r];
            #pragma unroll
            for (int c = 0; c < 4; ++c)
                O[(base + qi) * D_MODEL + h * HEAD_DIM + tx * 4 + c] =
                    round_tf32(o[r][c] * inv);   // tf32-round for the final GEMM
        }
    }
}

// ---------------- host launcher ----------------------------------------------
extern "C" void kernel_launch(void* const* d_in, const int* in_sizes, int n_in,
                              void* d_out, int out_size) {
    const float* hs = (const float*)d_in[0];
    const int*   cu = (const int*)d_in[1];
    const float* Wq = (const float*)d_in[2];
    const float* bq = (const float*)d_in[3];
    const float* Wk = (const float*)d_in[4];
    const float* Wv = (const float*)d_in[5];
    const float* bv = (const float*)d_in[6];
    const float* Wo = (const float*)d_in[7];
    const float* bo = (const float*)d_in[8];
    float* out = (float*)d_out;

    const int T    = in_sizes[0] / D_MODEL;   // 6000
    const int Bseg = in_sizes[1] - 1;         // 4

    float *pq, *pk, *pv, *pa, *phr, *pwr;
    cudaGetSymbolAddress((void**)&pq,  g_q);
    cudaGetSymbolAddress((void**)&pk,  g_k);
    cudaGetSymbolAddress((void**)&pv,  g_v);
    cudaGetSymbolAddress((void**)&pa,  g_attn);
    cudaGetSymbolAddress((void**)&phr, g_hs_r);
    cudaGetSymbolAddress((void**)&pwr, g_w_r);
    float* pwq = pwr + 0 * D_MODEL * D_MODEL;
    float* pwk = pwr + 1 * D_MODEL * D_MODEL;
    float* pwv = pwr + 2 * D_MODEL * D_MODEL;
    float* pwo = pwr + 3 * D_MODEL * D_MODEL;

    cudaFuncSetAttribute(flash_attn, cudaFuncAttributeMaxDynamicSharedMemorySize,
                         FLASH_SMEM_BYTES);
    cudaFuncSetAttribute(gemm_tf32mma, cudaFuncAttributeMaxDynamicSharedMemorySize,
                         GT_SMEM_BYTES);

    // tf32-round GEMM operands (RN rounding, unbiased)
    {
        int n4 = (T * D_MODEL) / 4;
        round_tf32_kernel<<<(n4 + 255) / 256, 256>>>((const float4*)hs, (float4*)phr, n4);
        int w4 = (D_MODEL * D_MODEL) / 4;
        int wg = (w4 + 255) / 256;
        round_tf32_kernel<<<wg, 256>>>((const float4*)Wq, (float4*)pwq, w4);
        round_tf32_kernel<<<wg, 256>>>((const float4*)Wk, (float4*)pwk, w4);
        round_tf32_kernel<<<wg, 256>>>((const float4*)Wv, (float4*)pwv, w4);
        round_tf32_kernel<<<wg, 256>>>((const float4*)Wo, (float4*)pwo, w4);
    }

    dim3 ggrid(D_MODEL / BNg, (T + BMg - 1) / BMg);   // (10, 47)

    // projections (tensor-core tf32 mma.sync)
    gemm_tf32mma<<<ggrid, 256, GT_SMEM_BYTES>>>(phr, pwq, bq,      pq, T);
    gemm_tf32mma<<<ggrid, 256, GT_SMEM_BYTES>>>(phr, pwk, nullptr, pk, T);
    gemm_tf32mma<<<ggrid, 256, GT_SMEM_BYTES>>>(phr, pwv, bv,      pv, T);

    // attention (fp32, output tf32-rounded)
    dim3 fgrid((MAX_SEQLEN + BQ - 1) / BQ, NUM_HEADS, Bseg);
    flash_attn<<<fgrid, 256, FLASH_SMEM_BYTES>>>(pq, pk, pv, cu, pa);

    // output projection (tensor-core tf32 mma.sync)
    gemm_tf32mma<<<ggrid, 256, GT_SMEM_BYTES>>>(pa, pwo, bo, out, T);
}

// round 6
// speedup vs baseline: 4.0417x; 1.7683x over previous
#include <cuda_runtime.h>
#include <cuda_bf16.h>
#include <cstdint>

// Problem constants (static shapes from setup_inputs)
#define D_MODEL 1280
#define NUM_HEADS 20
#define HEAD_DIM 64
#define MAX_SEQLEN 1500
#define MAX_T 6000           // 4 * 1500
#define ATT_SCALE 0.125f     // 64^-0.5
#define NEG_BIG -1e30f

// ---------------- scratch (static device globals; no runtime alloc) ----------
__device__ float g_q[MAX_T * D_MODEL];
__device__ float g_k[MAX_T * D_MODEL];
__device__ float g_v[MAX_T * D_MODEL];
__device__ float g_attn[MAX_T * D_MODEL];
__device__ float g_hs_r[MAX_T * D_MODEL];           // tf32-rounded hidden states
__device__ float g_w_r[4][D_MODEL * D_MODEL];       // tf32-rounded Wq,Wk,Wv,Wo

// ========================= PTX helpers ======================================
__device__ __forceinline__ uint32_t smem_u32(const void* p) {
    uint32_t a;
    asm("{ .reg .u64 t; cvta.to.shared.u64 t, %1; cvt.u32.u64 %0, t; }"
        : "=r"(a) : "l"(p));
    return a;
}

__device__ __forceinline__ void cp_async16(uint32_t dst, const void* src) {
    asm volatile("cp.async.cg.shared.global [%0], [%1], 16;"
                 :: "r"(dst), "l"(src));
}
#define CP_COMMIT() asm volatile("cp.async.commit_group;" ::: "memory")
#define CP_WAIT0()  asm volatile("cp.async.wait_group 0;" ::: "memory")
#define CP_WAIT1()  asm volatile("cp.async.wait_group 1;" ::: "memory")

__device__ __forceinline__ float round_tf32(float v) {
    uint32_t t;
    asm("cvt.rn.tf32.f32 %0, %1;" : "=r"(t) : "f"(v));
    return __uint_as_float(t);
}

// mma.sync m16n8k8 tf32: D[16,8] += A[16,8] @ B[8,8]  (A row-major, B col-major)
__device__ __forceinline__ void mma_tf32(float c[4], const uint32_t a[4],
                                         const uint32_t b[2]) {
    asm volatile(
        "mma.sync.aligned.m16n8k8.row.col.f32.tf32.tf32.f32 "
        "{%0,%1,%2,%3}, {%4,%5,%6,%7}, {%8,%9}, {%0,%1,%2,%3};"
        : "+f"(c[0]), "+f"(c[1]), "+f"(c[2]), "+f"(c[3])
        : "r"(a[0]), "r"(a[1]), "r"(a[2]), "r"(a[3]), "r"(b[0]), "r"(b[1]));
}

// ================= tf32 rounding kernel (vectorized) =========================
__global__ __launch_bounds__(256)
void round_tf32_kernel(const float4* __restrict__ in, float4* __restrict__ out, int n4) {
    int i = blockIdx.x * blockDim.x + threadIdx.x;
    if (i < n4) {
        float4 v = in[i];
        v.x = round_tf32(v.x); v.y = round_tf32(v.y);
        v.z = round_tf32(v.z); v.w = round_tf32(v.w);
        out[i] = v;
    }
}

// ============ tf32 mma.sync GEMM: C[M,1280] = A[M,1280] @ B[1280,1280]^T + bias
// CTA tile 128x128, BK=32, 8 warps, warp tile 64x32 (4x4 m16n8k8 tiles).
#define BMg 128
#define BNg 128
#define BKg 32
#define LDAg 36                                     // 32 + 4 pad (floats)
#define STAGE_FLOATS (BMg * LDAg + BNg * LDAg)      // 9216 floats = 36 KB
#define GT_SMEM_BYTES (2 * STAGE_FLOATS * 4)        // 72 KB

__device__ __forceinline__ void gt_load(const float* __restrict__ A,
                                        const float* __restrict__ B,
                                        int M, int m0, int n0, int k0,
                                        float* sA, float* sB, int tid) {
    #pragma unroll
    for (int i = 0; i < 4; ++i) {
        int e   = tid + i * 256;      // 0..1023
        int row = e >> 3;             // 0..127
        int g   = e & 7;              // float4 group within 32 k-cols
        int ar  = m0 + row; if (ar >= M) ar = M - 1;   // clamp; masked at store
        cp_async16(smem_u32(sA + row * LDAg + g * 4),
                   A + (size_t)ar * D_MODEL + k0 + g * 4);
        cp_async16(smem_u32(sB + row * LDAg + g * 4),
                   B + (size_t)(n0 + row) * D_MODEL + k0 + g * 4);
    }
}

__global__ __launch_bounds__(256)
void gemm_tf32mma(const float* __restrict__ A, const float* __restrict__ B,
                  const float* __restrict__ bias, float* __restrict__ C, int M,
                  int round_out) {
    extern __shared__ float sm[];
    float* sA[2] = { sm,                 sm + STAGE_FLOATS };
    float* sB[2] = { sm + BMg * LDAg,    sm + STAGE_FLOATS + BMg * LDAg };

    const int tid  = threadIdx.x;
    const int wid  = tid >> 5;
    const int lane = tid & 31;
    const int wm   = wid & 1;          // warp row (0..1) -> 64 rows
    const int wn   = wid >> 1;         // warp col (0..3) -> 32 cols
    const int m0   = blockIdx.y * BMg;
    const int n0   = blockIdx.x * BNg;

    const int arow = wm * 64 + (lane >> 2);
    const int brow = wn * 32 + (lane >> 2);
    const int kq   = lane & 3;

    float c[4][4][4];
    #pragma unroll
    for (int mt = 0; mt < 4; ++mt)
        #pragma unroll
        for (int nt = 0; nt < 4; ++nt)
            #pragma unroll
            for (int q = 0; q < 4; ++q) c[mt][nt][q] = 0.f;

    const int NCH = D_MODEL / BKg;     // 40
    gt_load(A, B, M, m0, n0, 0, sA[0], sB[0], tid);
    CP_COMMIT();

    for (int ch = 0; ch < NCH; ++ch) {
        CP_WAIT0();
        __syncthreads();
        if (ch + 1 < NCH) {
            gt_load(A, B, M, m0, n0, (ch + 1) * BKg,
                    sA[(ch + 1) & 1], sB[(ch + 1) & 1], tid);
            CP_COMMIT();
        }
        const float* cA = sA[ch & 1];
        const float* cB = sB[ch & 1];

        #pragma unroll
        for (int kk = 0; kk < 4; ++kk) {
            const int kb = kk * 8 + kq;
            uint32_t af[4][4];
            #pragma unroll
            for (int mt = 0; mt < 4; ++mt) {
                const float* p = cA + (arow + mt * 16) * LDAg + kb;
                af[mt][0] = __float_as_uint(p[0]);
                af[mt][1] = __float_as_uint(p[8 * LDAg]);
                af[mt][2] = __float_as_uint(p[4]);
                af[mt][3] = __float_as_uint(p[8 * LDAg + 4]);
            }
            uint32_t bf[4][2];
            #pragma unroll
            for (int nt = 0; nt < 4; ++nt) {
                const float* p = cB + (brow + nt * 8) * LDAg + kb;
                bf[nt][0] = __float_as_uint(p[0]);
                bf[nt][1] = __float_as_uint(p[4]);
            }
            #pragma unroll
            for (int mt = 0; mt < 4; ++mt)
                #pragma unroll
                for (int nt = 0; nt < 4; ++nt)
                    mma_tf32(c[mt][nt], af[mt], bf[nt]);
        }
        __syncthreads();
    }

    // epilogue: fragment -> global (float2 stores), + bias, optional tf32 round
    const int crow = m0 + wm * 64 + (lane >> 2);
    const int ccol = n0 + wn * 32 + 2 * (lane & 3);
    #pragma unroll
    for (int nt = 0; nt < 4; ++nt) {
        int col = ccol + nt * 8;
        float b0 = bias ? bias[col]     : 0.f;
        float b1 = bias ? bias[col + 1] : 0.f;
        #pragma unroll
        for (int mt = 0; mt < 4; ++mt) {
            int r0 = crow + mt * 16;
            if (r0 < M) {
                float v0 = c[mt][nt][0] + b0, v1 = c[mt][nt][1] + b1;
                if (round_out) { v0 = round_tf32(v0); v1 = round_tf32(v1); }
                *(float2*)(C + (size_t)r0 * D_MODEL + col) = make_float2(v0, v1);
            }
            int r1 = r0 + 8;
            if (r1 < M) {
                float v0 = c[mt][nt][2] + b0, v1 = c[mt][nt][3] + b1;
                if (round_out) { v0 = round_tf32(v0); v1 = round_tf32(v1); }
                *(float2*)(C + (size_t)r1 * D_MODEL + col) = make_float2(v0, v1);
            }
        }
    }
}

// ================ tensor-core flash attention =================================
// CTA: 256 threads (8 warps), BQ=128 (16 q-rows per warp), KV tiles of 64.
// Q fragments register-resident; Q smem reused as per-warp P staging.
// Leading dims: K/Q/P = 68 (== 4 mod 32), V = 72 (== 8 mod 32) -> conflict-free
// fragment loads.
#define FBQ 128
#define FBK 64
#define QLD 68
#define KLD 68
#define VLD 72
// smem floats: Qs/Ps 128*68 + 2 K stages 64*68 + 2 V stages 64*72
#define FA_SMEM_FLOATS (FBQ*QLD + 2*FBK*KLD + 2*FBK*VLD)
#define FA_SMEM_BYTES  (FA_SMEM_FLOATS * 4)

__device__ __forceinline__ void fa_load_kv(const float* __restrict__ K,
                                           const float* __restrict__ V,
                                           int base, int len, int h, int k0,
                                           float* Ks, float* Vs, int tid) {
    #pragma unroll
    for (int i = 0; i < 4; ++i) {
        int e   = tid + i * 256;     // 0..1023
        int row = e >> 4;            // 0..63
        int g   = e & 15;            // float4 group within 64 cols
        int kr  = k0 + row; if (kr >= len) kr = len - 1;
        size_t goff = (size_t)(base + kr) * D_MODEL + h * HEAD_DIM + g * 4;
        cp_async16(smem_u32(Ks + row * KLD + g * 4), K + goff);
        cp_async16(smem_u32(Vs + row * VLD + g * 4), V + goff);
    }
}

__global__ __launch_bounds__(256)
void flash_attn_mma(const float* __restrict__ Q, const float* __restrict__ K,
                    const float* __restrict__ V, const int* __restrict__ cu,
                    float* __restrict__ O) {
    extern __shared__ float sm[];
    float* Qs  = sm;                         // 128 x 68 (later: P staging)
    float* Ks0 = Qs  + FBQ * QLD;
    float* Ks1 = Ks0 + FBK * KLD;
    float* Vs0 = Ks1 + FBK * KLD;
    float* Vs1 = Vs0 + FBK * VLD;

    const int b  = blockIdx.z;
    const int h  = blockIdx.y;
    const int q0 = blockIdx.x * FBQ;

    const int base = cu[b];
    const int len  = cu[b + 1] - base;
    if (q0 >= len) return;

    const int tid  = threadIdx.x;
    const int wid  = tid >> 5;
    const int lane = tid & 31;
    const int qr   = lane >> 2;     // 0..7
    const int kq   = lane & 3;      // 0..3

    const int nk = (len + FBK - 1) / FBK;

    // kick off K/V stage 0 and 1 (clamped loads are safe for any nk)
    fa_load_kv(K, V, base, len, h, 0,   Ks0, Vs0, tid); CP_COMMIT();
    fa_load_kv(K, V, base, len, h, FBK, Ks1, Vs1, tid); CP_COMMIT();

    // load Q tile into smem (coalesced float4): 128 rows x 64 cols
    #pragma unroll
    for (int i = 0; i < 8; ++i) {
        int e   = tid + i * 256;     // 0..2047
        int row = e >> 4;            // 0..127
        int g   = e & 15;
        int qi  = q0 + row; if (qi >= len) qi = len - 1;
        float4 v = *(const float4*)(Q + (size_t)(base + qi) * D_MODEL + h * HEAD_DIM + g * 4);
        *(float4*)(Qs + row * QLD + g * 4) = v;
    }
    __syncthreads();

    // Q fragments -> registers (warp owns rows [wid*16, wid*16+16))
    uint32_t qf[8][4];
    {
        const float* qp = Qs + (wid * 16 + qr) * QLD + kq;
        #pragma unroll
        for (int ks = 0; ks < 8; ++ks) {
            const float* p = qp + ks * 8;
            qf[ks][0] = __float_as_uint(p[0]);
            qf[ks][1] = __float_as_uint(p[8 * QLD]);
            qf[ks][2] = __float_as_uint(p[4]);
            qf[ks][3] = __float_as_uint(p[8 * QLD + 4]);
        }
    }
    __syncthreads();    // all Q frags read; Qs may be reused as P

    float m0 = -3.0e38f, m1 = -3.0e38f, l0 = 0.f, l1 = 0.f;
    float o[8][4];
    #pragma unroll
    for (int dt = 0; dt < 8; ++dt)
        #pragma unroll
        for (int q = 0; q < 4; ++q) o[dt][q] = 0.f;

    float* Pw = Qs + wid * 16 * QLD;   // this warp's 16 x 68 P staging

    for (int kt = 0; kt < nk; ++kt) {
        const int s = kt & 1;
        const float* Ks = s ? Ks1 : Ks0;
        const float* Vs = s ? Vs1 : Vs0;
        if (kt + 1 < nk) { CP_WAIT1(); } else { CP_WAIT0(); }
        __syncthreads();

        // ---- S = Q @ K^T  (16 x 64 per warp) ----
        float sc[8][4];
        #pragma unroll
        for (int nt = 0; nt < 8; ++nt)
            #pragma unroll
            for (int q = 0; q < 4; ++q) sc[nt][q] = 0.f;

        #pragma unroll
        for (int ks = 0; ks < 8; ++ks) {
            const int kb = ks * 8 + kq;
            #pragma unroll
            for (int nt = 0; nt < 8; ++nt) {
                uint32_t bf[2];
                const float* p = Ks + (nt * 8 + qr) * KLD + kb;
                bf[0] = __float_as_uint(p[0]);
                bf[1] = __float_as_uint(p[4]);
                mma_tf32(sc[nt], qf[ks], bf);
            }
        }

        // ---- mask + scale ----
        const int kbase = kt * FBK;
        #pragma unroll
        for (int nt = 0; nt < 8; ++nt) {
            int c0 = kbase + nt * 8 + 2 * kq;
            bool ok0 = c0 < len, ok1 = (c0 + 1) < len;
            sc[nt][0] = ok0 ? sc[nt][0] * ATT_SCALE : NEG_BIG;
            sc[nt][1] = ok1 ? sc[nt][1] * ATT_SCALE : NEG_BIG;
            sc[nt][2] = ok0 ? sc[nt][2] * ATT_SCALE : NEG_BIG;
            sc[nt][3] = ok1 ? sc[nt][3] * ATT_SCALE : NEG_BIG;
        }

        // ---- online softmax (rows qr and qr+8) ----
        float mx0 = -3.0e38f, mx1 = -3.0e38f;
        #pragma unroll
        for (int nt = 0; nt < 8; ++nt) {
            mx0 = fmaxf(mx0, fmaxf(sc[nt][0], sc[nt][1]));
            mx1 = fmaxf(mx1, fmaxf(sc[nt][2], sc[nt][3]));
        }
        mx0 = fmaxf(mx0, __shfl_xor_sync(0xffffffffu, mx0, 1));
        mx0 = fmaxf(mx0, __shfl_xor_sync(0xffffffffu, mx0, 2));
        mx1 = fmaxf(mx1, __shfl_xor_sync(0xffffffffu, mx1, 1));
        mx1 = fmaxf(mx1, __shfl_xor_sync(0xffffffffu, mx1, 2));

        float nm0 = fmaxf(m0, mx0), nm1 = fmaxf(m1, mx1);
        float a0 = __expf(m0 - nm0), a1 = __expf(m1 - nm1);
        float rs0 = 0.f, rs1 = 0.f;
        #pragma unroll
        for (int nt = 0; nt < 8; ++nt) {
            float p00 = __expf(sc[nt][0] - nm0);
            float p01 = __expf(sc[nt][1] - nm0);
            float p10 = __expf(sc[nt][2] - nm1);
            float p11 = __expf(sc[nt][3] - nm1);
            rs0 += p00 + p01;
            rs1 += p10 + p11;
            float* pp = Pw + qr * QLD + nt * 8 + 2 * kq;
            *(float2*)pp = make_float2(round_tf32(p00), round_tf32(p01));
            *(float2*)(pp + 8 * QLD) = make_float2(round_tf32(p10), round_tf32(p11));
        }
        rs0 += __shfl_xor_sync(0xffffffffu, rs0, 1);
        rs0 += __shfl_xor_sync(0xffffffffu, rs0, 2);
        rs1 += __shfl_xor_sync(0xffffffffu, rs1, 1);
        rs1 += __shfl_xor_sync(0xffffffffu, rs1, 2);

        l0 = l0 * a0 + rs0;  m0 = nm0;
        l1 = l1 * a1 + rs1;  m1 = nm1;
        #pragma unroll
        for (int dt = 0; dt < 8; ++dt) {
            o[dt][0] *= a0; o[dt][1] *= a0;
            o[dt][2] *= a1; o[dt][3] *= a1;
        }
        __syncwarp();

        // ---- O += P @ V  (16 x 64 per warp, k over 64 keys) ----
        #pragma unroll
        for (int ks = 0; ks < 8; ++ks) {
            uint32_t pf[4];
            const float* pp = Pw + qr * QLD + ks * 8 + kq;
            pf[0] = __float_as_uint(pp[0]);
            pf[1] = __float_as_uint(pp[8 * QLD]);
            pf[2] = __float_as_uint(pp[4]);
            pf[3] = __float_as_uint(pp[8 * QLD + 4]);
            const float* vrow = Vs + (ks * 8 + kq) * VLD + qr;
            #pragma unroll
            for (int dt = 0; dt < 8; ++dt) {
                uint32_t bf[2];
                bf[0] = __float_as_uint(vrow[dt * 8]);
                bf[1] = __float_as_uint(vrow[4 * VLD + dt * 8]);
                mma_tf32(o[dt], pf, bf);
            }
        }
        __syncthreads();   // done reading stage s (and P) before overwrite

        if (kt + 2 < nk) {
            fa_load_kv(K, V, base, len, h, (kt + 2) * FBK,
                       s ? Ks1 : Ks0, s ? Vs1 : Vs0, tid);
            CP_COMMIT();
        }
    }

    // ---- epilogue: O /= l, tf32-round, store ----
    const int qr0 = q0 + wid * 16 + qr;
    const int qr1 = qr0 + 8;
    const float inv0 = 1.0f / l0, inv1 = 1.0f / l1;
    #pragma unroll
    for (int dt = 0; dt < 8; ++dt) {
        int col = h * HEAD_DIM + dt * 8 + 2 * kq;
        if (qr0 < len)
            *(float2*)(O + (size_t)(base + qr0) * D_MODEL + col) =
                make_float2(round_tf32(o[dt][0] * inv0), round_tf32(o[dt][1] * inv0));
        if (qr1 < len)
            *(float2*)(O + (size_t)(base + qr1) * D_MODEL + col) =
                make_float2(round_tf32(o[dt][2] * inv1), round_tf32(o[dt][3] * inv1));
    }
}

// ---------------- host launcher ----------------------------------------------
extern "C" void kernel_launch(void* const* d_in, const int* in_sizes, int n_in,
                              void* d_out, int out_size) {
    const float* hs = (const float*)d_in[0];
    const int*   cu = (const int*)d_in[1];
    const float* Wq = (const float*)d_in[2];
    const float* bq = (const float*)d_in[3];
    const float* Wk = (const float*)d_in[4];
    const float* Wv = (const float*)d_in[5];
    const float* bv = (const float*)d_in[6];
    const float* Wo = (const float*)d_in[7];
    const float* bo = (const float*)d_in[8];
    float* out = (float*)d_out;

    const int T    = in_sizes[0] / D_MODEL;   // 6000
    const int Bseg = in_sizes[1] - 1;         // 4

    float *pq, *pk, *pv, *pa, *phr, *pwr;
    cudaGetSymbolAddress((void**)&pq,  g_q);
    cudaGetSymbolAddress((void**)&pk,  g_k);
    cudaGetSymbolAddress((void**)&pv,  g_v);
    cudaGetSymbolAddress((void**)&pa,  g_attn);
    cudaGetSymbolAddress((void**)&phr, g_hs_r);
    cudaGetSymbolAddress((void**)&pwr, g_w_r);
    float* pwq = pwr + 0 * D_MODEL * D_MODEL;
    float* pwk = pwr + 1 * D_MODEL * D_MODEL;
    float* pwv = pwr + 2 * D_MODEL * D_MODEL;
    float* pwo = pwr + 3 * D_MODEL * D_MODEL;

    cudaFuncSetAttribute(flash_attn_mma, cudaFuncAttributeMaxDynamicSharedMemorySize,
                         FA_SMEM_BYTES);
    cudaFuncSetAttribute(gemm_tf32mma, cudaFuncAttributeMaxDynamicSharedMemorySize,
                         GT_SMEM_BYTES);

    // tf32-round GEMM operands (RN rounding, unbiased)
    {
        int n4 = (T * D_MODEL) / 4;
        round_tf32_kernel<<<(n4 + 255) / 256, 256>>>((const float4*)hs, (float4*)phr, n4);
        int w4 = (D_MODEL * D_MODEL) / 4;
        int wg = (w4 + 255) / 256;
        round_tf32_kernel<<<wg, 256>>>((const float4*)Wq, (float4*)pwq, w4);
        round_tf32_kernel<<<wg, 256>>>((const float4*)Wk, (float4*)pwk, w4);
        round_tf32_kernel<<<wg, 256>>>((const float4*)Wv, (float4*)pwv, w4);
        round_tf32_kernel<<<wg, 256>>>((const float4*)Wo, (float4*)pwo, w4);
    }

    dim3 ggrid(D_MODEL / BNg, (T + BMg - 1) / BMg);   // (10, 47)

    // projections (tensor-core tf32 mma.sync); outputs tf32-rounded for attention
    gemm_tf32mma<<<ggrid, 256, GT_SMEM_BYTES>>>(phr, pwq, bq,      pq, T, 1);
    gemm_tf32mma<<<ggrid, 256, GT_SMEM_BYTES>>>(phr, pwk, nullptr, pk, T, 1);
    gemm_tf32mma<<<ggrid, 256, GT_SMEM_BYTES>>>(phr, pwv, bv,      pv, T, 1);

    // attention (tensor-core tf32, fp32 accumulate; output tf32-rounded)
    dim3 fgrid((MAX_SEQLEN + FBQ - 1) / FBQ, NUM_HEADS, Bseg);
    flash_attn_mma<<<fgrid, 256, FA_SMEM_BYTES>>>(pq, pk, pv, cu, pa);

    // output projection (tensor-core tf32 mma.sync), full fp32 out
    gemm_tf32mma<<<ggrid, 256, GT_SMEM_BYTES>>>(pa, pwo, bo, out, T, 0);
}

// round 7
// speedup vs baseline: 4.1478x; 1.0263x over previous
#include <cuda_runtime.h>
#include <cuda_bf16.h>
#include <cstdint>

// Problem constants (static shapes from setup_inputs)
#define D_MODEL 1280
#define NUM_HEADS 20
#define HEAD_DIM 64
#define MAX_SEQLEN 1500
#define MAX_T 6000           // 4 * 1500
#define ATT_SCALE 0.125f     // 64^-0.5
#define NEG_BIG -1e30f

// ---------------- scratch (static device globals; no runtime alloc) ----------
__device__ float g_q[MAX_T * D_MODEL];
__device__ float g_k[MAX_T * D_MODEL];
__device__ float g_v[MAX_T * D_MODEL];
__device__ float g_attn[MAX_T * D_MODEL];
__device__ float g_hs_r[MAX_T * D_MODEL];           // tf32-rounded hidden states
__device__ float g_w_r[4][D_MODEL * D_MODEL];       // tf32-rounded Wq,Wk,Wv,Wo (contiguous)
__device__ float g_bias[3 * D_MODEL];               // combined bq | 0 | bv

// ========================= PTX helpers ======================================
__device__ __forceinline__ uint32_t smem_u32(const void* p) {
    uint32_t a;
    asm("{ .reg .u64 t; cvta.to.shared.u64 t, %1; cvt.u32.u64 %0, t; }"
        : "=r"(a) : "l"(p));
    return a;
}

__device__ __forceinline__ void cp_async16(uint32_t dst, const void* src) {
    asm volatile("cp.async.cg.shared.global [%0], [%1], 16;"
                 :: "r"(dst), "l"(src));
}
#define CP_COMMIT() asm volatile("cp.async.commit_group;" ::: "memory")
#define CP_WAIT0()  asm volatile("cp.async.wait_group 0;" ::: "memory")
#define CP_WAIT1()  asm volatile("cp.async.wait_group 1;" ::: "memory")

__device__ __forceinline__ float round_tf32(float v) {
    uint32_t t;
    asm("cvt.rn.tf32.f32 %0, %1;" : "=r"(t) : "f"(v));
    return __uint_as_float(t);
}

// mma.sync m16n8k8 tf32: D[16,8] += A[16,8] @ B[8,8]  (A row-major, B col-major)
__device__ __forceinline__ void mma_tf32(float c[4], const uint32_t a[4],
                                         const uint32_t b[2]) {
    asm volatile(
        "mma.sync.aligned.m16n8k8.row.col.f32.tf32.tf32.f32 "
        "{%0,%1,%2,%3}, {%4,%5,%6,%7}, {%8,%9}, {%0,%1,%2,%3};"
        : "+f"(c[0]), "+f"(c[1]), "+f"(c[2]), "+f"(c[3])
        : "r"(a[0]), "r"(a[1]), "r"(a[2]), "r"(a[3]), "r"(b[0]), "r"(b[1]));
}

// ================= small helper kernels =====================================
__global__ __launch_bounds__(256)
void round_tf32_kernel(const float4* __restrict__ in, float4* __restrict__ out, int n4) {
    int i = blockIdx.x * blockDim.x + threadIdx.x;
    if (i < n4) {
        float4 v = in[i];
        v.x = round_tf32(v.x); v.y = round_tf32(v.y);
        v.z = round_tf32(v.z); v.w = round_tf32(v.w);
        out[i] = v;
    }
}

__global__ __launch_bounds__(256)
void build_qkv_bias(const float* __restrict__ bq, const float* __restrict__ bv,
                    float* __restrict__ bias) {
    int i = blockIdx.x * blockDim.x + threadIdx.x;   // 0..3839
    if (i < 3 * D_MODEL) {
        float v = 0.f;
        if (i < D_MODEL) v = bq[i];
        else if (i >= 2 * D_MODEL) v = bv[i - 2 * D_MODEL];
        bias[i] = v;
    }
}

// ============ tf32 mma.sync GEMM: C[M, n_mats*1280] = A @ B^T + bias =========
// CTA tile 128x128, BK=64, 8 warps, warp tile 64x32 (4x4 m16n8k8 tiles).
// 2-stage cp.async pipeline, ONE barrier per K-chunk.
// blockIdx.x spans n_mats*10 column blocks; output block routed to C0/C1/C2.
#define BMg 128
#define BNg 128
#define BKg 64
#define LDAg 68                                     // 64 + 4 pad (floats)
#define STAGE_FLOATS (BMg * LDAg + BNg * LDAg)      // 17408 floats = 68 KB
#define GT_SMEM_BYTES (2 * STAGE_FLOATS * 4)        // 136 KB

__device__ __forceinline__ void gt_load(const float* __restrict__ A,
                                        const float* __restrict__ B,
                                        int M, int m0, int n0, int k0,
                                        float* sA, float* sB, int tid) {
    #pragma unroll
    for (int i = 0; i < 8; ++i) {
        int e   = tid + i * 256;      // 0..2047
        int row = e >> 4;             // 0..127
        int g   = e & 15;             // float4 group within 64 k-cols
        int ar  = m0 + row; if (ar >= M) ar = M - 1;   // clamp; masked at store
        cp_async16(smem_u32(sA + row * LDAg + g * 4),
                   A + (size_t)ar * D_MODEL + k0 + g * 4);
        cp_async16(smem_u32(sB + row * LDAg + g * 4),
                   B + (size_t)(n0 + row) * D_MODEL + k0 + g * 4);
    }
}

__global__ __launch_bounds__(256)
void gemm_tf32mma(const float* __restrict__ A, const float* __restrict__ B,
                  const float* __restrict__ bias,
                  float* __restrict__ C0, float* __restrict__ C1,
                  float* __restrict__ C2, int M, int round_out) {
    extern __shared__ float sm[];
    float* sA[2] = { sm,               sm + STAGE_FLOATS };
    float* sB[2] = { sm + BMg * LDAg,  sm + STAGE_FLOATS + BMg * LDAg };

    const int tid  = threadIdx.x;
    const int wid  = tid >> 5;
    const int lane = tid & 31;
    const int wm   = wid & 1;          // warp row (0..1) -> 64 rows
    const int wn   = wid >> 1;         // warp col (0..3) -> 32 cols
    const int m0   = blockIdx.y * BMg;
    const int n0   = blockIdx.x * BNg;             // global column (bias/B space)

    const int arow = wm * 64 + (lane >> 2);
    const int brow = wn * 32 + (lane >> 2);
    const int kq   = lane & 3;

    float c[4][4][4];
    #pragma unroll
    for (int mt = 0; mt < 4; ++mt)
        #pragma unroll
        for (int nt = 0; nt < 4; ++nt)
            #pragma unroll
            for (int q = 0; q < 4; ++q) c[mt][nt][q] = 0.f;

    const int NCH = D_MODEL / BKg;     // 20
    gt_load(A, B, M, m0, n0, 0, sA[0], sB[0], tid);
    CP_COMMIT();

    for (int ch = 0; ch < NCH; ++ch) {
        CP_WAIT0();
        __syncthreads();               // single barrier per chunk (see theory)
        if (ch + 1 < NCH) {
            gt_load(A, B, M, m0, n0, (ch + 1) * BKg,
                    sA[(ch + 1) & 1], sB[(ch + 1) & 1], tid);
            CP_COMMIT();
        }
        const float* cA = sA[ch & 1];
        const float* cB = sB[ch & 1];

        #pragma unroll
        for (int kk = 0; kk < 8; ++kk) {
            const int kb = kk * 8 + kq;
            uint32_t af[4][4];
            #pragma unroll
            for (int mt = 0; mt < 4; ++mt) {
                const float* p = cA + (arow + mt * 16) * LDAg + kb;
                af[mt][0] = __float_as_uint(p[0]);
                af[mt][1] = __float_as_uint(p[8 * LDAg]);
                af[mt][2] = __float_as_uint(p[4]);
                af[mt][3] = __float_as_uint(p[8 * LDAg + 4]);
            }
            uint32_t bf[4][2];
            #pragma unroll
            for (int nt = 0; nt < 4; ++nt) {
                const float* p = cB + (brow + nt * 8) * LDAg + kb;
                bf[nt][0] = __float_as_uint(p[0]);
                bf[nt][1] = __float_as_uint(p[4]);
            }
            #pragma unroll
            for (int mt = 0; mt < 4; ++mt)
                #pragma unroll
                for (int nt = 0; nt < 4; ++nt)
                    mma_tf32(c[mt][nt], af[mt], bf[nt]);
        }
    }

    // route output block to its matrix (10 column-blocks per 1280-wide matrix)
    const int mat = blockIdx.x / 10;
    float* C = (mat == 0) ? C0 : ((mat == 1) ? C1 : C2);
    const int ncol0 = (blockIdx.x - mat * 10) * BNg;   // column within matrix

    // epilogue: fragment -> global (float2 stores), + bias, optional tf32 round
    const int crow = m0 + wm * 64 + (lane >> 2);
    const int ccol = wn * 32 + 2 * (lane & 3);
    #pragma unroll
    for (int nt = 0; nt < 4; ++nt) {
        int col  = ccol + nt * 8;
        float b0 = bias[n0 + col];
        float b1 = bias[n0 + col + 1];
        int colg = ncol0 + col;
        #pragma unroll
        for (int mt = 0; mt < 4; ++mt) {
            int r0 = crow + mt * 16;
            if (r0 < M) {
                float v0 = c[mt][nt][0] + b0, v1 = c[mt][nt][1] + b1;
                if (round_out) { v0 = round_tf32(v0); v1 = round_tf32(v1); }
                *(float2*)(C + (size_t)r0 * D_MODEL + colg) = make_float2(v0, v1);
            }
            int r1 = r0 + 8;
            if (r1 < M) {
                float v0 = c[mt][nt][2] + b0, v1 = c[mt][nt][3] + b1;
                if (round_out) { v0 = round_tf32(v0); v1 = round_tf32(v1); }
                *(float2*)(C + (size_t)r1 * D_MODEL + colg) = make_float2(v0, v1);
            }
        }
    }
}

// ================ tensor-core flash attention (unchanged from R6) ============
#define FBQ 128
#define FBK 64
#define QLD 68
#define KLD 68
#define VLD 72
#define FA_SMEM_FLOATS (FBQ*QLD + 2*FBK*KLD + 2*FBK*VLD)
#define FA_SMEM_BYTES  (FA_SMEM_FLOATS * 4)

__device__ __forceinline__ void fa_load_kv(const float* __restrict__ K,
                                           const float* __restrict__ V,
                                           int base, int len, int h, int k0,
                                           float* Ks, float* Vs, int tid) {
    #pragma unroll
    for (int i = 0; i < 4; ++i) {
        int e   = tid + i * 256;     // 0..1023
        int row = e >> 4;            // 0..63
        int g   = e & 15;            // float4 group within 64 cols
        int kr  = k0 + row; if (kr >= len) kr = len - 1;
        size_t goff = (size_t)(base + kr) * D_MODEL + h * HEAD_DIM + g * 4;
        cp_async16(smem_u32(Ks + row * KLD + g * 4), K + goff);
        cp_async16(smem_u32(Vs + row * VLD + g * 4), V + goff);
    }
}

__global__ __launch_bounds__(256)
void flash_attn_mma(const float* __restrict__ Q, const float* __restrict__ K,
                    const float* __restrict__ V, const int* __restrict__ cu,
                    float* __restrict__ O) {
    extern __shared__ float sm[];
    float* Qs  = sm;                         // 128 x 68 (later: P staging)
    float* Ks0 = Qs  + FBQ * QLD;
    float* Ks1 = Ks0 + FBK * KLD;
    float* Vs0 = Ks1 + FBK * KLD;
    float* Vs1 = Vs0 + FBK * VLD;

    const int b  = blockIdx.z;
    const int h  = blockIdx.y;
    const int q0 = blockIdx.x * FBQ;

    const int base = cu[b];
    const int len  = cu[b + 1] - base;
    if (q0 >= len) return;

    const int tid  = threadIdx.x;
    const int wid  = tid >> 5;
    const int lane = tid & 31;
    const int qr   = lane >> 2;     // 0..7
    const int kq   = lane & 3;      // 0..3

    const int nk = (len + FBK - 1) / FBK;

    fa_load_kv(K, V, base, len, h, 0,   Ks0, Vs0, tid); CP_COMMIT();
    fa_load_kv(K, V, base, len, h, FBK, Ks1, Vs1, tid); CP_COMMIT();

    #pragma unroll
    for (int i = 0; i < 8; ++i) {
        int e   = tid + i * 256;     // 0..2047
        int row = e >> 4;            // 0..127
        int g   = e & 15;
        int qi  = q0 + row; if (qi >= len) qi = len - 1;
        float4 v = *(const float4*)(Q + (size_t)(base + qi) * D_MODEL + h * HEAD_DIM + g * 4);
        *(float4*)(Qs + row * QLD + g * 4) = v;
    }
    __syncthreads();

    uint32_t qf[8][4];
    {
        const float* qp = Qs + (wid * 16 + qr) * QLD + kq;
        #pragma unroll
        for (int ks = 0; ks < 8; ++ks) {
            const float* p = qp + ks * 8;
            qf[ks][0] = __float_as_uint(p[0]);
            qf[ks][1] = __float_as_uint(p[8 * QLD]);
            qf[ks][2] = __float_as_uint(p[4]);
            qf[ks][3] = __float_as_uint(p[8 * QLD + 4]);
        }
    }
    __syncthreads();    // all Q frags read; Qs may be reused as P

    float m0 = -3.0e38f, m1 = -3.0e38f, l0 = 0.f, l1 = 0.f;
    float o[8][4];
    #pragma unroll
    for (int dt = 0; dt < 8; ++dt)
        #pragma unroll
        for (int q = 0; q < 4; ++q) o[dt][q] = 0.f;

    float* Pw = Qs + wid * 16 * QLD;   // this warp's 16 x 68 P staging

    for (int kt = 0; kt < nk; ++kt) {
        const int s = kt & 1;
        const float* Ks = s ? Ks1 : Ks0;
        const float* Vs = s ? Vs1 : Vs0;
        if (kt + 1 < nk) { CP_WAIT1(); } else { CP_WAIT0(); }
        __syncthreads();

        float sc[8][4];
        #pragma unroll
        for (int nt = 0; nt < 8; ++nt)
            #pragma unroll
            for (int q = 0; q < 4; ++q) sc[nt][q] = 0.f;

        #pragma unroll
        for (int ks = 0; ks < 8; ++ks) {
            const int kb = ks * 8 + kq;
            #pragma unroll
            for (int nt = 0; nt < 8; ++nt) {
                uint32_t bf[2];
                const float* p = Ks + (nt * 8 + qr) * KLD + kb;
                bf[0] = __float_as_uint(p[0]);
                bf[1] = __float_as_uint(p[4]);
                mma_tf32(sc[nt], qf[ks], bf);
            }
        }

        const int kbase = kt * FBK;
        #pragma unroll
        for (int nt = 0; nt < 8; ++nt) {
            int c0 = kbase + nt * 8 + 2 * kq;
            bool ok0 = c0 < len, ok1 = (c0 + 1) < len;
            sc[nt][0] = ok0 ? sc[nt][0] * ATT_SCALE : NEG_BIG;
            sc[nt][1] = ok1 ? sc[nt][1] * ATT_SCALE : NEG_BIG;
            sc[nt][2] = ok0 ? sc[nt][2] * ATT_SCALE : NEG_BIG;
            sc[nt][3] = ok1 ? sc[nt][3] * ATT_SCALE : NEG_BIG;
        }

        float mx0 = -3.0e38f, mx1 = -3.0e38f;
        #pragma unroll
        for (int nt = 0; nt < 8; ++nt) {
            mx0 = fmaxf(mx0, fmaxf(sc[nt][0], sc[nt][1]));
            mx1 = fmaxf(mx1, fmaxf(sc[nt][2], sc[nt][3]));
        }
        mx0 = fmaxf(mx0, __shfl_xor_sync(0xffffffffu, mx0, 1));
        mx0 = fmaxf(mx0, __shfl_xor_sync(0xffffffffu, mx0, 2));
        mx1 = fmaxf(mx1, __shfl_xor_sync(0xffffffffu, mx1, 1));
        mx1 = fmaxf(mx1, __shfl_xor_sync(0xffffffffu, mx1, 2));

        float nm0 = fmaxf(m0, mx0), nm1 = fmaxf(m1, mx1);
        float a0 = __expf(m0 - nm0), a1 = __expf(m1 - nm1);
        float rs0 = 0.f, rs1 = 0.f;
        #pragma unroll
        for (int nt = 0; nt < 8; ++nt) {
            float p00 = __expf(sc[nt][0] - nm0);
            float p01 = __expf(sc[nt][1] - nm0);
            float p10 = __expf(sc[nt][2] - nm1);
            float p11 = __expf(sc[nt][3] - nm1);
            rs0 += p00 + p01;
            rs1 += p10 + p11;
            float* pp = Pw + qr * QLD + nt * 8 + 2 * kq;
            *(float2*)pp = make_float2(round_tf32(p00), round_tf32(p01));
            *(float2*)(pp + 8 * QLD) = make_float2(round_tf32(p10), round_tf32(p11));
        }
        rs0 += __shfl_xor_sync(0xffffffffu, rs0, 1);
        rs0 += __shfl_xor_sync(0xffffffffu, rs0, 2);
        rs1 += __shfl_xor_sync(0xffffffffu, rs1, 1);
        rs1 += __shfl_xor_sync(0xffffffffu, rs1, 2);

        l0 = l0 * a0 + rs0;  m0 = nm0;
        l1 = l1 * a1 + rs1;  m1 = nm1;
        #pragma unroll
        for (int dt = 0; dt < 8; ++dt) {
            o[dt][0] *= a0; o[dt][1] *= a0;
            o[dt][2] *= a1; o[dt][3] *= a1;
        }
        __syncwarp();

        #pragma unroll
        for (int ks = 0; ks < 8; ++ks) {
            uint32_t pf[4];
            const float* pp = Pw + qr * QLD + ks * 8 + kq;
            pf[0] = __float_as_uint(pp[0]);
            pf[1] = __float_as_uint(pp[8 * QLD]);
            pf[2] = __float_as_uint(pp[4]);
            pf[3] = __float_as_uint(pp[8 * QLD + 4]);
            const float* vrow = Vs + (ks * 8 + kq) * VLD + qr;
            #pragma unroll
            for (int dt = 0; dt < 8; ++dt) {
                uint32_t bf[2];
                bf[0] = __float_as_uint(vrow[dt * 8]);
                bf[1] = __float_as_uint(vrow[4 * VLD + dt * 8]);
                mma_tf32(o[dt], pf, bf);
            }
        }
        __syncthreads();   // done reading stage s (and P) before overwrite

        if (kt + 2 < nk) {
            fa_load_kv(K, V, base, len, h, (kt + 2) * FBK,
                       s ? Ks1 : Ks0, s ? Vs1 : Vs0, tid);
            CP_COMMIT();
        }
    }

    const int qr0 = q0 + wid * 16 + qr;
    const int qr1 = qr0 + 8;
    const float inv0 = 1.0f / l0, inv1 = 1.0f / l1;
    #pragma unroll
    for (int dt = 0; dt < 8; ++dt) {
        int col = h * HEAD_DIM + dt * 8 + 2 * kq;
        if (qr0 < len)
            *(float2*)(O + (size_t)(base + qr0) * D_MODEL + col) =
                make_float2(round_tf32(o[dt][0] * inv0), round_tf32(o[dt][1] * inv0));
        if (qr1 < len)
            *(float2*)(O + (size_t)(base + qr1) * D_MODEL + col) =
                make_float2(round_tf32(o[dt][2] * inv1), round_tf32(o[dt][3] * inv1));
    }
}

// ---------------- host launcher ----------------------------------------------
extern "C" void kernel_launch(void* const* d_in, const int* in_sizes, int n_in,
                              void* d_out, int out_size) {
    const float* hs = (const float*)d_in[0];
    const int*   cu = (const int*)d_in[1];
    const float* Wq = (const float*)d_in[2];
    const float* bq = (const float*)d_in[3];
    const float* Wk = (const float*)d_in[4];
    const float* Wv = (const float*)d_in[5];
    const float* bv = (const float*)d_in[6];
    const float* Wo = (const float*)d_in[7];
    const float* bo = (const float*)d_in[8];
    float* out = (float*)d_out;

    const int T    = in_sizes[0] / D_MODEL;   // 6000
    const int Bseg = in_sizes[1] - 1;         // 4

    float *pq, *pk, *pv, *pa, *phr, *pwr, *pbias;
    cudaGetSymbolAddress((void**)&pq,    g_q);
    cudaGetSymbolAddress((void**)&pk,    g_k);
    cudaGetSymbolAddress((void**)&pv,    g_v);
    cudaGetSymbolAddress((void**)&pa,    g_attn);
    cudaGetSymbolAddress((void**)&phr,   g_hs_r);
    cudaGetSymbolAddress((void**)&pwr,   g_w_r);
    cudaGetSymbolAddress((void**)&pbias, g_bias);
    float* pwq = pwr + 0 * D_MODEL * D_MODEL;
    float* pwk = pwr + 1 * D_MODEL * D_MODEL;
    float* pwv = pwr + 2 * D_MODEL * D_MODEL;
    float* pwo = pwr + 3 * D_MODEL * D_MODEL;

    cudaFuncSetAttribute(flash_attn_mma, cudaFuncAttributeMaxDynamicSharedMemorySize,
                         FA_SMEM_BYTES);
    cudaFuncSetAttribute(gemm_tf32mma, cudaFuncAttributeMaxDynamicSharedMemorySize,
                         GT_SMEM_BYTES);

    // tf32-round GEMM operands (RN rounding, unbiased) + combined qkv bias
    {
        int n4 = (T * D_MODEL) / 4;
        round_tf32_kernel<<<(n4 + 255) / 256, 256>>>((const float4*)hs, (float4*)phr, n4);
        int w4 = (D_MODEL * D_MODEL) / 4;
        int wg = (w4 + 255) / 256;
        round_tf32_kernel<<<wg, 256>>>((const float4*)Wq, (float4*)pwq, w4);
        round_tf32_kernel<<<wg, 256>>>((const float4*)Wk, (float4*)pwk, w4);
        round_tf32_kernel<<<wg, 256>>>((const float4*)Wv, (float4*)pwv, w4);
        round_tf32_kernel<<<wg, 256>>>((const float4*)Wo, (float4*)pwo, w4);
        build_qkv_bias<<<(3 * D_MODEL + 255) / 256, 256>>>(bq, bv, pbias);
    }

    // merged QKV projection: C[:, 0:3840] = hs_r @ [Wq|Wk|Wv]^T + [bq|0|bv]
    dim3 qkvgrid(3 * D_MODEL / BNg, (T + BMg - 1) / BMg);   // (30, 47)
    gemm_tf32mma<<<qkvgrid, 256, GT_SMEM_BYTES>>>(phr, pwr, pbias,
                                                  pq, pk, pv, T, 1);

    // attention (tensor-core tf32, fp32 accumulate; output tf32-rounded)
    dim3 fgrid((MAX_SEQLEN + FBQ - 1) / FBQ, NUM_HEADS, Bseg);
    flash_attn_mma<<<fgrid, 256, FA_SMEM_BYTES>>>(pq, pk, pv, cu, pa);

    // output projection (single matrix, grid.x=10 -> mat id always 0)
    dim3 ogrid(D_MODEL / BNg, (T + BMg - 1) / BMg);         // (10, 47)
    gemm_tf32mma<<<ogrid, 256, GT_SMEM_BYTES>>>(pa, pwo, bo,
                                                out, out, out, T, 0);
}

// round 8
// speedup vs baseline: 4.3083x; 1.0387x over previous
#include <cuda_runtime.h>
#include <cuda_bf16.h>
#include <cstdint>

// Problem constants (static shapes from setup_inputs)
#define D_MODEL 1280
#define NUM_HEADS 20
#define HEAD_DIM 64
#define MAX_SEQLEN 1500
#define MAX_T 6000           // 4 * 1500
#define ATT_SCALE 0.125f     // 64^-0.5
#define NEG_BIG -1e30f

// ---------------- scratch (static device globals; no runtime alloc) ----------
__device__ float g_q[MAX_T * D_MODEL];
__device__ float g_k[MAX_T * D_MODEL];
__device__ float g_v[MAX_T * D_MODEL];
__device__ float g_attn[MAX_T * D_MODEL];
__device__ float g_hs_r[MAX_T * D_MODEL];           // tf32-rounded hidden states
__device__ float g_w_r[4][D_MODEL * D_MODEL];       // tf32-rounded Wq,Wk,Wv,Wo (contiguous)
__device__ float g_bias[3 * D_MODEL];               // combined bq | 0 | bv

// ========================= PTX helpers ======================================
__device__ __forceinline__ uint32_t smem_u32(const void* p) {
    uint32_t a;
    asm("{ .reg .u64 t; cvta.to.shared.u64 t, %1; cvt.u32.u64 %0, t; }"
        : "=r"(a) : "l"(p));
    return a;
}

__device__ __forceinline__ void cp_async16(uint32_t dst, const void* src) {
    asm volatile("cp.async.cg.shared.global [%0], [%1], 16;"
                 :: "r"(dst), "l"(src));
}
#define CP_COMMIT() asm volatile("cp.async.commit_group;" ::: "memory")
#define CP_WAIT0()  asm volatile("cp.async.wait_group 0;" ::: "memory")
#define CP_WAIT1()  asm volatile("cp.async.wait_group 1;" ::: "memory")

__device__ __forceinline__ float round_tf32(float v) {
    uint32_t t;
    asm("cvt.rn.tf32.f32 %0, %1;" : "=r"(t) : "f"(v));
    return __uint_as_float(t);
}

// mma.sync m16n8k8 tf32: D[16,8] += A[16,8] @ B[8,8]  (A row-major, B col-major)
__device__ __forceinline__ void mma_tf32(float c[4], const uint32_t a[4],
                                         const uint32_t b[2]) {
    asm volatile(
        "mma.sync.aligned.m16n8k8.row.col.f32.tf32.tf32.f32 "
        "{%0,%1,%2,%3}, {%4,%5,%6,%7}, {%8,%9}, {%0,%1,%2,%3};"
        : "+f"(c[0]), "+f"(c[1]), "+f"(c[2]), "+f"(c[3])
        : "r"(a[0]), "r"(a[1]), "r"(a[2]), "r"(a[3]), "r"(b[0]), "r"(b[1]));
}

// ================= fused prep kernel: tf32 rounding + bias build =============
#define H4  (MAX_T * D_MODEL / 4)            // 1,920,000 float4 of hidden states
#define W4  (D_MODEL * D_MODEL / 4)          // 409,600 float4 per weight
#define B4  (3 * D_MODEL / 4)                // 960 float4 of combined bias
#define PREP_TOTAL (H4 + 4 * W4 + B4)

__global__ __launch_bounds__(256)
void prep_kernel(const float4* __restrict__ hs,
                 const float4* __restrict__ wq, const float4* __restrict__ wk,
                 const float4* __restrict__ wv, const float4* __restrict__ wo,
                 const float* __restrict__ bq, const float* __restrict__ bv,
                 float4* __restrict__ hs_r, float4* __restrict__ w_r,
                 float* __restrict__ bias) {
    int i = blockIdx.x * blockDim.x + threadIdx.x;
    if (i < H4) {
        float4 v = hs[i];
        v.x = round_tf32(v.x); v.y = round_tf32(v.y);
        v.z = round_tf32(v.z); v.w = round_tf32(v.w);
        hs_r[i] = v;
    } else if (i < H4 + 4 * W4) {
        int j = i - H4;
        const float4* src = (j < W4) ? wq : (j < 2 * W4) ? wk : (j < 3 * W4) ? wv : wo;
        float4 v = src[j & (W4 - 1)];   // W4 is power-of-2? 409600 not pow2 -> use mod
        // (W4 = 409600, not a power of two; recompute safely)
        v = src[j - (j / W4) * W4];
        v.x = round_tf32(v.x); v.y = round_tf32(v.y);
        v.z = round_tf32(v.z); v.w = round_tf32(v.w);
        w_r[j] = v;
    } else if (i < PREP_TOTAL) {
        int j = (i - H4 - 4 * W4) * 4;      // element index 0..3836 step 4
        #pragma unroll
        for (int e = 0; e < 4; ++e) {
            int idx = j + e;
            float v = 0.f;
            if (idx < D_MODEL) v = bq[idx];
            else if (idx >= 2 * D_MODEL) v = bv[idx - 2 * D_MODEL];
            bias[idx] = v;
        }
    }
}

// ============ tf32 mma.sync GEMM: C[M, n_mats*1280] = A @ B^T + bias =========
// CTA tile 256x128, BK=32, 8 warps (4 M x 2 N), warp tile 64x64.
// 3-stage cp.async pipeline, one barrier per K-chunk.
#define BMg 256
#define BNg 128
#define BKg 32
#define LDAg 36                                      // 32 + 4 pad (floats)
#define ASTG (BMg * LDAg)                            // 9216 floats (36 KB)
#define BSTG (BNg * LDAg)                            // 4608 floats (18 KB)
#define STAGE_FLOATS (ASTG + BSTG)                   // 13824 floats (54 KB)
#define GT_SMEM_BYTES (3 * STAGE_FLOATS * 4)         // 162 KB

__device__ __forceinline__ void gt_load(const float* __restrict__ A,
                                        const float* __restrict__ B,
                                        int M, int m0, int n0, int k0,
                                        float* sA, float* sB, int tid) {
    // A: 256 rows x 32 cols = 2048 float4 -> 8 per thread
    #pragma unroll
    for (int i = 0; i < 8; ++i) {
        int e   = tid + i * 256;
        int row = e >> 3;             // 0..255
        int g   = e & 7;              // float4 group within 32 k-cols
        int ar  = m0 + row; if (ar >= M) ar = M - 1;   // clamp; masked at store
        cp_async16(smem_u32(sA + row * LDAg + g * 4),
                   A + (size_t)ar * D_MODEL + k0 + g * 4);
    }
    // B: 128 rows x 32 cols = 1024 float4 -> 4 per thread
    #pragma unroll
    for (int i = 0; i < 4; ++i) {
        int e   = tid + i * 256;
        int row = e >> 3;             // 0..127
        int g   = e & 7;
        cp_async16(smem_u32(sB + row * LDAg + g * 4),
                   B + (size_t)(n0 + row) * D_MODEL + k0 + g * 4);
    }
}

__global__ __launch_bounds__(256, 1)
void gemm_tf32mma(const float* __restrict__ A, const float* __restrict__ B,
                  const float* __restrict__ bias,
                  float* __restrict__ C0, float* __restrict__ C1,
                  float* __restrict__ C2, int M, int round_out) {
    extern __shared__ float sm[];
    float* sA[3] = { sm, sm + STAGE_FLOATS, sm + 2 * STAGE_FLOATS };
    float* sB[3] = { sm + ASTG, sm + STAGE_FLOATS + ASTG, sm + 2 * STAGE_FLOATS + ASTG };

    const int tid  = threadIdx.x;
    const int wid  = tid >> 5;
    const int lane = tid & 31;
    const int wm   = wid & 3;          // warp row (0..3) -> 64 rows each
    const int wn   = wid >> 2;         // warp col (0..1) -> 64 cols each
    const int m0   = blockIdx.y * BMg;
    const int n0   = blockIdx.x * BNg;             // global column (bias/B space)

    const int arow = wm * 64 + (lane >> 2);
    const int brow = wn * 64 + (lane >> 2);
    const int kq   = lane & 3;

    float c[4][8][4];                  // [mt][nt][frag]
    #pragma unroll
    for (int mt = 0; mt < 4; ++mt)
        #pragma unroll
        for (int nt = 0; nt < 8; ++nt)
            #pragma unroll
            for (int q = 0; q < 4; ++q) c[mt][nt][q] = 0.f;

    const int NCH = D_MODEL / BKg;     // 40
    gt_load(A, B, M, m0, n0, 0,   sA[0], sB[0], tid); CP_COMMIT();
    gt_load(A, B, M, m0, n0, BKg, sA[1], sB[1], tid); CP_COMMIT();

    for (int ch = 0; ch < NCH; ++ch) {
        if (ch == NCH - 1) { CP_WAIT0(); } else { CP_WAIT1(); }
        __syncthreads();               // one barrier per chunk
        if (ch + 2 < NCH) {
            gt_load(A, B, M, m0, n0, (ch + 2) * BKg,
                    sA[(ch + 2) % 3], sB[(ch + 2) % 3], tid);
            CP_COMMIT();
        }
        const float* cA = sA[ch % 3];
        const float* cB = sB[ch % 3];

        #pragma unroll
        for (int kk = 0; kk < 4; ++kk) {
            const int kb = kk * 8 + kq;
            uint32_t af[4][4];
            #pragma unroll
            for (int mt = 0; mt < 4; ++mt) {
                const float* p = cA + (arow + mt * 16) * LDAg + kb;
                af[mt][0] = __float_as_uint(p[0]);
                af[mt][1] = __float_as_uint(p[8 * LDAg]);
                af[mt][2] = __float_as_uint(p[4]);
                af[mt][3] = __float_as_uint(p[8 * LDAg + 4]);
            }
            uint32_t bf[8][2];
            #pragma unroll
            for (int nt = 0; nt < 8; ++nt) {
                const float* p = cB + (brow + nt * 8) * LDAg + kb;
                bf[nt][0] = __float_as_uint(p[0]);
                bf[nt][1] = __float_as_uint(p[4]);
            }
            #pragma unroll
            for (int mt = 0; mt < 4; ++mt)
                #pragma unroll
                for (int nt = 0; nt < 8; ++nt)
                    mma_tf32(c[mt][nt], af[mt], bf[nt]);
        }
    }

    // route output block to its matrix (10 column-blocks per 1280-wide matrix)
    const int mat = blockIdx.x / 10;
    float* C = (mat == 0) ? C0 : ((mat == 1) ? C1 : C2);
    const int ncol0 = (blockIdx.x - mat * 10) * BNg;   // column within matrix

    // epilogue: fragment -> global (float2 stores), + bias, optional tf32 round
    const int crow = m0 + wm * 64 + (lane >> 2);
    const int ccol = wn * 64 + 2 * (lane & 3);
    #pragma unroll
    for (int nt = 0; nt < 8; ++nt) {
        int col  = ccol + nt * 8;
        float b0 = bias[n0 + col];
        float b1 = bias[n0 + col + 1];
        int colg = ncol0 + col;
        #pragma unroll
        for (int mt = 0; mt < 4; ++mt) {
            int r0 = crow + mt * 16;
            if (r0 < M) {
                float v0 = c[mt][nt][0] + b0, v1 = c[mt][nt][1] + b1;
                if (round_out) { v0 = round_tf32(v0); v1 = round_tf32(v1); }
                *(float2*)(C + (size_t)r0 * D_MODEL + colg) = make_float2(v0, v1);
            }
            int r1 = r0 + 8;
            if (r1 < M) {
                float v0 = c[mt][nt][2] + b0, v1 = c[mt][nt][3] + b1;
                if (round_out) { v0 = round_tf32(v0); v1 = round_tf32(v1); }
                *(float2*)(C + (size_t)r1 * D_MODEL + colg) = make_float2(v0, v1);
            }
        }
    }
}

// ================ tensor-core flash attention (unchanged from R6/R7) =========
#define FBQ 128
#define FBK 64
#define QLD 68
#define KLD 68
#define VLD 72
#define FA_SMEM_FLOATS (FBQ*QLD + 2*FBK*KLD + 2*FBK*VLD)
#define FA_SMEM_BYTES  (FA_SMEM_FLOATS * 4)

__device__ __forceinline__ void fa_load_kv(const float* __restrict__ K,
                                           const float* __restrict__ V,
                                           int base, int len, int h, int k0,
                                           float* Ks, float* Vs, int tid) {
    #pragma unroll
    for (int i = 0; i < 4; ++i) {
        int e   = tid + i * 256;     // 0..1023
        int row = e >> 4;            // 0..63
        int g   = e & 15;            // float4 group within 64 cols
        int kr  = k0 + row; if (kr >= len) kr = len - 1;
        size_t goff = (size_t)(base + kr) * D_MODEL + h * HEAD_DIM + g * 4;
        cp_async16(smem_u32(Ks + row * KLD + g * 4), K + goff);
        cp_async16(smem_u32(Vs + row * VLD + g * 4), V + goff);
    }
}

__global__ __launch_bounds__(256)
void flash_attn_mma(const float* __restrict__ Q, const float* __restrict__ K,
                    const float* __restrict__ V, const int* __restrict__ cu,
                    float* __restrict__ O) {
    extern __shared__ float sm[];
    float* Qs  = sm;                         // 128 x 68 (later: P staging)
    float* Ks0 = Qs  + FBQ * QLD;
    float* Ks1 = Ks0 + FBK * KLD;
    float* Vs0 = Ks1 + FBK * KLD;
    float* Vs1 = Vs0 + FBK * VLD;

    const int b  = blockIdx.z;
    const int h  = blockIdx.y;
    const int q0 = blockIdx.x * FBQ;

    const int base = cu[b];
    const int len  = cu[b + 1] - base;
    if (q0 >= len) return;

    const int tid  = threadIdx.x;
    const int wid  = tid >> 5;
    const int lane = tid & 31;
    const int qr   = lane >> 2;     // 0..7
    const int kq   = lane & 3;      // 0..3

    const int nk = (len + FBK - 1) / FBK;

    fa_load_kv(K, V, base, len, h, 0,   Ks0, Vs0, tid); CP_COMMIT();
    fa_load_kv(K, V, base, len, h, FBK, Ks1, Vs1, tid); CP_COMMIT();

    #pragma unroll
    for (int i = 0; i < 8; ++i) {
        int e   = tid + i * 256;     // 0..2047
        int row = e >> 4;            // 0..127
        int g   = e & 15;
        int qi  = q0 + row; if (qi >= len) qi = len - 1;
        float4 v = *(const float4*)(Q + (size_t)(base + qi) * D_MODEL + h * HEAD_DIM + g * 4);
        *(float4*)(Qs + row * QLD + g * 4) = v;
    }
    __syncthreads();

    uint32_t qf[8][4];
    {
        const float* qp = Qs + (wid * 16 + qr) * QLD + kq;
        #pragma unroll
        for (int ks = 0; ks < 8; ++ks) {
            const float* p = qp + ks * 8;
            qf[ks][0] = __float_as_uint(p[0]);
            qf[ks][1] = __float_as_uint(p[8 * QLD]);
            qf[ks][2] = __float_as_uint(p[4]);
            qf[ks][3] = __float_as_uint(p[8 * QLD + 4]);
        }
    }
    __syncthreads();    // all Q frags read; Qs may be reused as P

    float m0 = -3.0e38f, m1 = -3.0e38f, l0 = 0.f, l1 = 0.f;
    float o[8][4];
    #pragma unroll
    for (int dt = 0; dt < 8; ++dt)
        #pragma unroll
        for (int q = 0; q < 4; ++q) o[dt][q] = 0.f;

    float* Pw = Qs + wid * 16 * QLD;   // this warp's 16 x 68 P staging

    for (int kt = 0; kt < nk; ++kt) {
        const int s = kt & 1;
        const float* Ks = s ? Ks1 : Ks0;
        const float* Vs = s ? Vs1 : Vs0;
        if (kt + 1 < nk) { CP_WAIT1(); } else { CP_WAIT0(); }
        __syncthreads();

        float sc[8][4];
        #pragma unroll
        for (int nt = 0; nt < 8; ++nt)
            #pragma unroll
            for (int q = 0; q < 4; ++q) sc[nt][q] = 0.f;

        #pragma unroll
        for (int ks = 0; ks < 8; ++ks) {
            const int kb = ks * 8 + kq;
            #pragma unroll
            for (int nt = 0; nt < 8; ++nt) {
                uint32_t bf[2];
                const float* p = Ks + (nt * 8 + qr) * KLD + kb;
                bf[0] = __float_as_uint(p[0]);
                bf[1] = __float_as_uint(p[4]);
                mma_tf32(sc[nt], qf[ks], bf);
            }
        }

        const int kbase = kt * FBK;
        #pragma unroll
        for (int nt = 0; nt < 8; ++nt) {
            int c0 = kbase + nt * 8 + 2 * kq;
            bool ok0 = c0 < len, ok1 = (c0 + 1) < len;
            sc[nt][0] = ok0 ? sc[nt][0] * ATT_SCALE : NEG_BIG;
            sc[nt][1] = ok1 ? sc[nt][1] * ATT_SCALE : NEG_BIG;
            sc[nt][2] = ok0 ? sc[nt][2] * ATT_SCALE : NEG_BIG;
            sc[nt][3] = ok1 ? sc[nt][3] * ATT_SCALE : NEG_BIG;
        }

        float mx0 = -3.0e38f, mx1 = -3.0e38f;
        #pragma unroll
        for (int nt = 0; nt < 8; ++nt) {
            mx0 = fmaxf(mx0, fmaxf(sc[nt][0], sc[nt][1]));
            mx1 = fmaxf(mx1, fmaxf(sc[nt][2], sc[nt][3]));
        }
        mx0 = fmaxf(mx0, __shfl_xor_sync(0xffffffffu, mx0, 1));
        mx0 = fmaxf(mx0, __shfl_xor_sync(0xffffffffu, mx0, 2));
        mx1 = fmaxf(mx1, __shfl_xor_sync(0xffffffffu, mx1, 1));
        mx1 = fmaxf(mx1, __shfl_xor_sync(0xffffffffu, mx1, 2));

        float nm0 = fmaxf(m0, mx0), nm1 = fmaxf(m1, mx1);
        float a0 = __expf(m0 - nm0), a1 = __expf(m1 - nm1);
        float rs0 = 0.f, rs1 = 0.f;
        #pragma unroll
        for (int nt = 0; nt < 8; ++nt) {
            float p00 = __expf(sc[nt][0] - nm0);
            float p01 = __expf(sc[nt][1] - nm0);
            float p10 = __expf(sc[nt][2] - nm1);
            float p11 = __expf(sc[nt][3] - nm1);
            rs0 += p00 + p01;
            rs1 += p10 + p11;
            float* pp = Pw + qr * QLD + nt * 8 + 2 * kq;
            *(float2*)pp = make_float2(round_tf32(p00), round_tf32(p01));
            *(float2*)(pp + 8 * QLD) = make_float2(round_tf32(p10), round_tf32(p11));
        }
        rs0 += __shfl_xor_sync(0xffffffffu, rs0, 1);
        rs0 += __shfl_xor_sync(0xffffffffu, rs0, 2);
        rs1 += __shfl_xor_sync(0xffffffffu, rs1, 1);
        rs1 += __shfl_xor_sync(0xffffffffu, rs1, 2);

        l0 = l0 * a0 + rs0;  m0 = nm0;
        l1 = l1 * a1 + rs1;  m1 = nm1;
        #pragma unroll
        for (int dt = 0; dt < 8; ++dt) {
            o[dt][0] *= a0; o[dt][1] *= a0;
            o[dt][2] *= a1; o[dt][3] *= a1;
        }
        __syncwarp();

        #pragma unroll
        for (int ks = 0; ks < 8; ++ks) {
            uint32_t pf[4];
            const float* pp = Pw + qr * QLD + ks * 8 + kq;
            pf[0] = __float_as_uint(pp[0]);
            pf[1] = __float_as_uint(pp[8 * QLD]);
            pf[2] = __float_as_uint(pp[4]);
            pf[3] = __float_as_uint(pp[8 * QLD + 4]);
            const float* vrow = Vs + (ks * 8 + kq) * VLD + qr;
            #pragma unroll
            for (int dt = 0; dt < 8; ++dt) {
                uint32_t bf[2];
                bf[0] = __float_as_uint(vrow[dt * 8]);
                bf[1] = __float_as_uint(vrow[4 * VLD + dt * 8]);
                mma_tf32(o[dt], pf, bf);
            }
        }
        __syncthreads();   // done reading stage s (and P) before overwrite

        if (kt + 2 < nk) {
            fa_load_kv(K, V, base, len, h, (kt + 2) * FBK,
                       s ? Ks1 : Ks0, s ? Vs1 : Vs0, tid);
            CP_COMMIT();
        }
    }

    const int qr0 = q0 + wid * 16 + qr;
    const int qr1 = qr0 + 8;
    const float inv0 = 1.0f / l0, inv1 = 1.0f / l1;
    #pragma unroll
    for (int dt = 0; dt < 8; ++dt) {
        int col = h * HEAD_DIM + dt * 8 + 2 * kq;
        if (qr0 < len)
            *(float2*)(O + (size_t)(base + qr0) * D_MODEL + col) =
                make_float2(round_tf32(o[dt][0] * inv0), round_tf32(o[dt][1] * inv0));
        if (qr1 < len)
            *(float2*)(O + (size_t)(base + qr1) * D_MODEL + col) =
                make_float2(round_tf32(o[dt][2] * inv1), round_tf32(o[dt][3] * inv1));
    }
}

// ---------------- host launcher ----------------------------------------------
extern "C" void kernel_launch(void* const* d_in, const int* in_sizes, int n_in,
                              void* d_out, int out_size) {
    const float* hs = (const float*)d_in[0];
    const int*   cu = (const int*)d_in[1];
    const float* Wq = (const float*)d_in[2];
    const float* bq = (const float*)d_in[3];
    const float* Wk = (const float*)d_in[4];
    const float* Wv = (const float*)d_in[5];
    const float* bv = (const float*)d_in[6];
    const float* Wo = (const float*)d_in[7];
    const float* bo = (const float*)d_in[8];
    float* out = (float*)d_out;

    const int T    = in_sizes[0] / D_MODEL;   // 6000
    const int Bseg = in_sizes[1] - 1;         // 4

    float *pq, *pk, *pv, *pa, *phr, *pwr, *pbias;
    cudaGetSymbolAddress((void**)&pq,    g_q);
    cudaGetSymbolAddress((void**)&pk,    g_k);
    cudaGetSymbolAddress((void**)&pv,    g_v);
    cudaGetSymbolAddress((void**)&pa,    g_attn);
    cudaGetSymbolAddress((void**)&phr,   g_hs_r);
    cudaGetSymbolAddress((void**)&pwr,   g_w_r);
    cudaGetSymbolAddress((void**)&pbias, g_bias);
    float* pwo = pwr + 3 * D_MODEL * D_MODEL;

    cudaFuncSetAttribute(flash_attn_mma, cudaFuncAttributeMaxDynamicSharedMemorySize,
                         FA_SMEM_BYTES);
    cudaFuncSetAttribute(gemm_tf32mma, cudaFuncAttributeMaxDynamicSharedMemorySize,
                         GT_SMEM_BYTES);

    // fused prep: tf32-round hs + 4 weights, build combined qkv bias
    prep_kernel<<<(PREP_TOTAL + 255) / 256, 256>>>(
        (const float4*)hs, (const float4*)Wq, (const float4*)Wk,
        (const float4*)Wv, (const float4*)Wo, bq, bv,
        (float4*)phr, (float4*)pwr, pbias);

    // merged QKV projection: C[:, 0:3840] = hs_r @ [Wq|Wk|Wv]^T + [bq|0|bv]
    dim3 qkvgrid(3 * D_MODEL / BNg, (T + BMg - 1) / BMg);   // (30, 24)
    gemm_tf32mma<<<qkvgrid, 256, GT_SMEM_BYTES>>>(phr, pwr, pbias,
                                                  pq, pk, pv, T, 1);

    // attention (tensor-core tf32, fp32 accumulate; output tf32-rounded)
    dim3 fgrid((MAX_SEQLEN + FBQ - 1) / FBQ, NUM_HEADS, Bseg);
    flash_attn_mma<<<fgrid, 256, FA_SMEM_BYTES>>>(pq, pk, pv, cu, pa);

    // output projection (single matrix, grid.x=10 -> mat id always 0)
    dim3 ogrid(D_MODEL / BNg, (T + BMg - 1) / BMg);         // (10, 24)
    gemm_tf32mma<<<ogrid, 256, GT_SMEM_BYTES>>>(pa, pwo, bo,
                                                out, out, out, T, 0);
}

// round 9
// speedup vs baseline: 4.3247x; 1.0038x over previous
#include <cuda_runtime.h>
#include <cuda_bf16.h>
#include <cstdint>

// Problem constants (static shapes from setup_inputs)
#define D_MODEL 1280
#define NUM_HEADS 20
#define HEAD_DIM 64
#define MAX_SEQLEN 1500
#define MAX_T 6000           // 4 * 1500
#define ATT_SCALE 0.125f     // 64^-0.5
#define NEG_BIG -1e30f

// ---------------- scratch (static device globals; no runtime alloc) ----------
__device__ float g_q[MAX_T * D_MODEL];
__device__ float g_k[MAX_T * D_MODEL];
__device__ float g_v[MAX_T * D_MODEL];
__device__ float g_attn[MAX_T * D_MODEL];
__device__ float g_hs_r[MAX_T * D_MODEL];           // tf32-rounded hidden states
__device__ float g_w_r[4][D_MODEL * D_MODEL];       // tf32-rounded Wq,Wk,Wv,Wo (contiguous)
__device__ float g_bias[3 * D_MODEL];               // combined bq | 0 | bv

// ========================= PTX helpers ======================================
__device__ __forceinline__ uint32_t smem_u32(const void* p) {
    uint32_t a;
    asm("{ .reg .u64 t; cvta.to.shared.u64 t, %1; cvt.u32.u64 %0, t; }"
        : "=r"(a) : "l"(p));
    return a;
}

__device__ __forceinline__ void cp_async16(uint32_t dst, const void* src) {
    asm volatile("cp.async.cg.shared.global [%0], [%1], 16;"
                 :: "r"(dst), "l"(src));
}
#define CP_COMMIT() asm volatile("cp.async.commit_group;" ::: "memory")
#define CP_WAIT0()  asm volatile("cp.async.wait_group 0;" ::: "memory")
#define CP_WAIT1()  asm volatile("cp.async.wait_group 1;" ::: "memory")

__device__ __forceinline__ float round_tf32(float v) {
    uint32_t t;
    asm("cvt.rn.tf32.f32 %0, %1;" : "=r"(t) : "f"(v));
    return __uint_as_float(t);
}

// mma.sync m16n8k8 tf32: D[16,8] += A[16,8] @ B[8,8]  (A row-major, B col-major)
__device__ __forceinline__ void mma_tf32(float c[4], const uint32_t a[4],
                                         const uint32_t b[2]) {
    asm volatile(
        "mma.sync.aligned.m16n8k8.row.col.f32.tf32.tf32.f32 "
        "{%0,%1,%2,%3}, {%4,%5,%6,%7}, {%8,%9}, {%0,%1,%2,%3};"
        : "+f"(c[0]), "+f"(c[1]), "+f"(c[2]), "+f"(c[3])
        : "r"(a[0]), "r"(a[1]), "r"(a[2]), "r"(a[3]), "r"(b[0]), "r"(b[1]));
}

// ================= fused prep kernel: tf32 rounding + bias build =============
#define H4  (MAX_T * D_MODEL / 4)            // 1,920,000 float4 of hidden states
#define W4  (D_MODEL * D_MODEL / 4)          // 409,600 float4 per weight
#define B4  (3 * D_MODEL / 4)                // 960 float4 of combined bias
#define PREP_TOTAL (H4 + 4 * W4 + B4)

__global__ __launch_bounds__(256)
void prep_kernel(const float4* __restrict__ hs,
                 const float4* __restrict__ wq, const float4* __restrict__ wk,
                 const float4* __restrict__ wv, const float4* __restrict__ wo,
                 const float* __restrict__ bq, const float* __restrict__ bv,
                 float4* __restrict__ hs_r, float4* __restrict__ w_r,
                 float* __restrict__ bias) {
    int i = blockIdx.x * blockDim.x + threadIdx.x;
    if (i < H4) {
        float4 v = hs[i];
        v.x = round_tf32(v.x); v.y = round_tf32(v.y);
        v.z = round_tf32(v.z); v.w = round_tf32(v.w);
        hs_r[i] = v;
    } else if (i < H4 + 4 * W4) {
        int j = i - H4;
        const float4* src = (j < W4) ? wq : (j < 2 * W4) ? wk : (j < 3 * W4) ? wv : wo;
        float4 v = src[j - (j / W4) * W4];
        v.x = round_tf32(v.x); v.y = round_tf32(v.y);
        v.z = round_tf32(v.z); v.w = round_tf32(v.w);
        w_r[j] = v;
    } else if (i < PREP_TOTAL) {
        int j = (i - H4 - 4 * W4) * 4;      // element index 0..3836 step 4
        #pragma unroll
        for (int e = 0; e < 4; ++e) {
            int idx = j + e;
            float v = 0.f;
            if (idx < D_MODEL) v = bq[idx];
            else if (idx >= 2 * D_MODEL) v = bv[idx - 2 * D_MODEL];
            bias[idx] = v;
        }
    }
}

// ============ tf32 mma.sync GEMM: C[M, n_mats*1280] = A @ B^T + bias =========
// CTA tile 128x128, BK=32, 8 warps (2 M x 4 N), warp tile 64x32.
// 3-stage cp.async pipeline, one barrier per chunk, 2 CTAs/SM.
#define BMg 128
#define BNg 128
#define BKg 32
#define LDAg 36                                      // 32 + 4 pad (floats)
#define ASTG (BMg * LDAg)                            // 4608 floats (18 KB)
#define BSTG (BNg * LDAg)                            // 4608 floats (18 KB)
#define STAGE_FLOATS (ASTG + BSTG)                   // 9216 floats (36 KB)
#define GT_SMEM_BYTES (3 * STAGE_FLOATS * 4)         // 110.6 KB -> 2 CTAs/SM

__device__ __forceinline__ void gt_load(const float* __restrict__ A,
                                        const float* __restrict__ B,
                                        int M, int m0, int n0, int k0,
                                        float* sA, float* sB, int tid) {
    // A: 128 rows x 32 cols = 1024 float4 -> 4 per thread
    #pragma unroll
    for (int i = 0; i < 4; ++i) {
        int e   = tid + i * 256;
        int row = e >> 3;             // 0..127
        int g   = e & 7;              // float4 group within 32 k-cols
        int ar  = m0 + row; if (ar >= M) ar = M - 1;   // clamp; masked at store
        cp_async16(smem_u32(sA + row * LDAg + g * 4),
                   A + (size_t)ar * D_MODEL + k0 + g * 4);
        cp_async16(smem_u32(sB + row * LDAg + g * 4),
                   B + (size_t)(n0 + row) * D_MODEL + k0 + g * 4);
    }
}

__global__ __launch_bounds__(256, 2)
void gemm_tf32mma(const float* __restrict__ A, const float* __restrict__ B,
                  const float* __restrict__ bias,
                  float* __restrict__ C0, float* __restrict__ C1,
                  float* __restrict__ C2, int M, int round_out) {
    extern __shared__ float sm[];
    float* sA[3] = { sm, sm + STAGE_FLOATS, sm + 2 * STAGE_FLOATS };
    float* sB[3] = { sm + ASTG, sm + STAGE_FLOATS + ASTG, sm + 2 * STAGE_FLOATS + ASTG };

    const int tid  = threadIdx.x;
    const int wid  = tid >> 5;
    const int lane = tid & 31;
    const int wm   = wid & 1;          // warp row (0..1) -> 64 rows each
    const int wn   = wid >> 1;         // warp col (0..3) -> 32 cols each
    const int m0   = blockIdx.y * BMg;
    const int n0   = blockIdx.x * BNg;             // global column (bias/B space)

    const int arow = wm * 64 + (lane >> 2);
    const int brow = wn * 32 + (lane >> 2);
    const int kq   = lane & 3;

    float c[4][4][4];                  // [mt][nt][frag] -> 64 accumulator regs
    #pragma unroll
    for (int mt = 0; mt < 4; ++mt)
        #pragma unroll
        for (int nt = 0; nt < 4; ++nt)
            #pragma unroll
            for (int q = 0; q < 4; ++q) c[mt][nt][q] = 0.f;

    const int NCH = D_MODEL / BKg;     // 40
    gt_load(A, B, M, m0, n0, 0,   sA[0], sB[0], tid); CP_COMMIT();
    gt_load(A, B, M, m0, n0, BKg, sA[1], sB[1], tid); CP_COMMIT();

    for (int ch = 0; ch < NCH; ++ch) {
        if (ch == NCH - 1) { CP_WAIT0(); } else { CP_WAIT1(); }
        __syncthreads();               // one barrier per chunk
        if (ch + 2 < NCH) {
            gt_load(A, B, M, m0, n0, (ch + 2) * BKg,
                    sA[(ch + 2) % 3], sB[(ch + 2) % 3], tid);
            CP_COMMIT();
        }
        const float* cA = sA[ch % 3];
        const float* cB = sB[ch % 3];

        #pragma unroll
        for (int kk = 0; kk < 4; ++kk) {
            const int kb = kk * 8 + kq;
            uint32_t af[4][4];
            #pragma unroll
            for (int mt = 0; mt < 4; ++mt) {
                const float* p = cA + (arow + mt * 16) * LDAg + kb;
                af[mt][0] = __float_as_uint(p[0]);
                af[mt][1] = __float_as_uint(p[8 * LDAg]);
                af[mt][2] = __float_as_uint(p[4]);
                af[mt][3] = __float_as_uint(p[8 * LDAg + 4]);
            }
            uint32_t bf[4][2];
            #pragma unroll
            for (int nt = 0; nt < 4; ++nt) {
                const float* p = cB + (brow + nt * 8) * LDAg + kb;
                bf[nt][0] = __float_as_uint(p[0]);
                bf[nt][1] = __float_as_uint(p[4]);
            }
            #pragma unroll
            for (int mt = 0; mt < 4; ++mt)
                #pragma unroll
                for (int nt = 0; nt < 4; ++nt)
                    mma_tf32(c[mt][nt], af[mt], bf[nt]);
        }
    }

    // route output block to its matrix (10 column-blocks per 1280-wide matrix)
    const int mat = blockIdx.x / 10;
    float* C = (mat == 0) ? C0 : ((mat == 1) ? C1 : C2);
    const int ncol0 = (blockIdx.x - mat * 10) * BNg;   // column within matrix

    // epilogue: fragment -> global (float2 stores), + bias, optional tf32 round
    const int crow = m0 + wm * 64 + (lane >> 2);
    const int ccol = wn * 32 + 2 * (lane & 3);
    #pragma unroll
    for (int nt = 0; nt < 4; ++nt) {
        int col  = ccol + nt * 8;
        float b0 = bias[n0 + col];
        float b1 = bias[n0 + col + 1];
        int colg = ncol0 + col;
        #pragma unroll
        for (int mt = 0; mt < 4; ++mt) {
            int r0 = crow + mt * 16;
            if (r0 < M) {
                float v0 = c[mt][nt][0] + b0, v1 = c[mt][nt][1] + b1;
                if (round_out) { v0 = round_tf32(v0); v1 = round_tf32(v1); }
                *(float2*)(C + (size_t)r0 * D_MODEL + colg) = make_float2(v0, v1);
            }
            int r1 = r0 + 8;
            if (r1 < M) {
                float v0 = c[mt][nt][2] + b0, v1 = c[mt][nt][3] + b1;
                if (round_out) { v0 = round_tf32(v0); v1 = round_tf32(v1); }
                *(float2*)(C + (size_t)r1 * D_MODEL + colg) = make_float2(v0, v1);
            }
        }
    }
}

// ================ tensor-core flash attention (unchanged) ====================
#define FBQ 128
#define FBK 64
#define QLD 68
#define KLD 68
#define VLD 72
#define FA_SMEM_FLOATS (FBQ*QLD + 2*FBK*KLD + 2*FBK*VLD)
#define FA_SMEM_BYTES  (FA_SMEM_FLOATS * 4)

__device__ __forceinline__ void fa_load_kv(const float* __restrict__ K,
                                           const float* __restrict__ V,
                                           int base, int len, int h, int k0,
                                           float* Ks, float* Vs, int tid) {
    #pragma unroll
    for (int i = 0; i < 4; ++i) {
        int e   = tid + i * 256;     // 0..1023
        int row = e >> 4;            // 0..63
        int g   = e & 15;            // float4 group within 64 cols
        int kr  = k0 + row; if (kr >= len) kr = len - 1;
        size_t goff = (size_t)(base + kr) * D_MODEL + h * HEAD_DIM + g * 4;
        cp_async16(smem_u32(Ks + row * KLD + g * 4), K + goff);
        cp_async16(smem_u32(Vs + row * VLD + g * 4), V + goff);
    }
}

__global__ __launch_bounds__(256)
void flash_attn_mma(const float* __restrict__ Q, const float* __restrict__ K,
                    const float* __restrict__ V, const int* __restrict__ cu,
                    float* __restrict__ O) {
    extern __shared__ float sm[];
    float* Qs  = sm;                         // 128 x 68 (later: P staging)
    float* Ks0 = Qs  + FBQ * QLD;
    float* Ks1 = Ks0 + FBK * KLD;
    float* Vs0 = Ks1 + FBK * KLD;
    float* Vs1 = Vs0 + FBK * VLD;

    const int b  = blockIdx.z;
    const int h  = blockIdx.y;
    const int q0 = blockIdx.x * FBQ;

    const int base = cu[b];
    const int len  = cu[b + 1] - base;
    if (q0 >= len) return;

    const int tid  = threadIdx.x;
    const int wid  = tid >> 5;
    const int lane = tid & 31;
    const int qr   = lane >> 2;     // 0..7
    const int kq   = lane & 3;      // 0..3

    const int nk = (len + FBK - 1) / FBK;

    fa_load_kv(K, V, base, len, h, 0,   Ks0, Vs0, tid); CP_COMMIT();
    fa_load_kv(K, V, base, len, h, FBK, Ks1, Vs1, tid); CP_COMMIT();

    #pragma unroll
    for (int i = 0; i < 8; ++i) {
        int e   = tid + i * 256;     // 0..2047
        int row = e >> 4;            // 0..127
        int g   = e & 15;
        int qi  = q0 + row; if (qi >= len) qi = len - 1;
        float4 v = *(const float4*)(Q + (size_t)(base + qi) * D_MODEL + h * HEAD_DIM + g * 4);
        *(float4*)(Qs + row * QLD + g * 4) = v;
    }
    __syncthreads();

    uint32_t qf[8][4];
    {
        const float* qp = Qs + (wid * 16 + qr) * QLD + kq;
        #pragma unroll
        for (int ks = 0; ks < 8; ++ks) {
            const float* p = qp + ks * 8;
            qf[ks][0] = __float_as_uint(p[0]);
            qf[ks][1] = __float_as_uint(p[8 * QLD]);
            qf[ks][2] = __float_as_uint(p[4]);
            qf[ks][3] = __float_as_uint(p[8 * QLD + 4]);
        }
    }
    __syncthreads();    // all Q frags read; Qs may be reused as P

    float m0 = -3.0e38f, m1 = -3.0e38f, l0 = 0.f, l1 = 0.f;
    float o[8][4];
    #pragma unroll
    for (int dt = 0; dt < 8; ++dt)
        #pragma unroll
        for (int q = 0; q < 4; ++q) o[dt][q] = 0.f;

    float* Pw = Qs + wid * 16 * QLD;   // this warp's 16 x 68 P staging

    for (int kt = 0; kt < nk; ++kt) {
        const int s = kt & 1;
        const float* Ks = s ? Ks1 : Ks0;
        const float* Vs = s ? Vs1 : Vs0;
        if (kt + 1 < nk) { CP_WAIT1(); } else { CP_WAIT0(); }
        __syncthreads();

        float sc[8][4];
        #pragma unroll
        for (int nt = 0; nt < 8; ++nt)
            #pragma unroll
            for (int q = 0; q < 4; ++q) sc[nt][q] = 0.f;

        #pragma unroll
        for (int ks = 0; ks < 8; ++ks) {
            const int kb = ks * 8 + kq;
            #pragma unroll
            for (int nt = 0; nt < 8; ++nt) {
                uint32_t bf[2];
                const float* p = Ks + (nt * 8 + qr) * KLD + kb;
                bf[0] = __float_as_uint(p[0]);
                bf[1] = __float_as_uint(p[4]);
                mma_tf32(sc[nt], qf[ks], bf);
            }
        }

        const int kbase = kt * FBK;
        #pragma unroll
        for (int nt = 0; nt < 8; ++nt) {
            int c0 = kbase + nt * 8 + 2 * kq;
            bool ok0 = c0 < len, ok1 = (c0 + 1) < len;
            sc[nt][0] = ok0 ? sc[nt][0] * ATT_SCALE : NEG_BIG;
            sc[nt][1] = ok1 ? sc[nt][1] * ATT_SCALE : NEG_BIG;
            sc[nt][2] = ok0 ? sc[nt][2] * ATT_SCALE : NEG_BIG;
            sc[nt][3] = ok1 ? sc[nt][3] * ATT_SCALE : NEG_BIG;
        }

        float mx0 = -3.0e38f, mx1 = -3.0e38f;
        #pragma unroll
        for (int nt = 0; nt < 8; ++nt) {
            mx0 = fmaxf(mx0, fmaxf(sc[nt][0], sc[nt][1]));
            mx1 = fmaxf(mx1, fmaxf(sc[nt][2], sc[nt][3]));
        }
        mx0 = fmaxf(mx0, __shfl_xor_sync(0xffffffffu, mx0, 1));
        mx0 = fmaxf(mx0, __shfl_xor_sync(0xffffffffu, mx0, 2));
        mx1 = fmaxf(mx1, __shfl_xor_sync(0xffffffffu, mx1, 1));
        mx1 = fmaxf(mx1, __shfl_xor_sync(0xffffffffu, mx1, 2));

        float nm0 = fmaxf(m0, mx0), nm1 = fmaxf(m1, mx1);
        float a0 = __expf(m0 - nm0), a1 = __expf(m1 - nm1);
        float rs0 = 0.f, rs1 = 0.f;
        #pragma unroll
        for (int nt = 0; nt < 8; ++nt) {
            float p00 = __expf(sc[nt][0] - nm0);
            float p01 = __expf(sc[nt][1] - nm0);
            float p10 = __expf(sc[nt][2] - nm1);
            float p11 = __expf(sc[nt][3] - nm1);
            rs0 += p00 + p01;
            rs1 += p10 + p11;
            float* pp = Pw + qr * QLD + nt * 8 + 2 * kq;
            *(float2*)pp = make_float2(round_tf32(p00), round_tf32(p01));
            *(float2*)(pp + 8 * QLD) = make_float2(round_tf32(p10), round_tf32(p11));
        }
        rs0 += __shfl_xor_sync(0xffffffffu, rs0, 1);
        rs0 += __shfl_xor_sync(0xffffffffu, rs0, 2);
        rs1 += __shfl_xor_sync(0xffffffffu, rs1, 1);
        rs1 += __shfl_xor_sync(0xffffffffu, rs1, 2);

        l0 = l0 * a0 + rs0;  m0 = nm0;
        l1 = l1 * a1 + rs1;  m1 = nm1;
        #pragma unroll
        for (int dt = 0; dt < 8; ++dt) {
            o[dt][0] *= a0; o[dt][1] *= a0;
            o[dt][2] *= a1; o[dt][3] *= a1;
        }
        __syncwarp();

        #pragma unroll
        for (int ks = 0; ks < 8; ++ks) {
            uint32_t pf[4];
            const float* pp = Pw + qr * QLD + ks * 8 + kq;
            pf[0] = __float_as_uint(pp[0]);
            pf[1] = __float_as_uint(pp[8 * QLD]);
            pf[2] = __float_as_uint(pp[4]);
            pf[3] = __float_as_uint(pp[8 * QLD + 4]);
            const float* vrow = Vs + (ks * 8 + kq) * VLD + qr;
            #pragma unroll
            for (int dt = 0; dt < 8; ++dt) {
                uint32_t bf[2];
                bf[0] = __float_as_uint(vrow[dt * 8]);
                bf[1] = __float_as_uint(vrow[4 * VLD + dt * 8]);
                mma_tf32(o[dt], pf, bf);
            }
        }
        __syncthreads();   // done reading stage s (and P) before overwrite

        if (kt + 2 < nk) {
            fa_load_kv(K, V, base, len, h, (kt + 2) * FBK,
                       s ? Ks1 : Ks0, s ? Vs1 : Vs0, tid);
            CP_COMMIT();
        }
    }

    const int qr0 = q0 + wid * 16 + qr;
    const int qr1 = qr0 + 8;
    const float inv0 = 1.0f / l0, inv1 = 1.0f / l1;
    #pragma unroll
    for (int dt = 0; dt < 8; ++dt) {
        int col = h * HEAD_DIM + dt * 8 + 2 * kq;
        if (qr0 < len)
            *(float2*)(O + (size_t)(base + qr0) * D_MODEL + col) =
                make_float2(round_tf32(o[dt][0] * inv0), round_tf32(o[dt][1] * inv0));
        if (qr1 < len)
            *(float2*)(O + (size_t)(base + qr1) * D_MODEL + col) =
                make_float2(round_tf32(o[dt][2] * inv1), round_tf32(o[dt][3] * inv1));
    }
}

// ---------------- host launcher ----------------------------------------------
extern "C" void kernel_launch(void* const* d_in, const int* in_sizes, int n_in,
                              void* d_out, int out_size) {
    const float* hs = (const float*)d_in[0];
    const int*   cu = (const int*)d_in[1];
    const float* Wq = (const float*)d_in[2];
    const float* bq = (const float*)d_in[3];
    const float* Wk = (const float*)d_in[4];
    const float* Wv = (const float*)d_in[5];
    const float* bv = (const float*)d_in[6];
    const float* Wo = (const float*)d_in[7];
    const float* bo = (const float*)d_in[8];
    float* out = (float*)d_out;

    const int T    = in_sizes[0] / D_MODEL;   // 6000
    const int Bseg = in_sizes[1] - 1;         // 4

    float *pq, *pk, *pv, *pa, *phr, *pwr, *pbias;
    cudaGetSymbolAddress((void**)&pq,    g_q);
    cudaGetSymbolAddress((void**)&pk,    g_k);
    cudaGetSymbolAddress((void**)&pv,    g_v);
    cudaGetSymbolAddress((void**)&pa,    g_attn);
    cudaGetSymbolAddress((void**)&phr,   g_hs_r);
    cudaGetSymbolAddress((void**)&pwr,   g_w_r);
    cudaGetSymbolAddress((void**)&pbias, g_bias);
    float* pwo = pwr + 3 * D_MODEL * D_MODEL;

    cudaFuncSetAttribute(flash_attn_mma, cudaFuncAttributeMaxDynamicSharedMemorySize,
                         FA_SMEM_BYTES);
    cudaFuncSetAttribute(gemm_tf32mma, cudaFuncAttributeMaxDynamicSharedMemorySize,
                         GT_SMEM_BYTES);

    // fused prep: tf32-round hs + 4 weights, build combined qkv bias
    prep_kernel<<<(PREP_TOTAL + 255) / 256, 256>>>(
        (const float4*)hs, (const float4*)Wq, (const float4*)Wk,
        (const float4*)Wv, (const float4*)Wo, bq, bv,
        (float4*)phr, (float4*)pwr, pbias);

    // merged QKV projection: C[:, 0:3840] = hs_r @ [Wq|Wk|Wv]^T + [bq|0|bv]
    dim3 qkvgrid(3 * D_MODEL / BNg, (T + BMg - 1) / BMg);   // (30, 47)
    gemm_tf32mma<<<qkvgrid, 256, GT_SMEM_BYTES>>>(phr, pwr, pbias,
                                                  pq, pk, pv, T, 1);

    // attention (tensor-core tf32, fp32 accumulate; output tf32-rounded)
    dim3 fgrid((MAX_SEQLEN + FBQ - 1) / FBQ, NUM_HEADS, Bseg);
    flash_attn_mma<<<fgrid, 256, FA_SMEM_BYTES>>>(pq, pk, pv, cu, pa);

    // output projection (single matrix, grid.x=10 -> mat id always 0)
    dim3 ogrid(D_MODEL / BNg, (T + BMg - 1) / BMg);         // (10, 47)
    gemm_tf32mma<<<ogrid, 256, GT_SMEM_BYTES>>>(pa, pwo, bo,
                                                out, out, out, T, 0);
}

// round 10
// speedup vs baseline: 5.2162x; 1.2061x over previous
#include <cuda_runtime.h>
#include <cuda_bf16.h>
#include <cstdint>

// Problem constants (static shapes from setup_inputs)
#define D_MODEL 1280
#define NUM_HEADS 20
#define HEAD_DIM 64
#define MAX_SEQLEN 1500
#define MAX_T 6000           // 4 * 1500
#define ATT_SCALE 0.125f     // 64^-0.5
#define NEG_BIG -1e30f

// ---------------- scratch (static device globals; no runtime alloc) ----------
__device__ float g_q[MAX_T * D_MODEL];
__device__ float g_k[MAX_T * D_MODEL];
__device__ float g_v[MAX_T * D_MODEL];
__device__ float g_attn[MAX_T * D_MODEL];
__device__ float g_hs_r[MAX_T * D_MODEL];           // tf32-rounded hidden states
__device__ float g_w_r[4][D_MODEL * D_MODEL];       // tf32-rounded Wq,Wk,Wv,Wo (contiguous)
__device__ float g_bias[3 * D_MODEL];               // combined bq | 0 | bv

// ========================= PTX helpers ======================================
__device__ __forceinline__ uint32_t smem_u32(const void* p) {
    uint32_t a;
    asm("{ .reg .u64 t; cvta.to.shared.u64 t, %1; cvt.u32.u64 %0, t; }"
        : "=r"(a) : "l"(p));
    return a;
}

__device__ __forceinline__ void cp_async16(uint32_t dst, const void* src) {
    asm volatile("cp.async.cg.shared.global [%0], [%1], 16;"
                 :: "r"(dst), "l"(src));
}
#define CP_COMMIT() asm volatile("cp.async.commit_group;" ::: "memory")
#define CP_WAIT0()  asm volatile("cp.async.wait_group 0;" ::: "memory")
#define CP_WAIT1()  asm volatile("cp.async.wait_group 1;" ::: "memory")

__device__ __forceinline__ float round_tf32(float v) {
    uint32_t t;
    asm("cvt.rn.tf32.f32 %0, %1;" : "=r"(t) : "f"(v));
    return __uint_as_float(t);
}

// mma.sync m16n8k8 tf32: D[16,8] += A[16,8] @ B[8,8]  (A row-major, B col-major)
__device__ __forceinline__ void mma_tf32(float c[4], const uint32_t a[4],
                                         const uint32_t b[2]) {
    asm volatile(
        "mma.sync.aligned.m16n8k8.row.col.f32.tf32.tf32.f32 "
        "{%0,%1,%2,%3}, {%4,%5,%6,%7}, {%8,%9}, {%0,%1,%2,%3};"
        : "+f"(c[0]), "+f"(c[1]), "+f"(c[2]), "+f"(c[3])
        : "r"(a[0]), "r"(a[1]), "r"(a[2]), "r"(a[3]), "r"(b[0]), "r"(b[1]));
}

// ldmatrix: tf32 fragments via b16 tiles (pure bit movement).
// x4: 16x8 tf32 A-tile (4 b16 8x8 tiles) -> a0..a3 in mma order.
__device__ __forceinline__ void ldsm_x4(uint32_t r[4], uint32_t addr) {
    asm volatile("ldmatrix.sync.aligned.m8n8.x4.shared.b16 {%0,%1,%2,%3}, [%4];"
                 : "=r"(r[0]), "=r"(r[1]), "=r"(r[2]), "=r"(r[3]) : "r"(addr));
}
// x2: 8x8 tf32 B-tile pair (k, k+4) -> b0,b1 in mma order.
__device__ __forceinline__ void ldsm_x2(uint32_t r[2], uint32_t addr) {
    asm volatile("ldmatrix.sync.aligned.m8n8.x2.shared.b16 {%0,%1}, [%2];"
                 : "=r"(r[0]), "=r"(r[1]) : "r"(addr));
}

// ================= fused prep kernel: tf32 rounding + bias build =============
#define H4  (MAX_T * D_MODEL / 4)            // float4 of hidden states
#define W4  (D_MODEL * D_MODEL / 4)          // float4 per weight
#define B4  (3 * D_MODEL / 4)
#define PREP_TOTAL (H4 + 4 * W4 + B4)

__global__ __launch_bounds__(256)
void prep_kernel(const float4* __restrict__ hs,
                 const float4* __restrict__ wq, const float4* __restrict__ wk,
                 const float4* __restrict__ wv, const float4* __restrict__ wo,
                 const float* __restrict__ bq, const float* __restrict__ bv,
                 float4* __restrict__ hs_r, float4* __restrict__ w_r,
                 float* __restrict__ bias) {
    int i = blockIdx.x * blockDim.x + threadIdx.x;
    if (i < H4) {
        float4 v = hs[i];
        v.x = round_tf32(v.x); v.y = round_tf32(v.y);
        v.z = round_tf32(v.z); v.w = round_tf32(v.w);
        hs_r[i] = v;
    } else if (i < H4 + 4 * W4) {
        int j = i - H4;
        const float4* src = (j < W4) ? wq : (j < 2 * W4) ? wk : (j < 3 * W4) ? wv : wo;
        float4 v = src[j - (j / W4) * W4];
        v.x = round_tf32(v.x); v.y = round_tf32(v.y);
        v.z = round_tf32(v.z); v.w = round_tf32(v.w);
        w_r[j] = v;
    } else if (i < PREP_TOTAL) {
        int j = (i - H4 - 4 * W4) * 4;
        #pragma unroll
        for (int e = 0; e < 4; ++e) {
            int idx = j + e;
            float v = 0.f;
            if (idx < D_MODEL) v = bq[idx];
            else if (idx >= 2 * D_MODEL) v = bv[idx - 2 * D_MODEL];
            bias[idx] = v;
        }
    }
}

// ============ tf32 mma.sync GEMM: C[M, n_mats*1280] = A @ B^T + bias =========
// CTA tile 128x128, BK=32, 8 warps (2 M x 4 N), warp tile 64x32.
// 3-stage cp.async pipeline, one barrier per chunk, 2 CTAs/SM, ldmatrix frags.
#define BMg 128
#define BNg 128
#define BKg 32
#define LDAg 36                                      // 32 + 4 pad; 144B rows (16B-aligned, 9 units -> LDSM conflict-free)
#define ASTG (BMg * LDAg)
#define BSTG (BNg * LDAg)
#define STAGE_FLOATS (ASTG + BSTG)                   // 36 KB
#define GT_SMEM_BYTES (3 * STAGE_FLOATS * 4)         // 110.6 KB -> 2 CTAs/SM

__device__ __forceinline__ void gt_load(const float* __restrict__ A,
                                        const float* __restrict__ B,
                                        int M, int m0, int n0, int k0,
                                        float* sA, float* sB, int tid) {
    #pragma unroll
    for (int i = 0; i < 4; ++i) {
        int e   = tid + i * 256;
        int row = e >> 3;             // 0..127
        int g   = e & 7;              // float4 group within 32 k-cols
        int ar  = m0 + row; if (ar >= M) ar = M - 1;   // clamp; masked at store
        cp_async16(smem_u32(sA + row * LDAg + g * 4),
                   A + (size_t)ar * D_MODEL + k0 + g * 4);
        cp_async16(smem_u32(sB + row * LDAg + g * 4),
                   B + (size_t)(n0 + row) * D_MODEL + k0 + g * 4);
    }
}

__global__ __launch_bounds__(256, 2)
void gemm_tf32mma(const float* __restrict__ A, const float* __restrict__ B,
                  const float* __restrict__ bias,
                  float* __restrict__ C0, float* __restrict__ C1,
                  float* __restrict__ C2, int M, int round_out) {
    extern __shared__ float sm[];
    float* sA[3] = { sm, sm + STAGE_FLOATS, sm + 2 * STAGE_FLOATS };
    float* sB[3] = { sm + ASTG, sm + STAGE_FLOATS + ASTG, sm + 2 * STAGE_FLOATS + ASTG };

    const int tid  = threadIdx.x;
    const int wid  = tid >> 5;
    const int lane = tid & 31;
    const int wm   = wid & 1;          // warp row (0..1) -> 64 rows each
    const int wn   = wid >> 1;         // warp col (0..3) -> 32 cols each
    const int m0   = blockIdx.y * BMg;
    const int n0   = blockIdx.x * BNg;

    // ldmatrix per-thread address components (in floats)
    const int lane8 = lane & 7;
    const int aRow  = wm * 64 + ((lane >> 3) & 1) * 8 + lane8;   // + mt*16
    const int aCol  = ((lane >> 4) & 1) * 4;                      // + kk*8
    const int bRow  = wn * 32 + lane8;                            // + nt*8
    const int bCol  = ((lane >> 3) & 1) * 4;                      // + kk*8 (lanes<16 used)

    float c[4][4][4];                  // [mt][nt][frag] -> 64 accumulator regs
    #pragma unroll
    for (int mt = 0; mt < 4; ++mt)
        #pragma unroll
        for (int nt = 0; nt < 4; ++nt)
            #pragma unroll
            for (int q = 0; q < 4; ++q) c[mt][nt][q] = 0.f;

    const int NCH = D_MODEL / BKg;     // 40
    gt_load(A, B, M, m0, n0, 0,   sA[0], sB[0], tid); CP_COMMIT();
    gt_load(A, B, M, m0, n0, BKg, sA[1], sB[1], tid); CP_COMMIT();

    for (int ch = 0; ch < NCH; ++ch) {
        if (ch == NCH - 1) { CP_WAIT0(); } else { CP_WAIT1(); }
        __syncthreads();               // one barrier per chunk
        if (ch + 2 < NCH) {
            gt_load(A, B, M, m0, n0, (ch + 2) * BKg,
                    sA[(ch + 2) % 3], sB[(ch + 2) % 3], tid);
            CP_COMMIT();
        }
        const uint32_t aBase = smem_u32(sA[ch % 3]) + (uint32_t)(aRow * LDAg + aCol) * 4u;
        const uint32_t bBase = smem_u32(sB[ch % 3]) + (uint32_t)(bRow * LDAg + bCol) * 4u;

        #pragma unroll
        for (int kk = 0; kk < 4; ++kk) {
            uint32_t af[4][4];
            #pragma unroll
            for (int mt = 0; mt < 4; ++mt)
                ldsm_x4(af[mt], aBase + (uint32_t)(mt * 16 * LDAg + kk * 8) * 4u);
            uint32_t bf[4][2];
            #pragma unroll
            for (int nt = 0; nt < 4; ++nt)
                ldsm_x2(bf[nt], bBase + (uint32_t)(nt * 8 * LDAg + kk * 8) * 4u);
            #pragma unroll
            for (int mt = 0; mt < 4; ++mt)
                #pragma unroll
                for (int nt = 0; nt < 4; ++nt)
                    mma_tf32(c[mt][nt], af[mt], bf[nt]);
        }
    }

    // route output block to its matrix (10 column-blocks per 1280-wide matrix)
    const int mat = blockIdx.x / 10;
    float* C = (mat == 0) ? C0 : ((mat == 1) ? C1 : C2);
    const int ncol0 = (blockIdx.x - mat * 10) * BNg;

    // epilogue: fragment -> global (float2 stores), + bias, optional tf32 round
    const int crow = m0 + wm * 64 + (lane >> 2);
    const int ccol = wn * 32 + 2 * (lane & 3);
    #pragma unroll
    for (int nt = 0; nt < 4; ++nt) {
        int col  = ccol + nt * 8;
        float b0 = bias[n0 + col];
        float b1 = bias[n0 + col + 1];
        int colg = ncol0 + col;
        #pragma unroll
        for (int mt = 0; mt < 4; ++mt) {
            int r0 = crow + mt * 16;
            if (r0 < M) {
                float v0 = c[mt][nt][0] + b0, v1 = c[mt][nt][1] + b1;
                if (round_out) { v0 = round_tf32(v0); v1 = round_tf32(v1); }
                *(float2*)(C + (size_t)r0 * D_MODEL + colg) = make_float2(v0, v1);
            }
            int r1 = r0 + 8;
            if (r1 < M) {
                float v0 = c[mt][nt][2] + b0, v1 = c[mt][nt][3] + b1;
                if (round_out) { v0 = round_tf32(v0); v1 = round_tf32(v1); }
                *(float2*)(C + (size_t)r1 * D_MODEL + colg) = make_float2(v0, v1);
            }
        }
    }
}

// ================ tensor-core flash attention (ldmatrix K/P frags) ==========
#define FBQ 128
#define FBK 64
#define QLD 68
#define KLD 68
#define VLD 72
#define FA_SMEM_FLOATS (FBQ*QLD + 2*FBK*KLD + 2*FBK*VLD)
#define FA_SMEM_BYTES  (FA_SMEM_FLOATS * 4)

__device__ __forceinline__ void fa_load_kv(const float* __restrict__ K,
                                           const float* __restrict__ V,
                                           int base, int len, int h, int k0,
                                           float* Ks, float* Vs, int tid) {
    #pragma unroll
    for (int i = 0; i < 4; ++i) {
        int e   = tid + i * 256;     // 0..1023
        int row = e >> 4;            // 0..63
        int g   = e & 15;            // float4 group within 64 cols
        int kr  = k0 + row; if (kr >= len) kr = len - 1;
        size_t goff = (size_t)(base + kr) * D_MODEL + h * HEAD_DIM + g * 4;
        cp_async16(smem_u32(Ks + row * KLD + g * 4), K + goff);
        cp_async16(smem_u32(Vs + row * VLD + g * 4), V + goff);
    }
}

__global__ __launch_bounds__(256)
void flash_attn_mma(const float* __restrict__ Q, const float* __restrict__ K,
                    const float* __restrict__ V, const int* __restrict__ cu,
                    float* __restrict__ O) {
    extern __shared__ float sm[];
    float* Qs  = sm;                         // 128 x 68 (later: P staging)
    float* Ks0 = Qs  + FBQ * QLD;
    float* Ks1 = Ks0 + FBK * KLD;
    float* Vs0 = Ks1 + FBK * KLD;
    float* Vs1 = Vs0 + FBK * VLD;

    const int b  = blockIdx.z;
    const int h  = blockIdx.y;
    const int q0 = blockIdx.x * FBQ;

    const int base = cu[b];
    const int len  = cu[b + 1] - base;
    if (q0 >= len) return;

    const int tid  = threadIdx.x;
    const int wid  = tid >> 5;
    const int lane = tid & 31;
    const int qr   = lane >> 2;     // 0..7
    const int kq   = lane & 3;      // 0..3
    const int lane8 = lane & 7;

    // ldmatrix address components
    const int kRow = lane8;                         // + nt*8 (key index)
    const int kCol = ((lane >> 3) & 1) * 4;         // + ks*8
    const int pRow = ((lane >> 3) & 1) * 8 + lane8; // local P row (0..15)
    const int pCol = ((lane >> 4) & 1) * 4;         // + ks*8

    const int nk = (len + FBK - 1) / FBK;

    fa_load_kv(K, V, base, len, h, 0,   Ks0, Vs0, tid); CP_COMMIT();
    fa_load_kv(K, V, base, len, h, FBK, Ks1, Vs1, tid); CP_COMMIT();

    #pragma unroll
    for (int i = 0; i < 8; ++i) {
        int e   = tid + i * 256;     // 0..2047
        int row = e >> 4;            // 0..127
        int g   = e & 15;
        int qi  = q0 + row; if (qi >= len) qi = len - 1;
        float4 v = *(const float4*)(Q + (size_t)(base + qi) * D_MODEL + h * HEAD_DIM + g * 4);
        *(float4*)(Qs + row * QLD + g * 4) = v;
    }
    __syncthreads();

    // Q fragments via ldmatrix (warp rows [wid*16, wid*16+16))
    uint32_t qf[8][4];
    {
        uint32_t qBase = smem_u32(Qs) + (uint32_t)((wid * 16 + pRow) * QLD + pCol) * 4u;
        #pragma unroll
        for (int ks = 0; ks < 8; ++ks)
            ldsm_x4(qf[ks], qBase + (uint32_t)(ks * 8) * 4u);
    }
    __syncthreads();    // all Q frags read; Qs may be reused as P

    float m0 = -3.0e38f, m1 = -3.0e38f, l0 = 0.f, l1 = 0.f;
    float o[8][4];
    #pragma unroll
    for (int dt = 0; dt < 8; ++dt)
        #pragma unroll
        for (int q = 0; q < 4; ++q) o[dt][q] = 0.f;

    float* Pw = Qs + wid * 16 * QLD;   // this warp's 16 x 68 P staging
    const uint32_t pBase = smem_u32(Pw) + (uint32_t)(pRow * QLD + pCol) * 4u;

    for (int kt = 0; kt < nk; ++kt) {
        const int s = kt & 1;
        const float* Ks = s ? Ks1 : Ks0;
        const float* Vs = s ? Vs1 : Vs0;
        if (kt + 1 < nk) { CP_WAIT1(); } else { CP_WAIT0(); }
        __syncthreads();

        float sc[8][4];
        #pragma unroll
        for (int nt = 0; nt < 8; ++nt)
            #pragma unroll
            for (int q = 0; q < 4; ++q) sc[nt][q] = 0.f;

        const uint32_t kBase = smem_u32(Ks) + (uint32_t)(kRow * KLD + kCol) * 4u;
        #pragma unroll
        for (int ks = 0; ks < 8; ++ks) {
            #pragma unroll
            for (int nt = 0; nt < 8; ++nt) {
                uint32_t bf[2];
                ldsm_x2(bf, kBase + (uint32_t)(nt * 8 * KLD + ks * 8) * 4u);
                mma_tf32(sc[nt], qf[ks], bf);
            }
        }

        const int kbase = kt * FBK;
        #pragma unroll
        for (int nt = 0; nt < 8; ++nt) {
            int c0 = kbase + nt * 8 + 2 * kq;
            bool ok0 = c0 < len, ok1 = (c0 + 1) < len;
            sc[nt][0] = ok0 ? sc[nt][0] * ATT_SCALE : NEG_BIG;
            sc[nt][1] = ok1 ? sc[nt][1] * ATT_SCALE : NEG_BIG;
            sc[nt][2] = ok0 ? sc[nt][2] * ATT_SCALE : NEG_BIG;
            sc[nt][3] = ok1 ? sc[nt][3] * ATT_SCALE : NEG_BIG;
        }

        float mx0 = -3.0e38f, mx1 = -3.0e38f;
        #pragma unroll
        for (int nt = 0; nt < 8; ++nt) {
            mx0 = fmaxf(mx0, fmaxf(sc[nt][0], sc[nt][1]));
            mx1 = fmaxf(mx1, fmaxf(sc[nt][2], sc[nt][3]));
        }
        mx0 = fmaxf(mx0, __shfl_xor_sync(0xffffffffu, mx0, 1));
        mx0 = fmaxf(mx0, __shfl_xor_sync(0xffffffffu, mx0, 2));
        mx1 = fmaxf(mx1, __shfl_xor_sync(0xffffffffu, mx1, 1));
        mx1 = fmaxf(mx1, __shfl_xor_sync(0xffffffffu, mx1, 2));

        float nm0 = fmaxf(m0, mx0), nm1 = fmaxf(m1, mx1);
        float a0 = __expf(m0 - nm0), a1 = __expf(m1 - nm1);
        float rs0 = 0.f, rs1 = 0.f;
        #pragma unroll
        for (int nt = 0; nt < 8; ++nt) {
            float p00 = __expf(sc[nt][0] - nm0);
            float p01 = __expf(sc[nt][1] - nm0);
            float p10 = __expf(sc[nt][2] - nm1);
            float p11 = __expf(sc[nt][3] - nm1);
            rs0 += p00 + p01;
            rs1 += p10 + p11;
            float* pp = Pw + qr * QLD + nt * 8 + 2 * kq;
            *(float2*)pp = make_float2(round_tf32(p00), round_tf32(p01));
            *(float2*)(pp + 8 * QLD) = make_float2(round_tf32(p10), round_tf32(p11));
        }
        rs0 += __shfl_xor_sync(0xffffffffu, rs0, 1);
        rs0 += __shfl_xor_sync(0xffffffffu, rs0, 2);
        rs1 += __shfl_xor_sync(0xffffffffu, rs1, 1);
        rs1 += __shfl_xor_sync(0xffffffffu, rs1, 2);

        l0 = l0 * a0 + rs0;  m0 = nm0;
        l1 = l1 * a1 + rs1;  m1 = nm1;
        #pragma unroll
        for (int dt = 0; dt < 8; ++dt) {
            o[dt][0] *= a0; o[dt][1] *= a0;
            o[dt][2] *= a1; o[dt][3] *= a1;
        }
        __syncwarp();

        #pragma unroll
        for (int ks = 0; ks < 8; ++ks) {
            uint32_t pf[4];
            ldsm_x4(pf, pBase + (uint32_t)(ks * 8) * 4u);
            const float* vrow = Vs + (ks * 8 + kq) * VLD + qr;
            #pragma unroll
            for (int dt = 0; dt < 8; ++dt) {
                uint32_t bf[2];
                bf[0] = __float_as_uint(vrow[dt * 8]);
                bf[1] = __float_as_uint(vrow[4 * VLD + dt * 8]);
                mma_tf32(o[dt], pf, bf);
            }
        }
        __syncthreads();   // done reading stage s (and P) before overwrite

        if (kt + 2 < nk) {
            fa_load_kv(K, V, base, len, h, (kt + 2) * FBK,
                       s ? Ks1 : Ks0, s ? Vs1 : Vs0, tid);
            CP_COMMIT();
        }
    }

    const int qr0 = q0 + wid * 16 + qr;
    const int qr1 = qr0 + 8;
    const float inv0 = 1.0f / l0, inv1 = 1.0f / l1;
    #pragma unroll
    for (int dt = 0; dt < 8; ++dt) {
        int col = h * HEAD_DIM + dt * 8 + 2 * kq;
        if (qr0 < len)
            *(float2*)(O + (size_t)(base + qr0) * D_MODEL + col) =
                make_float2(round_tf32(o[dt][0] * inv0), round_tf32(o[dt][1] * inv0));
        if (qr1 < len)
            *(float2*)(O + (size_t)(base + qr1) * D_MODEL + col) =
                make_float2(round_tf32(o[dt][2] * inv1), round_tf32(o[dt][3] * inv1));
    }
}

// ---------------- host launcher ----------------------------------------------
extern "C" void kernel_launch(void* const* d_in, const int* in_sizes, int n_in,
                              void* d_out, int out_size) {
    const float* hs = (const float*)d_in[0];
    const int*   cu = (const int*)d_in[1];
    const float* Wq = (const float*)d_in[2];
    const float* bq = (const float*)d_in[3];
    const float* Wk = (const float*)d_in[4];
    const float* Wv = (const float*)d_in[5];
    const float* bv = (const float*)d_in[6];
    const float* Wo = (const float*)d_in[7];
    const float* bo = (const float*)d_in[8];
    float* out = (float*)d_out;

    const int T    = in_sizes[0] / D_MODEL;   // 6000
    const int Bseg = in_sizes[1] - 1;         // 4

    float *pq, *pk, *pv, *pa, *phr, *pwr, *pbias;
    cudaGetSymbolAddress((void**)&pq,    g_q);
    cudaGetSymbolAddress((void**)&pk,    g_k);
    cudaGetSymbolAddress((void**)&pv,    g_v);
    cudaGetSymbolAddress((void**)&pa,    g_attn);
    cudaGetSymbolAddress((void**)&phr,   g_hs_r);
    cudaGetSymbolAddress((void**)&pwr,   g_w_r);
    cudaGetSymbolAddress((void**)&pbias, g_bias);
    float* pwo = pwr + 3 * D_MODEL * D_MODEL;

    cudaFuncSetAttribute(flash_attn_mma, cudaFuncAttributeMaxDynamicSharedMemorySize,
                         FA_SMEM_BYTES);
    cudaFuncSetAttribute(gemm_tf32mma, cudaFuncAttributeMaxDynamicSharedMemorySize,
                         GT_SMEM_BYTES);

    // fused prep: tf32-round hs + 4 weights, build combined qkv bias
    prep_kernel<<<(PREP_TOTAL + 255) / 256, 256>>>(
        (const float4*)hs, (const float4*)Wq, (const float4*)Wk,
        (const float4*)Wv, (const float4*)Wo, bq, bv,
        (float4*)phr, (float4*)pwr, pbias);

    // merged QKV projection: C[:, 0:3840] = hs_r @ [Wq|Wk|Wv]^T + [bq|0|bv]
    dim3 qkvgrid(3 * D_MODEL / BNg, (T + BMg - 1) / BMg);   // (30, 47)
    gemm_tf32mma<<<qkvgrid, 256, GT_SMEM_BYTES>>>(phr, pwr, pbias,
                                                  pq, pk, pv, T, 1);

    // attention (tensor-core tf32, fp32 accumulate; output tf32-rounded)
    dim3 fgrid((MAX_SEQLEN + FBQ - 1) / FBQ, NUM_HEADS, Bseg);
    flash_attn_mma<<<fgrid, 256, FA_SMEM_BYTES>>>(pq, pk, pv, cu, pa);

    // output projection (single matrix, grid.x=10 -> mat id always 0)
    dim3 ogrid(D_MODEL / BNg, (T + BMg - 1) / BMg);         // (10, 47)
    gemm_tf32mma<<<ogrid, 256, GT_SMEM_BYTES>>>(pa, pwo, bo,
                                                out, out, out, T, 0);
}

// round 11
// speedup vs baseline: 5.5288x; 1.0599x over previous
#include <cuda_runtime.h>
#include <cuda_bf16.h>
#include <cstdint>

// Problem constants (static shapes from setup_inputs)
#define D_MODEL 1280
#define NUM_HEADS 20
#define HEAD_DIM 64
#define MAX_SEQLEN 1500
#define MAX_T 6000           // 4 * 1500
#define ATT_SCALE 0.125f     // 64^-0.5
#define NEG_BIG -1e30f

// ---------------- scratch (static device globals; no runtime alloc) ----------
__device__ float g_q[MAX_T * D_MODEL];
__device__ float g_k[MAX_T * D_MODEL];
__device__ float g_v[MAX_T * D_MODEL];
__device__ float g_attn[MAX_T * D_MODEL];
__device__ float g_hs_r[MAX_T * D_MODEL];           // tf32-rounded hidden states
__device__ float g_w_r[4][D_MODEL * D_MODEL];       // tf32-rounded Wq,Wk,Wv,Wo (contiguous)
__device__ float g_bias[3 * D_MODEL];               // combined bq | 0 | bv

// ========================= PTX helpers ======================================
__device__ __forceinline__ uint32_t smem_u32(const void* p) {
    uint32_t a;
    asm("{ .reg .u64 t; cvta.to.shared.u64 t, %1; cvt.u32.u64 %0, t; }"
        : "=r"(a) : "l"(p));
    return a;
}

__device__ __forceinline__ void cp_async16(uint32_t dst, const void* src) {
    asm volatile("cp.async.cg.shared.global [%0], [%1], 16;"
                 :: "r"(dst), "l"(src));
}
#define CP_COMMIT() asm volatile("cp.async.commit_group;" ::: "memory")
#define CP_WAIT0()  asm volatile("cp.async.wait_group 0;" ::: "memory")
#define CP_WAIT1()  asm volatile("cp.async.wait_group 1;" ::: "memory")

__device__ __forceinline__ float round_tf32(float v) {
    uint32_t t;
    asm("cvt.rn.tf32.f32 %0, %1;" : "=r"(t) : "f"(v));
    return __uint_as_float(t);
}

// mma.sync m16n8k8 tf32: D[16,8] += A[16,8] @ B[8,8]  (A row-major, B col-major)
__device__ __forceinline__ void mma_tf32(float c[4], const uint32_t a[4],
                                         const uint32_t b[2]) {
    asm volatile(
        "mma.sync.aligned.m16n8k8.row.col.f32.tf32.tf32.f32 "
        "{%0,%1,%2,%3}, {%4,%5,%6,%7}, {%8,%9}, {%0,%1,%2,%3};"
        : "+f"(c[0]), "+f"(c[1]), "+f"(c[2]), "+f"(c[3])
        : "r"(a[0]), "r"(a[1]), "r"(a[2]), "r"(a[3]), "r"(b[0]), "r"(b[1]));
}

// ldmatrix: tf32 fragments via b16 tiles (pure bit movement).
__device__ __forceinline__ void ldsm_x4(uint32_t r[4], uint32_t addr) {
    asm volatile("ldmatrix.sync.aligned.m8n8.x4.shared.b16 {%0,%1,%2,%3}, [%4];"
                 : "=r"(r[0]), "=r"(r[1]), "=r"(r[2]), "=r"(r[3]) : "r"(addr));
}
__device__ __forceinline__ void ldsm_x2(uint32_t r[2], uint32_t addr) {
    asm volatile("ldmatrix.sync.aligned.m8n8.x2.shared.b16 {%0,%1}, [%2];"
                 : "=r"(r[0]), "=r"(r[1]) : "r"(addr));
}

// ================= fused prep kernel: tf32 rounding + bias build =============
#define H4  (MAX_T * D_MODEL / 4)
#define W4  (D_MODEL * D_MODEL / 4)
#define B4  (3 * D_MODEL / 4)
#define PREP_TOTAL (H4 + 4 * W4 + B4)

__global__ __launch_bounds__(256)
void prep_kernel(const float4* __restrict__ hs,
                 const float4* __restrict__ wq, const float4* __restrict__ wk,
                 const float4* __restrict__ wv, const float4* __restrict__ wo,
                 const float* __restrict__ bq, const float* __restrict__ bv,
                 float4* __restrict__ hs_r, float4* __restrict__ w_r,
                 float* __restrict__ bias) {
    int i = blockIdx.x * blockDim.x + threadIdx.x;
    if (i < H4) {
        float4 v = hs[i];
        v.x = round_tf32(v.x); v.y = round_tf32(v.y);
        v.z = round_tf32(v.z); v.w = round_tf32(v.w);
        hs_r[i] = v;
    } else if (i < H4 + 4 * W4) {
        int j = i - H4;
        const float4* src = (j < W4) ? wq : (j < 2 * W4) ? wk : (j < 3 * W4) ? wv : wo;
        float4 v = src[j - (j / W4) * W4];
        v.x = round_tf32(v.x); v.y = round_tf32(v.y);
        v.z = round_tf32(v.z); v.w = round_tf32(v.w);
        w_r[j] = v;
    } else if (i < PREP_TOTAL) {
        int j = (i - H4 - 4 * W4) * 4;
        #pragma unroll
        for (int e = 0; e < 4; ++e) {
            int idx = j + e;
            float v = 0.f;
            if (idx < D_MODEL) v = bq[idx];
            else if (idx >= 2 * D_MODEL) v = bv[idx - 2 * D_MODEL];
            bias[idx] = v;
        }
    }
}

// ============ tf32 mma.sync GEMM: C[M, n_mats*1280] = A @ B^T + bias =========
// CTA tile 128x128, BK=32, 4 warps (2x2), warp tile 64x64.
// 3-stage cp.async pipeline, one barrier per chunk, 2 CTAs/SM, ldmatrix frags.
// dup_A = dup_B = 2 -> minimal crossbar traffic per MAC.
#define BMg 128
#define BNg 128
#define BKg 32
#define GTHREADS 128
#define LDAg 36                                      // 32 + 4 pad
#define ASTG (BMg * LDAg)
#define BSTG (BNg * LDAg)
#define STAGE_FLOATS (ASTG + BSTG)                   // 36 KB
#define GT_SMEM_BYTES (3 * STAGE_FLOATS * 4)         // 110.6 KB -> 2 CTAs/SM

__device__ __forceinline__ void gt_load(const float* __restrict__ A,
                                        const float* __restrict__ B,
                                        int M, int m0, int n0, int k0,
                                        float* sA, float* sB, int tid) {
    #pragma unroll
    for (int i = 0; i < 8; ++i) {
        int e   = tid + i * GTHREADS;  // 0..1023
        int row = e >> 3;              // 0..127
        int g   = e & 7;
        int ar  = m0 + row; if (ar >= M) ar = M - 1;   // clamp; masked at store
        cp_async16(smem_u32(sA + row * LDAg + g * 4),
                   A + (size_t)ar * D_MODEL + k0 + g * 4);
        cp_async16(smem_u32(sB + row * LDAg + g * 4),
                   B + (size_t)(n0 + row) * D_MODEL + k0 + g * 4);
    }
}

__global__ __launch_bounds__(GTHREADS, 2)
void gemm_tf32mma(const float* __restrict__ A, const float* __restrict__ B,
                  const float* __restrict__ bias,
                  float* __restrict__ C0, float* __restrict__ C1,
                  float* __restrict__ C2, int M, int round_out) {
    extern __shared__ float sm[];
    float* sA[3] = { sm, sm + STAGE_FLOATS, sm + 2 * STAGE_FLOATS };
    float* sB[3] = { sm + ASTG, sm + STAGE_FLOATS + ASTG, sm + 2 * STAGE_FLOATS + ASTG };

    const int tid  = threadIdx.x;
    const int wid  = tid >> 5;
    const int lane = tid & 31;
    const int wm   = wid & 1;          // warp row (0..1) -> 64 rows each
    const int wn   = wid >> 1;         // warp col (0..1) -> 64 cols each
    const int m0   = blockIdx.y * BMg;
    const int n0   = blockIdx.x * BNg;

    const int lane8 = lane & 7;
    // A x4: tiles (m..m+7,k0..3),(m+8..15,k0..3),(m..m+7,k4..7),(m+8..15,k4..7)?
    //   lanes 0-7 t0 rows, 8-15 t1 rows(+8), 16-23 t2 (col+4), 24-31 t3 (+8,col+4)
    const int aRow  = wm * 64 + ((lane >> 3) & 1) * 8 + lane8;   // + mt*16
    const int aCol  = ((lane >> 4) & 1) * 4;                      // + kk*8
    // B x4 pair: t0=(n..n+7,k),t1=(n..n+7,k+4),t2=(n+8..15,k),t3=(n+8..15,k+4)
    const int bRow  = wn * 64 + ((lane >> 4) & 1) * 8 + lane8;   // + nt2*16
    const int bCol  = ((lane >> 3) & 1) * 4;                      // + kk*8

    float c[4][8][4];                  // [mt][nt][frag] -> 128 accum regs
    #pragma unroll
    for (int mt = 0; mt < 4; ++mt)
        #pragma unroll
        for (int nt = 0; nt < 8; ++nt)
            #pragma unroll
            for (int q = 0; q < 4; ++q) c[mt][nt][q] = 0.f;

    const int NCH = D_MODEL / BKg;     // 40
    gt_load(A, B, M, m0, n0, 0,   sA[0], sB[0], tid); CP_COMMIT();
    gt_load(A, B, M, m0, n0, BKg, sA[1], sB[1], tid); CP_COMMIT();

    for (int ch = 0; ch < NCH; ++ch) {
        if (ch == NCH - 1) { CP_WAIT0(); } else { CP_WAIT1(); }
        __syncthreads();
        if (ch + 2 < NCH) {
            gt_load(A, B, M, m0, n0, (ch + 2) * BKg,
                    sA[(ch + 2) % 3], sB[(ch + 2) % 3], tid);
            CP_COMMIT();
        }
        const uint32_t aBase = smem_u32(sA[ch % 3]) + (uint32_t)(aRow * LDAg + aCol) * 4u;
        const uint32_t bBase = smem_u32(sB[ch % 3]) + (uint32_t)(bRow * LDAg + bCol) * 4u;

        #pragma unroll
        for (int kk = 0; kk < 4; ++kk) {
            uint32_t af[4][4];
            #pragma unroll
            for (int mt = 0; mt < 4; ++mt)
                ldsm_x4(af[mt], aBase + (uint32_t)(mt * 16 * LDAg + kk * 8) * 4u);
            uint32_t bf[4][4];     // [nt2] -> frags for nt=2*nt2, 2*nt2+1
            #pragma unroll
            for (int nt2 = 0; nt2 < 4; ++nt2)
                ldsm_x4(bf[nt2], bBase + (uint32_t)(nt2 * 16 * LDAg + kk * 8) * 4u);
            #pragma unroll
            for (int mt = 0; mt < 4; ++mt)
                #pragma unroll
                for (int nt2 = 0; nt2 < 4; ++nt2) {
                    mma_tf32(c[mt][2 * nt2],     af[mt], &bf[nt2][0]);
                    mma_tf32(c[mt][2 * nt2 + 1], af[mt], &bf[nt2][2]);
                }
        }
    }

    // route output block to its matrix (10 column-blocks per 1280-wide matrix)
    const int mat = blockIdx.x / 10;
    float* C = (mat == 0) ? C0 : ((mat == 1) ? C1 : C2);
    const int ncol0 = (blockIdx.x - mat * 10) * BNg;

    // epilogue: fragment -> global (float2 stores), + bias, optional tf32 round
    const int crow = m0 + wm * 64 + (lane >> 2);
    const int ccol = wn * 64 + 2 * (lane & 3);
    #pragma unroll
    for (int nt = 0; nt < 8; ++nt) {
        int col  = ccol + nt * 8;
        float b0 = bias[n0 + col];
        float b1 = bias[n0 + col + 1];
        int colg = ncol0 + col;
        #pragma unroll
        for (int mt = 0; mt < 4; ++mt) {
            int r0 = crow + mt * 16;
            if (r0 < M) {
                float v0 = c[mt][nt][0] + b0, v1 = c[mt][nt][1] + b1;
                if (round_out) { v0 = round_tf32(v0); v1 = round_tf32(v1); }
                *(float2*)(C + (size_t)r0 * D_MODEL + colg) = make_float2(v0, v1);
            }
            int r1 = r0 + 8;
            if (r1 < M) {
                float v0 = c[mt][nt][2] + b0, v1 = c[mt][nt][3] + b1;
                if (round_out) { v0 = round_tf32(v0); v1 = round_tf32(v1); }
                *(float2*)(C + (size_t)r1 * D_MODEL + colg) = make_float2(v0, v1);
            }
        }
    }
}

// ================ tensor-core flash attention (paired-x4 K frags) ===========
#define FBQ 128
#define FBK 64
#define QLD 68
#define KLD 68
#define VLD 72
#define FA_SMEM_FLOATS (FBQ*QLD + 2*FBK*KLD + 2*FBK*VLD)
#define FA_SMEM_BYTES  (FA_SMEM_FLOATS * 4)

__device__ __forceinline__ void fa_load_kv(const float* __restrict__ K,
                                           const float* __restrict__ V,
                                           int base, int len, int h, int k0,
                                           float* Ks, float* Vs, int tid) {
    #pragma unroll
    for (int i = 0; i < 4; ++i) {
        int e   = tid + i * 256;     // 0..1023
        int row = e >> 4;            // 0..63
        int g   = e & 15;
        int kr  = k0 + row; if (kr >= len) kr = len - 1;
        size_t goff = (size_t)(base + kr) * D_MODEL + h * HEAD_DIM + g * 4;
        cp_async16(smem_u32(Ks + row * KLD + g * 4), K + goff);
        cp_async16(smem_u32(Vs + row * VLD + g * 4), V + goff);
    }
}

__global__ __launch_bounds__(256)
void flash_attn_mma(const float* __restrict__ Q, const float* __restrict__ K,
                    const float* __restrict__ V, const int* __restrict__ cu,
                    float* __restrict__ O) {
    extern __shared__ float sm[];
    float* Qs  = sm;                         // 128 x 68 (later: P staging)
    float* Ks0 = Qs  + FBQ * QLD;
    float* Ks1 = Ks0 + FBK * KLD;
    float* Vs0 = Ks1 + FBK * KLD;
    float* Vs1 = Vs0 + FBK * VLD;

    const int b  = blockIdx.z;
    const int h  = blockIdx.y;
    const int q0 = blockIdx.x * FBQ;

    const int base = cu[b];
    const int len  = cu[b + 1] - base;
    if (q0 >= len) return;

    const int tid  = threadIdx.x;
    const int wid  = tid >> 5;
    const int lane = tid & 31;
    const int qr   = lane >> 2;
    const int kq   = lane & 3;
    const int lane8 = lane & 7;

    // K paired-x4: t0=(n..n+7,k),t1=(n..n+7,k+4),t2=(n+8..15,k),t3=(n+8..15,k+4)
    const int kRow = ((lane >> 4) & 1) * 8 + lane8;   // + nt2*16
    const int kCol = ((lane >> 3) & 1) * 4;           // + ks*8
    // Q/P x4 (16-row A-tiles)
    const int pRow = ((lane >> 3) & 1) * 8 + lane8;
    const int pCol = ((lane >> 4) & 1) * 4;

    const int nk = (len + FBK - 1) / FBK;

    fa_load_kv(K, V, base, len, h, 0,   Ks0, Vs0, tid); CP_COMMIT();
    fa_load_kv(K, V, base, len, h, FBK, Ks1, Vs1, tid); CP_COMMIT();

    #pragma unroll
    for (int i = 0; i < 8; ++i) {
        int e   = tid + i * 256;
        int row = e >> 4;
        int g   = e & 15;
        int qi  = q0 + row; if (qi >= len) qi = len - 1;
        float4 v = *(const float4*)(Q + (size_t)(base + qi) * D_MODEL + h * HEAD_DIM + g * 4);
        *(float4*)(Qs + row * QLD + g * 4) = v;
    }
    __syncthreads();

    uint32_t qf[8][4];
    {
        uint32_t qBase = smem_u32(Qs) + (uint32_t)((wid * 16 + pRow) * QLD + pCol) * 4u;
        #pragma unroll
        for (int ks = 0; ks < 8; ++ks)
            ldsm_x4(qf[ks], qBase + (uint32_t)(ks * 8) * 4u);
    }
    __syncthreads();

    float m0 = -3.0e38f, m1 = -3.0e38f, l0 = 0.f, l1 = 0.f;
    float o[8][4];
    #pragma unroll
    for (int dt = 0; dt < 8; ++dt)
        #pragma unroll
        for (int q = 0; q < 4; ++q) o[dt][q] = 0.f;

    float* Pw = Qs + wid * 16 * QLD;
    const uint32_t pBase = smem_u32(Pw) + (uint32_t)(pRow * QLD + pCol) * 4u;

    for (int kt = 0; kt < nk; ++kt) {
        const int s = kt & 1;
        const float* Ks = s ? Ks1 : Ks0;
        const float* Vs = s ? Vs1 : Vs0;
        if (kt + 1 < nk) { CP_WAIT1(); } else { CP_WAIT0(); }
        __syncthreads();

        float sc[8][4];
        #pragma unroll
        for (int nt = 0; nt < 8; ++nt)
            #pragma unroll
            for (int q = 0; q < 4; ++q) sc[nt][q] = 0.f;

        const uint32_t kBase = smem_u32(Ks) + (uint32_t)(kRow * KLD + kCol) * 4u;
        #pragma unroll
        for (int ks = 0; ks < 8; ++ks) {
            #pragma unroll
            for (int nt2 = 0; nt2 < 4; ++nt2) {
                uint32_t bf[4];
                ldsm_x4(bf, kBase + (uint32_t)(nt2 * 16 * KLD + ks * 8) * 4u);
                mma_tf32(sc[2 * nt2],     qf[ks], &bf[0]);
                mma_tf32(sc[2 * nt2 + 1], qf[ks], &bf[2]);
            }
        }

        const int kbase = kt * FBK;
        #pragma unroll
        for (int nt = 0; nt < 8; ++nt) {
            int c0 = kbase + nt * 8 + 2 * kq;
            bool ok0 = c0 < len, ok1 = (c0 + 1) < len;
            sc[nt][0] = ok0 ? sc[nt][0] * ATT_SCALE : NEG_BIG;
            sc[nt][1] = ok1 ? sc[nt][1] * ATT_SCALE : NEG_BIG;
            sc[nt][2] = ok0 ? sc[nt][2] * ATT_SCALE : NEG_BIG;
            sc[nt][3] = ok1 ? sc[nt][3] * ATT_SCALE : NEG_BIG;
        }

        float mx0 = -3.0e38f, mx1 = -3.0e38f;
        #pragma unroll
        for (int nt = 0; nt < 8; ++nt) {
            mx0 = fmaxf(mx0, fmaxf(sc[nt][0], sc[nt][1]));
            mx1 = fmaxf(mx1, fmaxf(sc[nt][2], sc[nt][3]));
        }
        mx0 = fmaxf(mx0, __shfl_xor_sync(0xffffffffu, mx0, 1));
        mx0 = fmaxf(mx0, __shfl_xor_sync(0xffffffffu, mx0, 2));
        mx1 = fmaxf(mx1, __shfl_xor_sync(0xffffffffu, mx1, 1));
        mx1 = fmaxf(mx1, __shfl_xor_sync(0xffffffffu, mx1, 2));

        float nm0 = fmaxf(m0, mx0), nm1 = fmaxf(m1, mx1);
        float a0 = __expf(m0 - nm0), a1 = __expf(m1 - nm1);
        float rs0 = 0.f, rs1 = 0.f;
        #pragma unroll
        for (int nt = 0; nt < 8; ++nt) {
            float p00 = __expf(sc[nt][0] - nm0);
            float p01 = __expf(sc[nt][1] - nm0);
            float p10 = __expf(sc[nt][2] - nm1);
            float p11 = __expf(sc[nt][3] - nm1);
            rs0 += p00 + p01;
            rs1 += p10 + p11;
            float* pp = Pw + qr * QLD + nt * 8 + 2 * kq;
            *(float2*)pp = make_float2(round_tf32(p00), round_tf32(p01));
            *(float2*)(pp + 8 * QLD) = make_float2(round_tf32(p10), round_tf32(p11));
        }
        rs0 += __shfl_xor_sync(0xffffffffu, rs0, 1);
        rs0 += __shfl_xor_sync(0xffffffffu, rs0, 2);
        rs1 += __shfl_xor_sync(0xffffffffu, rs1, 1);
        rs1 += __shfl_xor_sync(0xffffffffu, rs1, 2);

        l0 = l0 * a0 + rs0;  m0 = nm0;
        l1 = l1 * a1 + rs1;  m1 = nm1;
        #pragma unroll
        for (int dt = 0; dt < 8; ++dt) {
            o[dt][0] *= a0; o[dt][1] *= a0;
            o[dt][2] *= a1; o[dt][3] *= a1;
        }
        __syncwarp();

        #pragma unroll
        for (int ks = 0; ks < 8; ++ks) {
            uint32_t pf[4];
            ldsm_x4(pf, pBase + (uint32_t)(ks * 8) * 4u);
            const float* vrow = Vs + (ks * 8 + kq) * VLD + qr;
            #pragma unroll
            for (int dt = 0; dt < 8; ++dt) {
                uint32_t bf[2];
                bf[0] = __float_as_uint(vrow[dt * 8]);
                bf[1] = __float_as_uint(vrow[4 * VLD + dt * 8]);
                mma_tf32(o[dt], pf, bf);
            }
        }
        __syncthreads();

        if (kt + 2 < nk) {
            fa_load_kv(K, V, base, len, h, (kt + 2) * FBK,
                       s ? Ks1 : Ks0, s ? Vs1 : Vs0, tid);
            CP_COMMIT();
        }
    }

    const int qr0 = q0 + wid * 16 + qr;
    const int qr1 = qr0 + 8;
    const float inv0 = 1.0f / l0, inv1 = 1.0f / l1;
    #pragma unroll
    for (int dt = 0; dt < 8; ++dt) {
        int col = h * HEAD_DIM + dt * 8 + 2 * kq;
        if (qr0 < len)
            *(float2*)(O + (size_t)(base + qr0) * D_MODEL + col) =
                make_float2(round_tf32(o[dt][0] * inv0), round_tf32(o[dt][1] * inv0));
        if (qr1 < len)
            *(float2*)(O + (size_t)(base + qr1) * D_MODEL + col) =
                make_float2(round_tf32(o[dt][2] * inv1), round_tf32(o[dt][3] * inv1));
    }
}

// ---------------- host launcher ----------------------------------------------
extern "C" void kernel_launch(void* const* d_in, const int* in_sizes, int n_in,
                              void* d_out, int out_size) {
    const float* hs = (const float*)d_in[0];
    const int*   cu = (const int*)d_in[1];
    const float* Wq = (const float*)d_in[2];
    const float* bq = (const float*)d_in[3];
    const float* Wk = (const float*)d_in[4];
    const float* Wv = (const float*)d_in[5];
    const float* bv = (const float*)d_in[6];
    const float* Wo = (const float*)d_in[7];
    const float* bo = (const float*)d_in[8];
    float* out = (float*)d_out;

    const int T    = in_sizes[0] / D_MODEL;   // 6000
    const int Bseg = in_sizes[1] - 1;         // 4

    float *pq, *pk, *pv, *pa, *phr, *pwr, *pbias;
    cudaGetSymbolAddress((void**)&pq,    g_q);
    cudaGetSymbolAddress((void**)&pk,    g_k);
    cudaGetSymbolAddress((void**)&pv,    g_v);
    cudaGetSymbolAddress((void**)&pa,    g_attn);
    cudaGetSymbolAddress((void**)&phr,   g_hs_r);
    cudaGetSymbolAddress((void**)&pwr,   g_w_r);
    cudaGetSymbolAddress((void**)&pbias, g_bias);
    float* pwo = pwr + 3 * D_MODEL * D_MODEL;

    cudaFuncSetAttribute(flash_attn_mma, cudaFuncAttributeMaxDynamicSharedMemorySize,
                         FA_SMEM_BYTES);
    cudaFuncSetAttribute(gemm_tf32mma, cudaFuncAttributeMaxDynamicSharedMemorySize,
                         GT_SMEM_BYTES);

    // fused prep: tf32-round hs + 4 weights, build combined qkv bias
    prep_kernel<<<(PREP_TOTAL + 255) / 256, 256>>>(
        (const float4*)hs, (const float4*)Wq, (const float4*)Wk,
        (const float4*)Wv, (const float4*)Wo, bq, bv,
        (float4*)phr, (float4*)pwr, pbias);

    // merged QKV projection: C[:, 0:3840] = hs_r @ [Wq|Wk|Wv]^T + [bq|0|bv]
    dim3 qkvgrid(3 * D_MODEL / BNg, (T + BMg - 1) / BMg);   // (30, 47)
    gemm_tf32mma<<<qkvgrid, GTHREADS, GT_SMEM_BYTES>>>(phr, pwr, pbias,
                                                       pq, pk, pv, T, 1);

    // attention (tensor-core tf32, fp32 accumulate; output tf32-rounded)
    dim3 fgrid((MAX_SEQLEN + FBQ - 1) / FBQ, NUM_HEADS, Bseg);
    flash_attn_mma<<<fgrid, 256, FA_SMEM_BYTES>>>(pq, pk, pv, cu, pa);

    // output projection (single matrix, grid.x=10 -> mat id always 0)
    dim3 ogrid(D_MODEL / BNg, (T + BMg - 1) / BMg);         // (10, 47)
    gemm_tf32mma<<<ogrid, GTHREADS, GT_SMEM_BYTES>>>(pa, pwo, bo,
                                                     out, out, out, T, 0);
}

// round 12
// speedup vs baseline: 5.7911x; 1.0474x over previous
#include <cuda_runtime.h>
#include <cuda_bf16.h>
#include <cstdint>

// Problem constants (static shapes from setup_inputs)
#define D_MODEL 1280
#define NUM_HEADS 20
#define HEAD_DIM 64
#define MAX_SEQLEN 1500
#define MAX_T 6000           // 4 * 1500
#define TP 6080              // padded token stride for V^T (>= 4500+1536, mult of 64)
#define ATT_SCALE 0.125f     // 64^-0.5 (exact power of two)
#define NEG_BIG -1e30f

// ---------------- scratch (static device globals; no runtime alloc) ----------
__device__ float g_q[MAX_T * D_MODEL];
__device__ float g_k[MAX_T * D_MODEL];
__device__ float g_vt[D_MODEL * TP];                // V transposed: [d][token]
__device__ float g_attn[MAX_T * D_MODEL];
__device__ float g_hs_r[MAX_T * D_MODEL];           // tf32-rounded hidden states
__device__ float g_w_r[4][D_MODEL * D_MODEL];       // tf32-rounded Wq,Wk,Wv,Wo (contiguous)
__device__ float g_bias[3 * D_MODEL];               // combined bq | 0 | bv

// ========================= PTX helpers ======================================
__device__ __forceinline__ uint32_t smem_u32(const void* p) {
    uint32_t a;
    asm("{ .reg .u64 t; cvta.to.shared.u64 t, %1; cvt.u32.u64 %0, t; }"
        : "=r"(a) : "l"(p));
    return a;
}

__device__ __forceinline__ void cp_async16(uint32_t dst, const void* src) {
    asm volatile("cp.async.cg.shared.global [%0], [%1], 16;"
                 :: "r"(dst), "l"(src));
}
#define CP_COMMIT() asm volatile("cp.async.commit_group;" ::: "memory")
#define CP_WAIT0()  asm volatile("cp.async.wait_group 0;" ::: "memory")
#define CP_WAIT1()  asm volatile("cp.async.wait_group 1;" ::: "memory")

__device__ __forceinline__ float round_tf32(float v) {
    uint32_t t;
    asm("cvt.rn.tf32.f32 %0, %1;" : "=r"(t) : "f"(v));
    return __uint_as_float(t);
}

// mma.sync m16n8k8 tf32: D[16,8] += A[16,8] @ B[8,8]  (A row-major, B col-major)
__device__ __forceinline__ void mma_tf32(float c[4], const uint32_t a[4],
                                         const uint32_t b[2]) {
    asm volatile(
        "mma.sync.aligned.m16n8k8.row.col.f32.tf32.tf32.f32 "
        "{%0,%1,%2,%3}, {%4,%5,%6,%7}, {%8,%9}, {%0,%1,%2,%3};"
        : "+f"(c[0]), "+f"(c[1]), "+f"(c[2]), "+f"(c[3])
        : "r"(a[0]), "r"(a[1]), "r"(a[2]), "r"(a[3]), "r"(b[0]), "r"(b[1]));
}

// ldmatrix: tf32 fragments via b16 tiles (pure bit movement).
__device__ __forceinline__ void ldsm_x4(uint32_t r[4], uint32_t addr) {
    asm volatile("ldmatrix.sync.aligned.m8n8.x4.shared.b16 {%0,%1,%2,%3}, [%4];"
                 : "=r"(r[0]), "=r"(r[1]), "=r"(r[2]), "=r"(r[3]) : "r"(addr));
}

// ================= fused prep kernel: tf32 rounding + bias build =============
#define H4  (MAX_T * D_MODEL / 4)
#define W4  (D_MODEL * D_MODEL / 4)
#define B4  (3 * D_MODEL / 4)
#define PREP_TOTAL (H4 + 4 * W4 + B4)

__global__ __launch_bounds__(256)
void prep_kernel(const float4* __restrict__ hs,
                 const float4* __restrict__ wq, const float4* __restrict__ wk,
                 const float4* __restrict__ wv, const float4* __restrict__ wo,
                 const float* __restrict__ bq, const float* __restrict__ bv,
                 float4* __restrict__ hs_r, float4* __restrict__ w_r,
                 float* __restrict__ bias) {
    int i = blockIdx.x * blockDim.x + threadIdx.x;
    if (i < H4) {
        float4 v = hs[i];
        v.x = round_tf32(v.x); v.y = round_tf32(v.y);
        v.z = round_tf32(v.z); v.w = round_tf32(v.w);
        hs_r[i] = v;
    } else if (i < H4 + 4 * W4) {
        int j = i - H4;
        const float4* src = (j < W4) ? wq : (j < 2 * W4) ? wk : (j < 3 * W4) ? wv : wo;
        float4 v = src[j - (j / W4) * W4];
        v.x = round_tf32(v.x); v.y = round_tf32(v.y);
        v.z = round_tf32(v.z); v.w = round_tf32(v.w);
        w_r[j] = v;
    } else if (i < PREP_TOTAL) {
        int j = (i - H4 - 4 * W4) * 4;
        #pragma unroll
        for (int e = 0; e < 4; ++e) {
            int idx = j + e;
            float v = 0.f;
            if (idx < D_MODEL) v = bq[idx];
            else if (idx >= 2 * D_MODEL) v = bv[idx - 2 * D_MODEL];
            bias[idx] = v;
        }
    }
}

// ============ tf32 mma.sync GEMM (templated M-tile): C = A @ B^T + bias ======
// CTA tile (MT*32)x128, BK=32, 4 warps (2x2), warp tile (MT*16)x64.
// 3-stage cp.async, one barrier per chunk, 2 CTAs/SM, paired ldmatrix frags.
// mat==2 output (V) is stored TRANSPOSED into g_vt with stride TP.
#define BNg 128
#define BKg 32
#define GTHREADS 128
#define LDAg 36                                      // 32 + 4 pad
#define BSTG (BNg * LDAg)

template<int MT>
__device__ __forceinline__ void gt_load(const float* __restrict__ A,
                                        const float* __restrict__ B,
                                        int M, int m0, int n0, int k0,
                                        float* sA, float* sB, int tid) {
    constexpr int BM = MT * 32;
    #pragma unroll
    for (int i = 0; i < BM / 16; ++i) {
        int e   = tid + i * GTHREADS;
        int row = e >> 3;
        int g   = e & 7;
        int ar  = m0 + row; if (ar >= M) ar = M - 1;   // clamp; masked at store
        cp_async16(smem_u32(sA + row * LDAg + g * 4),
                   A + (size_t)ar * D_MODEL + k0 + g * 4);
    }
    #pragma unroll
    for (int i = 0; i < 8; ++i) {
        int e   = tid + i * GTHREADS;
        int row = e >> 3;
        int g   = e & 7;
        cp_async16(smem_u32(sB + row * LDAg + g * 4),
                   B + (size_t)(n0 + row) * D_MODEL + k0 + g * 4);
    }
}

template<int MT>
__global__ __launch_bounds__(GTHREADS, 2)
void gemm_tf32mma(const float* __restrict__ A, const float* __restrict__ B,
                  const float* __restrict__ bias,
                  float* __restrict__ C0, float* __restrict__ C1,
                  float* __restrict__ C2, int M, int round_out) {
    constexpr int BM = MT * 32;
    constexpr int ASTG = BM * LDAg;
    constexpr int STG_FLOATS = ASTG + BSTG;
    extern __shared__ float sm[];
    float* sA[3] = { sm, sm + STG_FLOATS, sm + 2 * STG_FLOATS };
    float* sB[3] = { sm + ASTG, sm + STG_FLOATS + ASTG, sm + 2 * STG_FLOATS + ASTG };

    const int tid  = threadIdx.x;
    const int wid  = tid >> 5;
    const int lane = tid & 31;
    const int wm   = wid & 1;          // warp row -> MT*16 rows
    const int wn   = wid >> 1;         // warp col -> 64 cols
    const int m0   = blockIdx.y * BM;
    const int n0   = blockIdx.x * BNg;

    const int lane8 = lane & 7;
    const int aRow  = wm * (MT * 16) + ((lane >> 3) & 1) * 8 + lane8;   // + mt*16
    const int aCol  = ((lane >> 4) & 1) * 4;                             // + kk*8
    const int bRow  = wn * 64 + ((lane >> 4) & 1) * 8 + lane8;          // + nt2*16
    const int bCol  = ((lane >> 3) & 1) * 4;                             // + kk*8

    float c[MT][8][4];
    #pragma unroll
    for (int mt = 0; mt < MT; ++mt)
        #pragma unroll
        for (int nt = 0; nt < 8; ++nt)
            #pragma unroll
            for (int q = 0; q < 4; ++q) c[mt][nt][q] = 0.f;

    const int NCH = D_MODEL / BKg;     // 40
    gt_load<MT>(A, B, M, m0, n0, 0,   sA[0], sB[0], tid); CP_COMMIT();
    gt_load<MT>(A, B, M, m0, n0, BKg, sA[1], sB[1], tid); CP_COMMIT();

    for (int ch = 0; ch < NCH; ++ch) {
        if (ch == NCH - 1) { CP_WAIT0(); } else { CP_WAIT1(); }
        __syncthreads();
        if (ch + 2 < NCH) {
            gt_load<MT>(A, B, M, m0, n0, (ch + 2) * BKg,
                        sA[(ch + 2) % 3], sB[(ch + 2) % 3], tid);
            CP_COMMIT();
        }
        const uint32_t aBase = smem_u32(sA[ch % 3]) + (uint32_t)(aRow * LDAg + aCol) * 4u;
        const uint32_t bBase = smem_u32(sB[ch % 3]) + (uint32_t)(bRow * LDAg + bCol) * 4u;

        #pragma unroll
        for (int kk = 0; kk < 4; ++kk) {
            uint32_t af[MT][4];
            #pragma unroll
            for (int mt = 0; mt < MT; ++mt)
                ldsm_x4(af[mt], aBase + (uint32_t)(mt * 16 * LDAg + kk * 8) * 4u);
            uint32_t bf[4][4];
            #pragma unroll
            for (int nt2 = 0; nt2 < 4; ++nt2)
                ldsm_x4(bf[nt2], bBase + (uint32_t)(nt2 * 16 * LDAg + kk * 8) * 4u);
            #pragma unroll
            for (int mt = 0; mt < MT; ++mt)
                #pragma unroll
                for (int nt2 = 0; nt2 < 4; ++nt2) {
                    mma_tf32(c[mt][2 * nt2],     af[mt], &bf[nt2][0]);
                    mma_tf32(c[mt][2 * nt2 + 1], af[mt], &bf[nt2][2]);
                }
        }
    }

    // route output block to its matrix (10 column-blocks per 1280-wide matrix)
    const int mat = blockIdx.x / 10;
    float* C = (mat == 0) ? C0 : ((mat == 1) ? C1 : C2);
    const int ncol0 = (blockIdx.x - mat * 10) * BNg;

    const int crow = m0 + wm * (MT * 16) + (lane >> 2);
    const int ccol = wn * 64 + 2 * (lane & 3);

    if (mat == 2) {
        // V: store TRANSPOSED into g_vt[col][row] (stride TP)
        #pragma unroll
        for (int nt = 0; nt < 8; ++nt) {
            int col  = ccol + nt * 8;
            float b0 = bias[n0 + col];
            float b1 = bias[n0 + col + 1];
            int cg0 = ncol0 + col, cg1 = cg0 + 1;
            #pragma unroll
            for (int mt = 0; mt < MT; ++mt) {
                int r0 = crow + mt * 16;
                if (r0 < M) {
                    C[(size_t)cg0 * TP + r0] = round_tf32(c[mt][nt][0] + b0);
                    C[(size_t)cg1 * TP + r0] = round_tf32(c[mt][nt][1] + b1);
                }
                int r1 = r0 + 8;
                if (r1 < M) {
                    C[(size_t)cg0 * TP + r1] = round_tf32(c[mt][nt][2] + b0);
                    C[(size_t)cg1 * TP + r1] = round_tf32(c[mt][nt][3] + b1);
                }
            }
        }
    } else {
        #pragma unroll
        for (int nt = 0; nt < 8; ++nt) {
            int col  = ccol + nt * 8;
            float b0 = bias[n0 + col];
            float b1 = bias[n0 + col + 1];
            int colg = ncol0 + col;
            #pragma unroll
            for (int mt = 0; mt < MT; ++mt) {
                int r0 = crow + mt * 16;
                if (r0 < M) {
                    float v0 = c[mt][nt][0] + b0, v1 = c[mt][nt][1] + b1;
                    if (round_out) { v0 = round_tf32(v0); v1 = round_tf32(v1); }
                    *(float2*)(C + (size_t)r0 * D_MODEL + colg) = make_float2(v0, v1);
                }
                int r1 = r0 + 8;
                if (r1 < M) {
                    float v0 = c[mt][nt][2] + b0, v1 = c[mt][nt][3] + b1;
                    if (round_out) { v0 = round_tf32(v0); v1 = round_tf32(v1); }
                    *(float2*)(C + (size_t)r1 * D_MODEL + colg) = make_float2(v0, v1);
                }
            }
        }
    }
}

#define GT_SMEM_QKV (3 * (128 * LDAg + BSTG) * 4)    // 110592 B (MT=4)
#define GT_SMEM_O   (3 * ( 64 * LDAg + BSTG) * 4)    // 82944 B (MT=2)

// ================ tensor-core flash attention ================================
// V consumed from g_vt ([d][token]) -> paired ldmatrix B-frags in P.V loop.
// ATT_SCALE folded into Q at smem store (exact *2^-3). Mask only partial tiles.
#define FBQ 128
#define FBK 64
#define QLD 68
#define KLD 68
#define VLD 68
#define FA_SMEM_FLOATS (FBQ*QLD + 2*FBK*KLD + 2*FBK*VLD)
#define FA_SMEM_BYTES  (FA_SMEM_FLOATS * 4)

__device__ __forceinline__ void fa_load_kv(const float* __restrict__ K,
                                           const float* __restrict__ Vt,
                                           int base, int len, int h, int k0,
                                           float* Ks, float* Vs, int tid) {
    #pragma unroll
    for (int i = 0; i < 4; ++i) {
        int e   = tid + i * 256;     // 0..1023
        int row = e >> 4;            // 0..63
        int g   = e & 15;
        // K: row = key index (clamped)
        int kr  = k0 + row; if (kr >= len) kr = len - 1;
        cp_async16(smem_u32(Ks + row * KLD + g * 4),
                   K + (size_t)(base + kr) * D_MODEL + h * HEAD_DIM + g * 4);
        // V^T: row = d, cols = tokens (no clamp; invalid cols hit P=0)
        cp_async16(smem_u32(Vs + row * VLD + g * 4),
                   Vt + (size_t)(h * HEAD_DIM + row) * TP + base + k0 + g * 4);
    }
}

__global__ __launch_bounds__(256)
void flash_attn_mma(const float* __restrict__ Q, const float* __restrict__ K,
                    const float* __restrict__ Vt, const int* __restrict__ cu,
                    float* __restrict__ O) {
    extern __shared__ float sm[];
    float* Qs  = sm;                         // 128 x 68 (later: P staging)
    float* Ks0 = Qs  + FBQ * QLD;
    float* Ks1 = Ks0 + FBK * KLD;
    float* Vs0 = Ks1 + FBK * KLD;
    float* Vs1 = Vs0 + FBK * VLD;

    const int b  = blockIdx.z;
    const int h  = blockIdx.y;
    const int q0 = blockIdx.x * FBQ;

    const int base = cu[b];
    const int len  = cu[b + 1] - base;
    if (q0 >= len) return;

    const int tid  = threadIdx.x;
    const int wid  = tid >> 5;
    const int lane = tid & 31;
    const int qr   = lane >> 2;
    const int kq   = lane & 3;
    const int lane8 = lane & 7;

    // paired-x4 B-frag address components (same pattern for K and V^T)
    const int bfRow = ((lane >> 4) & 1) * 8 + lane8;   // + tile2*16
    const int bfCol = ((lane >> 3) & 1) * 4;           // + ks*8
    // Q/P x4 (16-row A-tiles)
    const int pRow = ((lane >> 3) & 1) * 8 + lane8;
    const int pCol = ((lane >> 4) & 1) * 4;

    const int nk = (len + FBK - 1) / FBK;

    fa_load_kv(K, Vt, base, len, h, 0,   Ks0, Vs0, tid); CP_COMMIT();
    fa_load_kv(K, Vt, base, len, h, FBK, Ks1, Vs1, tid); CP_COMMIT();

    // Q tile -> smem, with ATT_SCALE folded in (exact power of two)
    #pragma unroll
    for (int i = 0; i < 8; ++i) {
        int e   = tid + i * 256;
        int row = e >> 4;
        int g   = e & 15;
        int qi  = q0 + row; if (qi >= len) qi = len - 1;
        float4 v = *(const float4*)(Q + (size_t)(base + qi) * D_MODEL + h * HEAD_DIM + g * 4);
        v.x *= ATT_SCALE; v.y *= ATT_SCALE; v.z *= ATT_SCALE; v.w *= ATT_SCALE;
        *(float4*)(Qs + row * QLD + g * 4) = v;
    }
    __syncthreads();

    uint32_t qf[8][4];
    {
        uint32_t qBase = smem_u32(Qs) + (uint32_t)((wid * 16 + pRow) * QLD + pCol) * 4u;
        #pragma unroll
        for (int ks = 0; ks < 8; ++ks)
            ldsm_x4(qf[ks], qBase + (uint32_t)(ks * 8) * 4u);
    }
    __syncthreads();

    float m0 = -3.0e38f, m1 = -3.0e38f, l0 = 0.f, l1 = 0.f;
    float o[8][4];
    #pragma unroll
    for (int dt = 0; dt < 8; ++dt)
        #pragma unroll
        for (int q = 0; q < 4; ++q) o[dt][q] = 0.f;

    float* Pw = Qs + wid * 16 * QLD;
    const uint32_t pBase = smem_u32(Pw) + (uint32_t)(pRow * QLD + pCol) * 4u;

    for (int kt = 0; kt < nk; ++kt) {
        const int s = kt & 1;
        const float* Ks = s ? Ks1 : Ks0;
        const float* Vs = s ? Vs1 : Vs0;
        if (kt + 1 < nk) { CP_WAIT1(); } else { CP_WAIT0(); }
        __syncthreads();

        float sc[8][4];
        #pragma unroll
        for (int nt = 0; nt < 8; ++nt)
            #pragma unroll
            for (int q = 0; q < 4; ++q) sc[nt][q] = 0.f;

        const uint32_t kBase = smem_u32(Ks) + (uint32_t)(bfRow * KLD + bfCol) * 4u;
        #pragma unroll
        for (int ks = 0; ks < 8; ++ks) {
            #pragma unroll
            for (int nt2 = 0; nt2 < 4; ++nt2) {
                uint32_t bf[4];
                ldsm_x4(bf, kBase + (uint32_t)(nt2 * 16 * KLD + ks * 8) * 4u);
                mma_tf32(sc[2 * nt2],     qf[ks], &bf[0]);
                mma_tf32(sc[2 * nt2 + 1], qf[ks], &bf[2]);
            }
        }

        // mask only partial tiles (scale already folded into Q)
        const int kbase = kt * FBK;
        if (kbase + FBK > len) {
            #pragma unroll
            for (int nt = 0; nt < 8; ++nt) {
                int c0 = kbase + nt * 8 + 2 * kq;
                if (c0 >= len)     { sc[nt][0] = NEG_BIG; sc[nt][2] = NEG_BIG; }
                if (c0 + 1 >= len) { sc[nt][1] = NEG_BIG; sc[nt][3] = NEG_BIG; }
            }
        }

        float mx0 = -3.0e38f, mx1 = -3.0e38f;
        #pragma unroll
        for (int nt = 0; nt < 8; ++nt) {
            mx0 = fmaxf(mx0, fmaxf(sc[nt][0], sc[nt][1]));
            mx1 = fmaxf(mx1, fmaxf(sc[nt][2], sc[nt][3]));
        }
        mx0 = fmaxf(mx0, __shfl_xor_sync(0xffffffffu, mx0, 1));
        mx0 = fmaxf(mx0, __shfl_xor_sync(0xffffffffu, mx0, 2));
        mx1 = fmaxf(mx1, __shfl_xor_sync(0xffffffffu, mx1, 1));
        mx1 = fmaxf(mx1, __shfl_xor_sync(0xffffffffu, mx1, 2));

        float nm0 = fmaxf(m0, mx0), nm1 = fmaxf(m1, mx1);
        float a0 = __expf(m0 - nm0), a1 = __expf(m1 - nm1);
        float rs0 = 0.f, rs1 = 0.f;
        #pragma unroll
        for (int nt = 0; nt < 8; ++nt) {
            float p00 = __expf(sc[nt][0] - nm0);
            float p01 = __expf(sc[nt][1] - nm0);
            float p10 = __expf(sc[nt][2] - nm1);
            float p11 = __expf(sc[nt][3] - nm1);
            rs0 += p00 + p01;
            rs1 += p10 + p11;
            float* pp = Pw + qr * QLD + nt * 8 + 2 * kq;
            *(float2*)pp = make_float2(round_tf32(p00), round_tf32(p01));
            *(float2*)(pp + 8 * QLD) = make_float2(round_tf32(p10), round_tf32(p11));
        }
        rs0 += __shfl_xor_sync(0xffffffffu, rs0, 1);
        rs0 += __shfl_xor_sync(0xffffffffu, rs0, 2);
        rs1 += __shfl_xor_sync(0xffffffffu, rs1, 1);
        rs1 += __shfl_xor_sync(0xffffffffu, rs1, 2);

        l0 = l0 * a0 + rs0;  m0 = nm0;
        l1 = l1 * a1 + rs1;  m1 = nm1;
        #pragma unroll
        for (int dt = 0; dt < 8; ++dt) {
            o[dt][0] *= a0; o[dt][1] *= a0;
            o[dt][2] *= a1; o[dt][3] *= a1;
        }
        __syncwarp();

        // O += P @ V via paired-x4 ldmatrix on V^T tiles
        const uint32_t vBase = smem_u32(Vs) + (uint32_t)(bfRow * VLD + bfCol) * 4u;
        #pragma unroll
        for (int ks = 0; ks < 8; ++ks) {
            uint32_t pf[4];
            ldsm_x4(pf, pBase + (uint32_t)(ks * 8) * 4u);
            #pragma unroll
            for (int dt2 = 0; dt2 < 4; ++dt2) {
                uint32_t bf[4];
                ldsm_x4(bf, vBase + (uint32_t)(dt2 * 16 * VLD + ks * 8) * 4u);
                mma_tf32(o[2 * dt2],     pf, &bf[0]);
                mma_tf32(o[2 * dt2 + 1], pf, &bf[2]);
            }
        }
        __syncthreads();

        if (kt + 2 < nk) {
            fa_load_kv(K, Vt, base, len, h, (kt + 2) * FBK,
                       s ? Ks1 : Ks0, s ? Vs1 : Vs0, tid);
            CP_COMMIT();
        }
    }

    const int qr0 = q0 + wid * 16 + qr;
    const int qr1 = qr0 + 8;
    const float inv0 = 1.0f / l0, inv1 = 1.0f / l1;
    #pragma unroll
    for (int dt = 0; dt < 8; ++dt) {
        int col = h * HEAD_DIM + dt * 8 + 2 * kq;
        if (qr0 < len)
            *(float2*)(O + (size_t)(base + qr0) * D_MODEL + col) =
                make_float2(round_tf32(o[dt][0] * inv0), round_tf32(o[dt][1] * inv0));
        if (qr1 < len)
            *(float2*)(O + (size_t)(base + qr1) * D_MODEL + col) =
                make_float2(round_tf32(o[dt][2] * inv1), round_tf32(o[dt][3] * inv1));
    }
}

// ---------------- host launcher ----------------------------------------------
extern "C" void kernel_launch(void* const* d_in, const int* in_sizes, int n_in,
                              void* d_out, int out_size) {
    const float* hs = (const float*)d_in[0];
    const int*   cu = (const int*)d_in[1];
    const float* Wq = (const float*)d_in[2];
    const float* bq = (const float*)d_in[3];
    const float* Wk = (const float*)d_in[4];
    const float* Wv = (const float*)d_in[5];
    const float* bv = (const float*)d_in[6];
    const float* Wo = (const float*)d_in[7];
    const float* bo = (const float*)d_in[8];
    float* out = (float*)d_out;

    const int T    = in_sizes[0] / D_MODEL;   // 6000
    const int Bseg = in_sizes[1] - 1;         // 4

    float *pq, *pk, *pvt, *pa, *phr, *pwr, *pbias;
    cudaGetSymbolAddress((void**)&pq,    g_q);
    cudaGetSymbolAddress((void**)&pk,    g_k);
    cudaGetSymbolAddress((void**)&pvt,   g_vt);
    cudaGetSymbolAddress((void**)&pa,    g_attn);
    cudaGetSymbolAddress((void**)&phr,   g_hs_r);
    cudaGetSymbolAddress((void**)&pwr,   g_w_r);
    cudaGetSymbolAddress((void**)&pbias, g_bias);
    float* pwo = pwr + 3 * D_MODEL * D_MODEL;

    cudaFuncSetAttribute(flash_attn_mma, cudaFuncAttributeMaxDynamicSharedMemorySize,
                         FA_SMEM_BYTES);
    cudaFuncSetAttribute(gemm_tf32mma<4>, cudaFuncAttributeMaxDynamicSharedMemorySize,
                         GT_SMEM_QKV);
    cudaFuncSetAttribute(gemm_tf32mma<2>, cudaFuncAttributeMaxDynamicSharedMemorySize,
                         GT_SMEM_O);

    // fused prep: tf32-round hs + 4 weights, build combined qkv bias
    prep_kernel<<<(PREP_TOTAL + 255) / 256, 256>>>(
        (const float4*)hs, (const float4*)Wq, (const float4*)Wk,
        (const float4*)Wv, (const float4*)Wo, bq, bv,
        (float4*)phr, (float4*)pwr, pbias);

    // merged QKV projection (V written transposed into g_vt)
    dim3 qkvgrid(3 * D_MODEL / BNg, (T + 127) / 128);   // (30, 47)
    gemm_tf32mma<4><<<qkvgrid, GTHREADS, GT_SMEM_QKV>>>(phr, pwr, pbias,
                                                        pq, pk, pvt, T, 1);

    // attention (tensor-core tf32, fp32 accumulate; output tf32-rounded)
    dim3 fgrid((MAX_SEQLEN + FBQ - 1) / FBQ, NUM_HEADS, Bseg);
    flash_attn_mma<<<fgrid, 256, FA_SMEM_BYTES>>>(pq, pk, pvt, cu, pa);

    // output projection: 64-row tiles for finer wave granularity
    dim3 ogrid(D_MODEL / BNg, (T + 63) / 64);           // (10, 94)
    gemm_tf32mma<2><<<ogrid, GTHREADS, GT_SMEM_O>>>(pa, pwo, bo,
                                                    out, out, out, T, 0);
}

// round 13
// speedup vs baseline: 5.9473x; 1.0270x over previous
#include <cuda_runtime.h>
#include <cuda_bf16.h>
#include <cstdint>

// Problem constants (static shapes from setup_inputs)
#define D_MODEL 1280
#define NUM_HEADS 20
#define HEAD_DIM 64
#define MAX_SEQLEN 1500
#define MAX_T 6000           // 4 * 1500
#define TP 6080              // padded token stride for V^T
#define ATT_SCALE 0.125f     // 64^-0.5 (exact power of two)
#define NEG_BIG -1e30f

// ---------------- scratch (static device globals; no runtime alloc) ----------
__device__ float g_q[MAX_T * D_MODEL];
__device__ float g_k[MAX_T * D_MODEL];
__device__ float g_vt[D_MODEL * TP];                // V transposed: [d][token]
__device__ float g_attn[MAX_T * D_MODEL];
__device__ float g_hs_r[MAX_T * D_MODEL];           // tf32-rounded hidden states
__device__ float g_w_r[4][D_MODEL * D_MODEL];       // tf32-rounded Wq,Wk,Wv,Wo
__device__ float g_bias[3 * D_MODEL];               // combined bq | 0 | bv

// ========================= PTX helpers ======================================
__device__ __forceinline__ uint32_t smem_u32(const void* p) {
    uint32_t a;
    asm("{ .reg .u64 t; cvta.to.shared.u64 t, %1; cvt.u32.u64 %0, t; }"
        : "=r"(a) : "l"(p));
    return a;
}

__device__ __forceinline__ void cp_async16(uint32_t dst, const void* src) {
    asm volatile("cp.async.cg.shared.global [%0], [%1], 16;"
                 :: "r"(dst), "l"(src));
}
#define CP_COMMIT() asm volatile("cp.async.commit_group;" ::: "memory")
#define CP_WAIT0()  asm volatile("cp.async.wait_group 0;" ::: "memory")
#define CP_WAIT1()  asm volatile("cp.async.wait_group 1;" ::: "memory")

__device__ __forceinline__ float round_tf32(float v) {
    uint32_t t;
    asm("cvt.rn.tf32.f32 %0, %1;" : "=r"(t) : "f"(v));
    return __uint_as_float(t);
}

// mma.sync m16n8k8 tf32: D[16,8] += A[16,8] @ B[8,8]  (A row-major, B col-major)
__device__ __forceinline__ void mma_tf32(float c[4], const uint32_t a[4],
                                         const uint32_t b[2]) {
    asm volatile(
        "mma.sync.aligned.m16n8k8.row.col.f32.tf32.tf32.f32 "
        "{%0,%1,%2,%3}, {%4,%5,%6,%7}, {%8,%9}, {%0,%1,%2,%3};"
        : "+f"(c[0]), "+f"(c[1]), "+f"(c[2]), "+f"(c[3])
        : "r"(a[0]), "r"(a[1]), "r"(a[2]), "r"(a[3]), "r"(b[0]), "r"(b[1]));
}

__device__ __forceinline__ void ldsm_x4(uint32_t r[4], uint32_t addr) {
    asm volatile("ldmatrix.sync.aligned.m8n8.x4.shared.b16 {%0,%1,%2,%3}, [%4];"
                 : "=r"(r[0]), "=r"(r[1]), "=r"(r[2]), "=r"(r[3]) : "r"(addr));
}

// ================= fused prep kernel: tf32 rounding + bias build =============
#define H4  (MAX_T * D_MODEL / 4)
#define W4  (D_MODEL * D_MODEL / 4)
#define B4  (3 * D_MODEL / 4)
#define PREP_TOTAL (H4 + 4 * W4 + B4)

__global__ __launch_bounds__(256)
void prep_kernel(const float4* __restrict__ hs,
                 const float4* __restrict__ wq, const float4* __restrict__ wk,
                 const float4* __restrict__ wv, const float4* __restrict__ wo,
                 const float* __restrict__ bq, const float* __restrict__ bv,
                 float4* __restrict__ hs_r, float4* __restrict__ w_r,
                 float* __restrict__ bias) {
    int i = blockIdx.x * blockDim.x + threadIdx.x;
    if (i < H4) {
        float4 v = hs[i];
        v.x = round_tf32(v.x); v.y = round_tf32(v.y);
        v.z = round_tf32(v.z); v.w = round_tf32(v.w);
        hs_r[i] = v;
    } else if (i < H4 + 4 * W4) {
        int j = i - H4;
        const float4* src = (j < W4) ? wq : (j < 2 * W4) ? wk : (j < 3 * W4) ? wv : wo;
        float4 v = src[j - (j / W4) * W4];
        v.x = round_tf32(v.x); v.y = round_tf32(v.y);
        v.z = round_tf32(v.z); v.w = round_tf32(v.w);
        w_r[j] = v;
    } else if (i < PREP_TOTAL) {
        int j = (i - H4 - 4 * W4) * 4;
        #pragma unroll
        for (int e = 0; e < 4; ++e) {
            int idx = j + e;
            float v = 0.f;
            if (idx < D_MODEL) v = bq[idx];
            else if (idx >= 2 * D_MODEL) v = bv[idx - 2 * D_MODEL];
            bias[idx] = v;
        }
    }
}

// ============ tf32 mma.sync GEMM (MT=4): C = A @ B^T + bias ==================
// CTA tile 128x128, BK=32, 4 warps (2x2), warp tile 64x64.
// 3-stage cp.async, one barrier per chunk, 2 CTAs/SM, paired ldmatrix frags.
// mat==2 output (V) is stored TRANSPOSED into g_vt with stride TP.
#define BNg 128
#define BKg 32
#define GTHREADS 128
#define LDAg 36
#define BSTG (BNg * LDAg)
#define ASTG (128 * LDAg)
#define STG_FLOATS (ASTG + BSTG)
#define GT_SMEM_BYTES (3 * STG_FLOATS * 4)           // 110.6 KB -> 2 CTAs/SM

__device__ __forceinline__ void gt_load(const float* __restrict__ A,
                                        const float* __restrict__ B,
                                        int M, int m0, int n0, int k0,
                                        float* sA, float* sB, int tid) {
    #pragma unroll
    for (int i = 0; i < 8; ++i) {
        int e   = tid + i * GTHREADS;
        int row = e >> 3;
        int g   = e & 7;
        int ar  = m0 + row; if (ar >= M) ar = M - 1;
        cp_async16(smem_u32(sA + row * LDAg + g * 4),
                   A + (size_t)ar * D_MODEL + k0 + g * 4);
        cp_async16(smem_u32(sB + row * LDAg + g * 4),
                   B + (size_t)(n0 + row) * D_MODEL + k0 + g * 4);
    }
}

__global__ __launch_bounds__(GTHREADS, 2)
void gemm_tf32mma(const float* __restrict__ A, const float* __restrict__ B,
                  const float* __restrict__ bias,
                  float* __restrict__ C0, float* __restrict__ C1,
                  float* __restrict__ C2, int M, int round_out) {
    extern __shared__ float sm[];
    float* sA[3] = { sm, sm + STG_FLOATS, sm + 2 * STG_FLOATS };
    float* sB[3] = { sm + ASTG, sm + STG_FLOATS + ASTG, sm + 2 * STG_FLOATS + ASTG };

    const int tid  = threadIdx.x;
    const int wid  = tid >> 5;
    const int lane = tid & 31;
    const int wm   = wid & 1;
    const int wn   = wid >> 1;
    const int m0   = blockIdx.y * 128;
    const int n0   = blockIdx.x * BNg;

    const int lane8 = lane & 7;
    const int aRow  = wm * 64 + ((lane >> 3) & 1) * 8 + lane8;
    const int aCol  = ((lane >> 4) & 1) * 4;
    const int bRow  = wn * 64 + ((lane >> 4) & 1) * 8 + lane8;
    const int bCol  = ((lane >> 3) & 1) * 4;

    float c[4][8][4];
    #pragma unroll
    for (int mt = 0; mt < 4; ++mt)
        #pragma unroll
        for (int nt = 0; nt < 8; ++nt)
            #pragma unroll
            for (int q = 0; q < 4; ++q) c[mt][nt][q] = 0.f;

    const int NCH = D_MODEL / BKg;
    gt_load(A, B, M, m0, n0, 0,   sA[0], sB[0], tid); CP_COMMIT();
    gt_load(A, B, M, m0, n0, BKg, sA[1], sB[1], tid); CP_COMMIT();

    for (int ch = 0; ch < NCH; ++ch) {
        if (ch == NCH - 1) { CP_WAIT0(); } else { CP_WAIT1(); }
        __syncthreads();
        if (ch + 2 < NCH) {
            gt_load(A, B, M, m0, n0, (ch + 2) * BKg,
                    sA[(ch + 2) % 3], sB[(ch + 2) % 3], tid);
            CP_COMMIT();
        }
        const uint32_t aBase = smem_u32(sA[ch % 3]) + (uint32_t)(aRow * LDAg + aCol) * 4u;
        const uint32_t bBase = smem_u32(sB[ch % 3]) + (uint32_t)(bRow * LDAg + bCol) * 4u;

        #pragma unroll
        for (int kk = 0; kk < 4; ++kk) {
            uint32_t af[4][4];
            #pragma unroll
            for (int mt = 0; mt < 4; ++mt)
                ldsm_x4(af[mt], aBase + (uint32_t)(mt * 16 * LDAg + kk * 8) * 4u);
            uint32_t bf[4][4];
            #pragma unroll
            for (int nt2 = 0; nt2 < 4; ++nt2)
                ldsm_x4(bf[nt2], bBase + (uint32_t)(nt2 * 16 * LDAg + kk * 8) * 4u);
            #pragma unroll
            for (int mt = 0; mt < 4; ++mt)
                #pragma unroll
                for (int nt2 = 0; nt2 < 4; ++nt2) {
                    mma_tf32(c[mt][2 * nt2],     af[mt], &bf[nt2][0]);
                    mma_tf32(c[mt][2 * nt2 + 1], af[mt], &bf[nt2][2]);
                }
        }
    }

    const int mat = blockIdx.x / 10;
    float* C = (mat == 0) ? C0 : ((mat == 1) ? C1 : C2);
    const int ncol0 = (blockIdx.x - mat * 10) * BNg;

    const int crow = m0 + wm * 64 + (lane >> 2);
    const int ccol = wn * 64 + 2 * (lane & 3);

    if (mat == 2) {
        // V: store TRANSPOSED into g_vt[col][row] (stride TP)
        #pragma unroll
        for (int nt = 0; nt < 8; ++nt) {
            int col  = ccol + nt * 8;
            float b0 = bias[n0 + col];
            float b1 = bias[n0 + col + 1];
            int cg0 = ncol0 + col, cg1 = cg0 + 1;
            #pragma unroll
            for (int mt = 0; mt < 4; ++mt) {
                int r0 = crow + mt * 16;
                if (r0 < M) {
                    C[(size_t)cg0 * TP + r0] = round_tf32(c[mt][nt][0] + b0);
                    C[(size_t)cg1 * TP + r0] = round_tf32(c[mt][nt][1] + b1);
                }
                int r1 = r0 + 8;
                if (r1 < M) {
                    C[(size_t)cg0 * TP + r1] = round_tf32(c[mt][nt][2] + b0);
                    C[(size_t)cg1 * TP + r1] = round_tf32(c[mt][nt][3] + b1);
                }
            }
        }
    } else {
        #pragma unroll
        for (int nt = 0; nt < 8; ++nt) {
            int col  = ccol + nt * 8;
            float b0 = bias[n0 + col];
            float b1 = bias[n0 + col + 1];
            int colg = ncol0 + col;
            #pragma unroll
            for (int mt = 0; mt < 4; ++mt) {
                int r0 = crow + mt * 16;
                if (r0 < M) {
                    float v0 = c[mt][nt][0] + b0, v1 = c[mt][nt][1] + b1;
                    if (round_out) { v0 = round_tf32(v0); v1 = round_tf32(v1); }
                    *(float2*)(C + (size_t)r0 * D_MODEL + colg) = make_float2(v0, v1);
                }
                int r1 = r0 + 8;
                if (r1 < M) {
                    float v0 = c[mt][nt][2] + b0, v1 = c[mt][nt][3] + b1;
                    if (round_out) { v0 = round_tf32(v0); v1 = round_tf32(v1); }
                    *(float2*)(C + (size_t)r1 * D_MODEL + colg) = make_float2(v0, v1);
                }
            }
        }
    }
}

// ================ tensor-core flash attention ================================
// 128 threads (4 warps), each warp owns 32 q-rows -> K/V fragment traffic per
// MAC halves vs the 8-warp layout. FBQ=128, KV tiles of 64, V from g_vt.
#define FTHREADS 128
#define FBQ 128
#define FBK 64
#define QLD 68
#define KLD 68
#define VLD 68
#define FA_SMEM_FLOATS (FBQ*QLD + 2*FBK*KLD + 2*FBK*VLD)
#define FA_SMEM_BYTES  (FA_SMEM_FLOATS * 4)

__device__ __forceinline__ void fa_load_kv(const float* __restrict__ K,
                                           const float* __restrict__ Vt,
                                           int base, int len, int h, int k0,
                                           float* Ks, float* Vs, int tid) {
    #pragma unroll
    for (int i = 0; i < 8; ++i) {
        int e   = tid + i * FTHREADS;  // 0..1023
        int row = e >> 4;              // 0..63
        int g   = e & 15;
        int kr  = k0 + row; if (kr >= len) kr = len - 1;
        cp_async16(smem_u32(Ks + row * KLD + g * 4),
                   K + (size_t)(base + kr) * D_MODEL + h * HEAD_DIM + g * 4);
        cp_async16(smem_u32(Vs + row * VLD + g * 4),
                   Vt + (size_t)(h * HEAD_DIM + row) * TP + base + k0 + g * 4);
    }
}

__global__ __launch_bounds__(FTHREADS, 2)
void flash_attn_mma(const float* __restrict__ Q, const float* __restrict__ K,
                    const float* __restrict__ Vt, const int* __restrict__ cu,
                    float* __restrict__ O) {
    extern __shared__ float sm[];
    float* Qs  = sm;                         // 128 x 68 (later: P staging)
    float* Ks0 = Qs  + FBQ * QLD;
    float* Ks1 = Ks0 + FBK * KLD;
    float* Vs0 = Ks1 + FBK * KLD;
    float* Vs1 = Vs0 + FBK * VLD;

    const int b  = blockIdx.z;
    const int h  = blockIdx.y;
    const int q0 = blockIdx.x * FBQ;

    const int base = cu[b];
    const int len  = cu[b + 1] - base;
    if (q0 >= len) return;

    const int tid  = threadIdx.x;
    const int wid  = tid >> 5;       // 0..3, owns rows [wid*32, wid*32+32)
    const int lane = tid & 31;
    const int qr   = lane >> 2;
    const int kq   = lane & 3;
    const int lane8 = lane & 7;

    // paired-x4 B-frag address components (K and V^T share the pattern)
    const int bfRow = ((lane >> 4) & 1) * 8 + lane8;   // + tile2*16
    const int bfCol = ((lane >> 3) & 1) * 4;           // + ks*8
    // A-frag (Q/P) x4 pattern
    const int pRow = ((lane >> 3) & 1) * 8 + lane8;
    const int pCol = ((lane >> 4) & 1) * 4;

    const int nk = (len + FBK - 1) / FBK;

    fa_load_kv(K, Vt, base, len, h, 0,   Ks0, Vs0, tid); CP_COMMIT();
    fa_load_kv(K, Vt, base, len, h, FBK, Ks1, Vs1, tid); CP_COMMIT();

    // Q tile -> smem with ATT_SCALE folded in (exact *2^-3)
    #pragma unroll
    for (int i = 0; i < 16; ++i) {
        int e   = tid + i * FTHREADS;  // 0..2047
        int row = e >> 4;
        int g   = e & 15;
        int qi  = q0 + row; if (qi >= len) qi = len - 1;
        float4 v = *(const float4*)(Q + (size_t)(base + qi) * D_MODEL + h * HEAD_DIM + g * 4);
        v.x *= ATT_SCALE; v.y *= ATT_SCALE; v.z *= ATT_SCALE; v.w *= ATT_SCALE;
        *(float4*)(Qs + row * QLD + g * 4) = v;
    }
    __syncthreads();

    // Q fragments for both 16-row halves (warp rows wid*32 + mt*16 + ...)
    uint32_t qf[2][8][4];
    {
        uint32_t qBase = smem_u32(Qs) + (uint32_t)((wid * 32 + pRow) * QLD + pCol) * 4u;
        #pragma unroll
        for (int mt = 0; mt < 2; ++mt)
            #pragma unroll
            for (int ks = 0; ks < 8; ++ks)
                ldsm_x4(qf[mt][ks], qBase + (uint32_t)(mt * 16 * QLD + ks * 8) * 4u);
    }
    __syncthreads();    // Qs may be reused as P staging

    float mrow[2][2], lrow[2][2];
    #pragma unroll
    for (int mt = 0; mt < 2; ++mt) {
        mrow[mt][0] = -3.0e38f; mrow[mt][1] = -3.0e38f;
        lrow[mt][0] = 0.f;      lrow[mt][1] = 0.f;
    }
    float o[2][8][4];
    #pragma unroll
    for (int mt = 0; mt < 2; ++mt)
        #pragma unroll
        for (int dt = 0; dt < 8; ++dt)
            #pragma unroll
            for (int q = 0; q < 4; ++q) o[mt][dt][q] = 0.f;

    float* Pw = Qs + wid * 32 * QLD;   // this warp's 32 x 68 P staging
    const uint32_t pBase = smem_u32(Pw) + (uint32_t)(pRow * QLD + pCol) * 4u;

    for (int kt = 0; kt < nk; ++kt) {
        const int s = kt & 1;
        const float* Ks = s ? Ks1 : Ks0;
        const float* Vs = s ? Vs1 : Vs0;
        if (kt + 1 < nk) { CP_WAIT1(); } else { CP_WAIT0(); }
        __syncthreads();

        // ---- S = Q @ K^T (32 x 64 per warp); K frags loaded once, used 2x --
        float sc[2][8][4];
        #pragma unroll
        for (int mt = 0; mt < 2; ++mt)
            #pragma unroll
            for (int nt = 0; nt < 8; ++nt)
                #pragma unroll
                for (int q = 0; q < 4; ++q) sc[mt][nt][q] = 0.f;

        const uint32_t kBase = smem_u32(Ks) + (uint32_t)(bfRow * KLD + bfCol) * 4u;
        #pragma unroll
        for (int ks = 0; ks < 8; ++ks) {
            #pragma unroll
            for (int nt2 = 0; nt2 < 4; ++nt2) {
                uint32_t bf[4];
                ldsm_x4(bf, kBase + (uint32_t)(nt2 * 16 * KLD + ks * 8) * 4u);
                #pragma unroll
                for (int mt = 0; mt < 2; ++mt) {
                    mma_tf32(sc[mt][2 * nt2],     qf[mt][ks], &bf[0]);
                    mma_tf32(sc[mt][2 * nt2 + 1], qf[mt][ks], &bf[2]);
                }
            }
        }

        // ---- mask only partial tiles ----
        const int kbase = kt * FBK;
        if (kbase + FBK > len) {
            #pragma unroll
            for (int nt = 0; nt < 8; ++nt) {
                int c0 = kbase + nt * 8 + 2 * kq;
                #pragma unroll
                for (int mt = 0; mt < 2; ++mt) {
                    if (c0 >= len)     { sc[mt][nt][0] = NEG_BIG; sc[mt][nt][2] = NEG_BIG; }
                    if (c0 + 1 >= len) { sc[mt][nt][1] = NEG_BIG; sc[mt][nt][3] = NEG_BIG; }
                }
            }
        }

        // ---- online softmax (4 row-groups: mt x {qr, qr+8}) ----
        #pragma unroll
        for (int mt = 0; mt < 2; ++mt) {
            float mx0 = -3.0e38f, mx1 = -3.0e38f;
            #pragma unroll
            for (int nt = 0; nt < 8; ++nt) {
                mx0 = fmaxf(mx0, fmaxf(sc[mt][nt][0], sc[mt][nt][1]));
                mx1 = fmaxf(mx1, fmaxf(sc[mt][nt][2], sc[mt][nt][3]));
            }
            mx0 = fmaxf(mx0, __shfl_xor_sync(0xffffffffu, mx0, 1));
            mx0 = fmaxf(mx0, __shfl_xor_sync(0xffffffffu, mx0, 2));
            mx1 = fmaxf(mx1, __shfl_xor_sync(0xffffffffu, mx1, 1));
            mx1 = fmaxf(mx1, __shfl_xor_sync(0xffffffffu, mx1, 2));

            float nm0 = fmaxf(mrow[mt][0], mx0), nm1 = fmaxf(mrow[mt][1], mx1);
            float a0 = __expf(mrow[mt][0] - nm0), a1 = __expf(mrow[mt][1] - nm1);
            float rs0 = 0.f, rs1 = 0.f;
            #pragma unroll
            for (int nt = 0; nt < 8; ++nt) {
                float p00 = __expf(sc[mt][nt][0] - nm0);
                float p01 = __expf(sc[mt][nt][1] - nm0);
                float p10 = __expf(sc[mt][nt][2] - nm1);
                float p11 = __expf(sc[mt][nt][3] - nm1);
                rs0 += p00 + p01;
                rs1 += p10 + p11;
                float* pp = Pw + (mt * 16 + qr) * QLD + nt * 8 + 2 * kq;
                *(float2*)pp = make_float2(round_tf32(p00), round_tf32(p01));
                *(float2*)(pp + 8 * QLD) = make_float2(round_tf32(p10), round_tf32(p11));
            }
            rs0 += __shfl_xor_sync(0xffffffffu, rs0, 1);
            rs0 += __shfl_xor_sync(0xffffffffu, rs0, 2);
            rs1 += __shfl_xor_sync(0xffffffffu, rs1, 1);
            rs1 += __shfl_xor_sync(0xffffffffu, rs1, 2);

            lrow[mt][0] = lrow[mt][0] * a0 + rs0;  mrow[mt][0] = nm0;
            lrow[mt][1] = lrow[mt][1] * a1 + rs1;  mrow[mt][1] = nm1;
            #pragma unroll
            for (int dt = 0; dt < 8; ++dt) {
                o[mt][dt][0] *= a0; o[mt][dt][1] *= a0;
                o[mt][dt][2] *= a1; o[mt][dt][3] *= a1;
            }
        }
        __syncwarp();

        // ---- O += P @ V; V frags loaded once, used by both mt halves ----
        const uint32_t vBase = smem_u32(Vs) + (uint32_t)(bfRow * VLD + bfCol) * 4u;
        #pragma unroll
        for (int ks = 0; ks < 8; ++ks) {
            uint32_t pf[2][4];
            ldsm_x4(pf[0], pBase + (uint32_t)(ks * 8) * 4u);
            ldsm_x4(pf[1], pBase + (uint32_t)(16 * QLD + ks * 8) * 4u);
            #pragma unroll
            for (int dt2 = 0; dt2 < 4; ++dt2) {
                uint32_t bf[4];
                ldsm_x4(bf, vBase + (uint32_t)(dt2 * 16 * VLD + ks * 8) * 4u);
                #pragma unroll
                for (int mt = 0; mt < 2; ++mt) {
                    mma_tf32(o[mt][2 * dt2],     pf[mt], &bf[0]);
                    mma_tf32(o[mt][2 * dt2 + 1], pf[mt], &bf[2]);
                }
            }
        }
        __syncthreads();

        if (kt + 2 < nk) {
            fa_load_kv(K, Vt, base, len, h, (kt + 2) * FBK,
                       s ? Ks1 : Ks0, s ? Vs1 : Vs0, tid);
            CP_COMMIT();
        }
    }

    // ---- epilogue ----
    #pragma unroll
    for (int mt = 0; mt < 2; ++mt) {
        const int qr0 = q0 + wid * 32 + mt * 16 + qr;
        const int qr1 = qr0 + 8;
        const float inv0 = 1.0f / lrow[mt][0], inv1 = 1.0f / lrow[mt][1];
        #pragma unroll
        for (int dt = 0; dt < 8; ++dt) {
            int col = h * HEAD_DIM + dt * 8 + 2 * kq;
            if (qr0 < len)
                *(float2*)(O + (size_t)(base + qr0) * D_MODEL + col) =
                    make_float2(round_tf32(o[mt][dt][0] * inv0),
                                round_tf32(o[mt][dt][1] * inv0));
            if (qr1 < len)
                *(float2*)(O + (size_t)(base + qr1) * D_MODEL + col) =
                    make_float2(round_tf32(o[mt][dt][2] * inv1),
                                round_tf32(o[mt][dt][3] * inv1));
        }
    }
}

// ---------------- host launcher ----------------------------------------------
extern "C" void kernel_launch(void* const* d_in, const int* in_sizes, int n_in,
                              void* d_out, int out_size) {
    const float* hs = (const float*)d_in[0];
    const int*   cu = (const int*)d_in[1];
    const float* Wq = (const float*)d_in[2];
    const float* bq = (const float*)d_in[3];
    const float* Wk = (const float*)d_in[4];
    const float* Wv = (const float*)d_in[5];
    const float* bv = (const float*)d_in[6];
    const float* Wo = (const float*)d_in[7];
    const float* bo = (const float*)d_in[8];
    float* out = (float*)d_out;

    const int T    = in_sizes[0] / D_MODEL;   // 6000
    const int Bseg = in_sizes[1] - 1;         // 4

    float *pq, *pk, *pvt, *pa, *phr, *pwr, *pbias;
    cudaGetSymbolAddress((void**)&pq,    g_q);
    cudaGetSymbolAddress((void**)&pk,    g_k);
    cudaGetSymbolAddress((void**)&pvt,   g_vt);
    cudaGetSymbolAddress((void**)&pa,    g_attn);
    cudaGetSymbolAddress((void**)&phr,   g_hs_r);
    cudaGetSymbolAddress((void**)&pwr,   g_w_r);
    cudaGetSymbolAddress((void**)&pbias, g_bias);
    float* pwo = pwr + 3 * D_MODEL * D_MODEL;

    cudaFuncSetAttribute(flash_attn_mma, cudaFuncAttributeMaxDynamicSharedMemorySize,
                         FA_SMEM_BYTES);
    cudaFuncSetAttribute(gemm_tf32mma, cudaFuncAttributeMaxDynamicSharedMemorySize,
                         GT_SMEM_BYTES);

    // fused prep: tf32-round hs + 4 weights, build combined qkv bias
    prep_kernel<<<(PREP_TOTAL + 255) / 256, 256>>>(
        (const float4*)hs, (const float4*)Wq, (const float4*)Wk,
        (const float4*)Wv, (const float4*)Wo, bq, bv,
        (float4*)phr, (float4*)pwr, pbias);

    // merged QKV projection (V written transposed into g_vt)
    dim3 qkvgrid(3 * D_MODEL / BNg, (T + 127) / 128);   // (30, 47)
    gemm_tf32mma<<<qkvgrid, GTHREADS, GT_SMEM_BYTES>>>(phr, pwr, pbias,
                                                       pq, pk, pvt, T, 1);

    // attention (tensor-core tf32; 4 warps x 32 q-rows)
    dim3 fgrid((MAX_SEQLEN + FBQ - 1) / FBQ, NUM_HEADS, Bseg);
    flash_attn_mma<<<fgrid, FTHREADS, FA_SMEM_BYTES>>>(pq, pk, pvt, cu, pa);

    // output projection (MT=4, reverted from MT=2)
    dim3 ogrid(D_MODEL / BNg, (T + 127) / 128);         // (10, 47)
    gemm_tf32mma<<<ogrid, GTHREADS, GT_SMEM_BYTES>>>(pa, pwo, bo,
                                                     out, out, out, T, 0);
}